// round 5
// baseline (speedup 1.0000x reference)
#include <cuda_runtime.h>
#include <cuda_bf16.h>
#include <stdint.h>
#include <math.h>

// Problem constants
#define S_LEN   2048
#define BATCH   2
#define NHEAD   16
#define HDIM    128
#define DMODEL  2048
#define INNER   2048          // NHEAD*HDIM
#define ROWS    (BATCH*S_LEN) // 4096

// Scratch (allocation forbidden -> __device__ globals)
__device__ __nv_bfloat16 g_xhi[(size_t)ROWS * DMODEL];
__device__ __nv_bfloat16 g_xlo[(size_t)ROWS * DMODEL];
__device__ __nv_bfloat16 g_wthi[4][(size_t)DMODEL * INNER];  // W^T per matrix, [N,K]
__device__ __nv_bfloat16 g_wtlo[4][(size_t)DMODEL * INNER];
__device__ __nv_bfloat16 g_qhi[(size_t)ROWS * INNER];
__device__ __nv_bfloat16 g_qlo[(size_t)ROWS * INNER];
__device__ __nv_bfloat16 g_khi[(size_t)ROWS * INNER];
__device__ __nv_bfloat16 g_klo[(size_t)ROWS * INNER];
__device__ __nv_bfloat16 g_vhi[(size_t)ROWS * INNER];
__device__ __nv_bfloat16 g_vlo[(size_t)ROWS * INNER];
__device__ __nv_bfloat16 g_aohi[(size_t)ROWS * INNER];
__device__ __nv_bfloat16 g_aolo[(size_t)ROWS * INNER];

// ---------------------------------------------------------------------------
// Helpers (base PTX only: cp.async / ldmatrix / mma.sync)
// ---------------------------------------------------------------------------
__device__ __forceinline__ uint32_t smem_u32(const void* p) {
    uint32_t a;
    asm("{ .reg .u64 t; cvta.to.shared.u64 t, %1; cvt.u32.u64 %0, t; }"
        : "=r"(a) : "l"(p));
    return a;
}
__device__ __forceinline__ void cp16(uint32_t dst, const void* src) {
    asm volatile("cp.async.cg.shared.global [%0], [%1], 16;" :: "r"(dst), "l"(src));
}
__device__ __forceinline__ void cp_commit() { asm volatile("cp.async.commit_group;"); }
template<int N> __device__ __forceinline__ void cp_wait() {
    asm volatile("cp.async.wait_group %0;" :: "n"(N));
}
__device__ __forceinline__ void ldm_x4(uint32_t* r, uint32_t addr) {
    asm volatile("ldmatrix.sync.aligned.m8n8.x4.shared.b16 {%0,%1,%2,%3}, [%4];"
                 : "=r"(r[0]), "=r"(r[1]), "=r"(r[2]), "=r"(r[3]) : "r"(addr));
}
__device__ __forceinline__ void ldm_x4t(uint32_t* r, uint32_t addr) {
    asm volatile("ldmatrix.sync.aligned.m8n8.x4.trans.shared.b16 {%0,%1,%2,%3}, [%4];"
                 : "=r"(r[0]), "=r"(r[1]), "=r"(r[2]), "=r"(r[3]) : "r"(addr));
}
__device__ __forceinline__ void mma16816(float* c, const uint32_t* a, const uint32_t* b) {
    asm volatile(
        "mma.sync.aligned.m16n8k16.row.col.f32.bf16.bf16.f32 "
        "{%0,%1,%2,%3}, {%4,%5,%6,%7}, {%8,%9}, {%0,%1,%2,%3};"
        : "+f"(c[0]), "+f"(c[1]), "+f"(c[2]), "+f"(c[3])
        : "r"(a[0]), "r"(a[1]), "r"(a[2]), "r"(a[3]), "r"(b[0]), "r"(b[1]));
}
__device__ __forceinline__ uint32_t pack_bf2(float a, float b) {
    __nv_bfloat162 t = __floats2bfloat162_rn(a, b);
    return *(uint32_t*)&t;
}
__device__ __forceinline__ void split1(float v, __nv_bfloat16& h, float& r) {
    h = __float2bfloat16(v);
    r = v - __bfloat162float(h);
}

// ---------------------------------------------------------------------------
// bf16 hi/lo split GEMM: C = A[M,K] @ Bt[N,K]^T (hh+hl+lh), 3-stage pipeline.
// MODE 0: fp32 C.  MODE 1: bf16 hi/lo split C.  MODE 2: RMSNorm + split C.
// ---------------------------------------------------------------------------
#define G_BM 128
#define G_BN 128
#define G_BK 32
#define ROWB 80
#define TILEB (128 * ROWB)
#define STAGEB (4 * TILEB)            // 40960
#define GEMM_SMEM (3 * STAGEB)        // 122880 (also covers 128x132 fp32 stage)

template<int MODE>
__global__ __launch_bounds__(256, 1)
void gemm_mma_kernel(const __nv_bfloat16* __restrict__ Ahi,
                     const __nv_bfloat16* __restrict__ Alo,
                     const __nv_bfloat16* __restrict__ Bhi,
                     const __nv_bfloat16* __restrict__ Blo,
                     float* __restrict__ C,
                     __nv_bfloat16* __restrict__ Chi,
                     __nv_bfloat16* __restrict__ Clo,
                     const float* __restrict__ gamma,
                     int M, int N, int K)
{
    extern __shared__ char smem[];
    const uint32_t sbase = smem_u32(smem);
    const int tid  = threadIdx.x;
    const int warp = tid >> 5;
    const int lane = tid & 31;
    const int wm = warp >> 1;
    const int wn = warp & 1;

    const int row0 = blockIdx.y * G_BM;
    const int col0 = blockIdx.x * G_BN;
    const size_t Kb = (size_t)K * 2;

    const char* gp[4] = {
        (const char*)Ahi + (size_t)row0 * Kb,
        (const char*)Alo + (size_t)row0 * Kb,
        (const char*)Bhi + (size_t)col0 * Kb,
        (const char*)Blo + (size_t)col0 * Kb
    };

    float acc[2][8][4];
#pragma unroll
    for (int mt = 0; mt < 2; mt++)
#pragma unroll
        for (int nt = 0; nt < 8; nt++)
#pragma unroll
            for (int r = 0; r < 4; r++) acc[mt][nt][r] = 0.0f;

    const int NCH = K / G_BK;

    auto load_chunk = [&](int c, int s) {
        size_t koff = (size_t)c * (G_BK * 2);
        uint32_t stb = sbase + s * STAGEB;
#pragma unroll
        for (int t = 0; t < 4; t++) {
            uint32_t tb = stb + t * TILEB;
            const char* g = gp[t];
#pragma unroll
            for (int i = 0; i < 2; i++) {
                int idx = i * 256 + tid;
                int row = idx >> 2;
                int ks  = idx & 3;
                cp16(tb + row * ROWB + ks * 16,
                     g + (size_t)row * Kb + koff + ks * 16);
            }
        }
    };

    load_chunk(0, 0); cp_commit();
    load_chunk(1, 1); cp_commit();

    for (int c = 0; c < NCH; ++c) {
        if (c + 2 < NCH) { load_chunk(c + 2, (c + 2) % 3); cp_commit(); cp_wait<2>(); }
        else if (c + 1 < NCH) cp_wait<1>();
        else cp_wait<0>();
        __syncthreads();

        const uint32_t base = sbase + (c % 3) * STAGEB;
#pragma unroll
        for (int ks = 0; ks < 2; ks++) {
            uint32_t ah[2][4], al[2][4];
#pragma unroll
            for (int mt = 0; mt < 2; mt++) {
                uint32_t arow = wm * 32 + mt * 16 + (lane & 15);
                uint32_t aoff = arow * ROWB + (ks * 16 + 8 * (lane >> 4)) * 2;
                ldm_x4(ah[mt], base + aoff);
                ldm_x4(al[mt], base + TILEB + aoff);
            }
            uint32_t bh[8][2], bl[8][2];
#pragma unroll
            for (int p = 0; p < 4; p++) {
                uint32_t brow = wn * 64 + p * 16 + (lane & 7) + 8 * (lane >> 4);
                uint32_t boff = brow * ROWB + (ks * 16 + 8 * ((lane >> 3) & 1)) * 2;
                uint32_t t0[4], t1[4];
                ldm_x4(t0, base + 2 * TILEB + boff);
                ldm_x4(t1, base + 3 * TILEB + boff);
                bh[2*p][0]   = t0[0]; bh[2*p][1]   = t0[1];
                bh[2*p+1][0] = t0[2]; bh[2*p+1][1] = t0[3];
                bl[2*p][0]   = t1[0]; bl[2*p][1]   = t1[1];
                bl[2*p+1][0] = t1[2]; bl[2*p+1][1] = t1[3];
            }
#pragma unroll
            for (int mt = 0; mt < 2; mt++)
#pragma unroll
                for (int nt = 0; nt < 8; nt++) {
                    mma16816(acc[mt][nt], ah[mt], bh[nt]);
                    mma16816(acc[mt][nt], ah[mt], bl[nt]);
                    mma16816(acc[mt][nt], al[mt], bh[nt]);
                }
        }
        __syncthreads();
    }

    if (MODE == 0) {
#pragma unroll
        for (int mt = 0; mt < 2; mt++) {
            int r0 = row0 + wm * 32 + mt * 16 + (lane >> 2);
#pragma unroll
            for (int nt = 0; nt < 8; nt++) {
                int cc = col0 + wn * 64 + nt * 8 + (lane & 3) * 2;
                *(float2*)(C + (size_t)r0 * N + cc) =
                    make_float2(acc[mt][nt][0], acc[mt][nt][1]);
                *(float2*)(C + (size_t)(r0 + 8) * N + cc) =
                    make_float2(acc[mt][nt][2], acc[mt][nt][3]);
            }
        }
    } else if (MODE == 1) {
#pragma unroll
        for (int mt = 0; mt < 2; mt++) {
            int r0 = row0 + wm * 32 + mt * 16 + (lane >> 2);
#pragma unroll
            for (int nt = 0; nt < 8; nt++) {
                int cc = col0 + wn * 64 + nt * 8 + (lane & 3) * 2;
                __nv_bfloat16 h0, h1; float l0, l1;
                split1(acc[mt][nt][0], h0, l0);
                split1(acc[mt][nt][1], h1, l1);
                __nv_bfloat162 hp; hp.x = h0; hp.y = h1;
                *(uint32_t*)(Chi + (size_t)r0 * N + cc) = *(uint32_t*)&hp;
                *(uint32_t*)(Clo + (size_t)r0 * N + cc) = pack_bf2(l0, l1);
                split1(acc[mt][nt][2], h0, l0);
                split1(acc[mt][nt][3], h1, l1);
                __nv_bfloat162 hq; hq.x = h0; hq.y = h1;
                *(uint32_t*)(Chi + (size_t)(r0 + 8) * N + cc) = *(uint32_t*)&hq;
                *(uint32_t*)(Clo + (size_t)(r0 + 8) * N + cc) = pack_bf2(l0, l1);
            }
        }
    } else {
        // MODE 2: stage block in smem, per-row (head-dim) RMSNorm, split, store
        float* CS = (float*)smem;          // 128 x 132
#pragma unroll
        for (int mt = 0; mt < 2; mt++) {
            int r = wm * 32 + mt * 16 + (lane >> 2);
#pragma unroll
            for (int nt = 0; nt < 8; nt++) {
                int cc = wn * 64 + nt * 8 + (lane & 3) * 2;
                CS[r * 132 + cc]       = acc[mt][nt][0];
                CS[r * 132 + cc + 1]   = acc[mt][nt][1];
                CS[(r+8) * 132 + cc]     = acc[mt][nt][2];
                CS[(r+8) * 132 + cc + 1] = acc[mt][nt][3];
            }
        }
        __syncthreads();
        float4 g4 = *(const float4*)(gamma + lane * 4);
#pragma unroll
        for (int rr = 0; rr < 16; rr++) {
            int row = warp * 16 + rr;
            float4 v = *(float4*)&CS[row * 132 + lane * 4];
            float ss = v.x*v.x + v.y*v.y + v.z*v.z + v.w*v.w;
#pragma unroll
            for (int o = 16; o > 0; o >>= 1)
                ss += __shfl_xor_sync(0xffffffffu, ss, o);
            float rn = rsqrtf(ss * (1.0f / 128.0f) + 1e-6f);
            float f[4] = { v.x*rn*g4.x, v.y*rn*g4.y, v.z*rn*g4.z, v.w*rn*g4.w };
            __nv_bfloat16 h[4]; float l[4];
#pragma unroll
            for (int j = 0; j < 4; j++) split1(f[j], h[j], l[j]);
            size_t o = (size_t)(row0 + row) * N + col0 + lane * 4;
            *(uint2*)(Chi + o) = *(uint2*)h;
            uint2 lp; lp.x = pack_bf2(l[0], l[1]); lp.y = pack_bf2(l[2], l[3]);
            *(uint2*)(Clo + o) = lp;
        }
    }
}

// ---------------------------------------------------------------------------
// Flash attention, mma.sync bf16 hi/lo. 256 threads, 128 q-rows x 64 k-rows,
// double-buffered K/V tiles via cp.async.
// ---------------------------------------------------------------------------
#define F_ROWB 272
#define FT64   (64 * F_ROWB)            // 17408
#define QBYTES (128 * F_ROWB)           // 34816
#define KVSTAGE (4 * FT64)              // 69632
#define FLASH_SMEM (2 * QBYTES + 2 * KVSTAGE)   // 208896

__global__ __launch_bounds__(256, 1)
void flash_mma_kernel(const __nv_bfloat16* __restrict__ Qhi,
                      const __nv_bfloat16* __restrict__ Qlo,
                      const __nv_bfloat16* __restrict__ Khi,
                      const __nv_bfloat16* __restrict__ Klo,
                      const __nv_bfloat16* __restrict__ Vhi,
                      const __nv_bfloat16* __restrict__ Vlo,
                      __nv_bfloat16* __restrict__ Ohi,
                      __nv_bfloat16* __restrict__ Olo)
{
    extern __shared__ char sm_raw[];
    const uint32_t sb  = smem_u32(sm_raw);
    const uint32_t sQh = sb, sQl = sb + QBYTES;
    const uint32_t sKV = sb + 2 * QBYTES;

    const int tid  = threadIdx.x;
    const int warp = tid >> 5;
    const int lane = tid & 31;
    const int lr   = lane >> 2;
    const int lc   = lane & 3;
    const int m0   = warp * 16;          // 8 warps cover 128 q-rows

    const int mblk = blockIdx.x, h = blockIdx.y, b = blockIdx.z;
    const size_t qoff = ((size_t)(b * S_LEN + mblk * 128)) * INNER + h * HDIM;
    const size_t koff = ((size_t)(b * S_LEN)) * INNER + h * HDIM;

    // Q tiles: 128 rows hi+lo
#pragma unroll
    for (int i = 0; i < 8; i++) {
        int idx = i * 256 + tid;        // 0..2047
        int r = idx >> 4, s = idx & 15;
        uint32_t so = r * F_ROWB + s * 16;
        const size_t go = qoff + (size_t)r * INNER + s * 8;
        cp16(sQh + so, Qhi + go);
        cp16(sQl + so, Qlo + go);
    }

    auto load_kv = [&](int it, int stage) {
        uint32_t stb = sKV + stage * KVSTAGE;
        int n0 = it * 64;
#pragma unroll
        for (int i = 0; i < 4; i++) {
            int idx = i * 256 + tid;    // 0..1023
            int r = idx >> 4, s = idx & 15;
            uint32_t so = r * F_ROWB + s * 16;
            const size_t go = koff + (size_t)(n0 + r) * INNER + s * 8;
            cp16(stb + so,          Khi + go);
            cp16(stb + FT64 + so,   Klo + go);
            cp16(stb + 2*FT64 + so, Vhi + go);
            cp16(stb + 3*FT64 + so, Vlo + go);
        }
    };

    load_kv(0, 0);
    cp_commit();   // group: Q + KV0

    float o[16][4];
#pragma unroll
    for (int nt = 0; nt < 16; nt++)
#pragma unroll
        for (int r = 0; r < 4; r++) o[nt][r] = 0.0f;
    float s_m[2] = { -1e30f, -1e30f };
    float s_l[2] = { 0.0f, 0.0f };
    const float scale = 0.08838834764831845f;

    const uint32_t a_row = m0 + (lane & 15);
    const uint32_t lhalf = 8 * (lane >> 4);

    for (int it = 0; it < S_LEN / 64; it++) {
        if (it + 1 < S_LEN / 64) {
            load_kv(it + 1, (it + 1) & 1);
            cp_commit();
            cp_wait<1>();
        } else {
            cp_wait<0>();
        }
        __syncthreads();

        const uint32_t cKh = sKV + (it & 1) * KVSTAGE;
        const uint32_t cKl = cKh + FT64;
        const uint32_t cVh = cKh + 2 * FT64;
        const uint32_t cVl = cKh + 3 * FT64;

        // ---- S = Q @ K^T (hh + hl + lh) ----
        float s[8][4];
#pragma unroll
        for (int j = 0; j < 8; j++)
#pragma unroll
            for (int r = 0; r < 4; r++) s[j][r] = 0.0f;

#pragma unroll
        for (int t = 0; t < 8; t++) {
            const int d0 = t * 16;
            uint32_t ah[4], al[4];
            uint32_t aoff = a_row * F_ROWB + (d0 + lhalf) * 2;
            ldm_x4(ah, sQh + aoff);
            ldm_x4(al, sQl + aoff);
#pragma unroll
            for (int p = 0; p < 4; p++) {
                uint32_t bh[4], bl[4];
                uint32_t boff = (p * 16 + (lane & 15)) * F_ROWB + (d0 + lhalf) * 2;
                ldm_x4(bh, cKh + boff);
                ldm_x4(bl, cKl + boff);
                uint32_t b0h[2] = { bh[0], bh[2] }, b1h[2] = { bh[1], bh[3] };
                uint32_t b0l[2] = { bl[0], bl[2] }, b1l[2] = { bl[1], bl[3] };
                mma16816(s[2*p],   ah, b0h);
                mma16816(s[2*p],   ah, b0l);
                mma16816(s[2*p],   al, b0h);
                mma16816(s[2*p+1], ah, b1h);
                mma16816(s[2*p+1], ah, b1l);
                mma16816(s[2*p+1], al, b1h);
            }
        }

        // ---- online softmax ----
#pragma unroll
        for (int j = 0; j < 8; j++)
#pragma unroll
            for (int r = 0; r < 4; r++) s[j][r] *= scale;

        float mx0 = -1e30f, mx1 = -1e30f;
#pragma unroll
        for (int j = 0; j < 8; j++) {
            mx0 = fmaxf(mx0, fmaxf(s[j][0], s[j][1]));
            mx1 = fmaxf(mx1, fmaxf(s[j][2], s[j][3]));
        }
        mx0 = fmaxf(mx0, __shfl_xor_sync(0xffffffffu, mx0, 1));
        mx0 = fmaxf(mx0, __shfl_xor_sync(0xffffffffu, mx0, 2));
        mx1 = fmaxf(mx1, __shfl_xor_sync(0xffffffffu, mx1, 1));
        mx1 = fmaxf(mx1, __shfl_xor_sync(0xffffffffu, mx1, 2));

        float mn0 = fmaxf(s_m[0], mx0), mn1 = fmaxf(s_m[1], mx1);
        float al0 = __expf(s_m[0] - mn0), al1 = __expf(s_m[1] - mn1);
        s_m[0] = mn0; s_m[1] = mn1;

        float rs0 = 0.0f, rs1 = 0.0f;
#pragma unroll
        for (int j = 0; j < 8; j++) {
            s[j][0] = __expf(s[j][0] - mn0);
            s[j][1] = __expf(s[j][1] - mn0);
            s[j][2] = __expf(s[j][2] - mn1);
            s[j][3] = __expf(s[j][3] - mn1);
            rs0 += s[j][0] + s[j][1];
            rs1 += s[j][2] + s[j][3];
        }
        rs0 += __shfl_xor_sync(0xffffffffu, rs0, 1);
        rs0 += __shfl_xor_sync(0xffffffffu, rs0, 2);
        rs1 += __shfl_xor_sync(0xffffffffu, rs1, 1);
        rs1 += __shfl_xor_sync(0xffffffffu, rs1, 2);
        s_l[0] = s_l[0] * al0 + rs0;
        s_l[1] = s_l[1] * al1 + rs1;

#pragma unroll
        for (int nt = 0; nt < 16; nt++) {
            o[nt][0] *= al0; o[nt][1] *= al0;
            o[nt][2] *= al1; o[nt][3] *= al1;
        }

        // ---- pack P into bf16 hi/lo A-frags ----
        uint32_t ph[4][4], pl[4][4];
#pragma unroll
        for (int t = 0; t < 4; t++) {
#pragma unroll
            for (int q = 0; q < 4; q++) {
                int j = 2 * t + (q >> 1);
                int cc = (q & 1) * 2;
                float v0 = s[j][cc], v1 = s[j][cc + 1];
                __nv_bfloat16 h0, h1; float r0, r1;
                split1(v0, h0, r0);
                split1(v1, h1, r1);
                __nv_bfloat162 hp; hp.x = h0; hp.y = h1;
                ph[t][q] = *(uint32_t*)&hp;
                pl[t][q] = pack_bf2(r0, r1);
            }
        }

        // ---- O += P @ V (hh + hl + lh) ----
#pragma unroll
        for (int t = 0; t < 4; t++) {
#pragma unroll
            for (int np = 0; np < 8; np++) {
                uint32_t vh[4], vl[4];
                uint32_t voff = (t * 16 + (lane & 15)) * F_ROWB + (np * 16 + lhalf) * 2;
                ldm_x4t(vh, cVh + voff);
                ldm_x4t(vl, cVl + voff);
                uint32_t b0h[2] = { vh[0], vh[1] }, b1h[2] = { vh[2], vh[3] };
                uint32_t b0l[2] = { vl[0], vl[1] }, b1l[2] = { vl[2], vl[3] };
                mma16816(o[2*np],   ph[t], b0h);
                mma16816(o[2*np],   ph[t], b0l);
                mma16816(o[2*np],   pl[t], b0h);
                mma16816(o[2*np+1], ph[t], b1h);
                mma16816(o[2*np+1], ph[t], b1l);
                mma16816(o[2*np+1], pl[t], b1h);
            }
        }
        __syncthreads();
    }

    // ---- epilogue: normalize, split, store ----
    float inv0 = 1.0f / s_l[0];
    float inv1 = 1.0f / s_l[1];
    size_t or0 = ((size_t)(b * S_LEN + mblk * 128 + m0 + lr)) * INNER + h * HDIM;
    size_t or1 = or0 + 8 * (size_t)INNER;
#pragma unroll
    for (int nt = 0; nt < 16; nt++) {
        int col = nt * 8 + lc * 2;
        float a0 = o[nt][0] * inv0, a1 = o[nt][1] * inv0;
        float b0 = o[nt][2] * inv1, b1 = o[nt][3] * inv1;
        __nv_bfloat16 h00, h01, h10, h11; float l00, l01, l10, l11;
        split1(a0, h00, l00); split1(a1, h01, l01);
        split1(b0, h10, l10); split1(b1, h11, l11);
        __nv_bfloat162 hp0; hp0.x = h00; hp0.y = h01;
        __nv_bfloat162 hp1; hp1.x = h10; hp1.y = h11;
        *(uint32_t*)(Ohi + or0 + col) = *(uint32_t*)&hp0;
        *(uint32_t*)(Ohi + or1 + col) = *(uint32_t*)&hp1;
        *(uint32_t*)(Olo + or0 + col) = pack_bf2(l00, l01);
        *(uint32_t*)(Olo + or1 + col) = pack_bf2(l10, l11);
    }
}

// ---------------------------------------------------------------------------
// fp32 -> bf16 hi/lo split (elementwise)
// ---------------------------------------------------------------------------
__global__ void split_kernel(const float4* __restrict__ in,
                             __nv_bfloat16* __restrict__ hi,
                             __nv_bfloat16* __restrict__ lo, int n4) {
    int i = blockIdx.x * blockDim.x + threadIdx.x;
    if (i >= n4) return;
    float4 v = in[i];
    float f[4] = { v.x, v.y, v.z, v.w };
    __nv_bfloat16 h[4]; float l[4];
#pragma unroll
    for (int j = 0; j < 4; j++) split1(f[j], h[j], l[j]);
    *(uint2*)(hi + 4 * (size_t)i) = *(uint2*)h;
    uint2 lp; lp.x = pack_bf2(l[0], l[1]); lp.y = pack_bf2(l[2], l[3]);
    *(uint2*)(lo + 4 * (size_t)i) = lp;
}

// ---------------------------------------------------------------------------
// Transpose + split: W[K, N] fp32 -> T{hi,lo}[N, K] bf16
// ---------------------------------------------------------------------------
__global__ void transpose_split_kernel(const float* __restrict__ W,
                                       __nv_bfloat16* __restrict__ Thi,
                                       __nv_bfloat16* __restrict__ Tlo) {
    __shared__ float t[32][33];
    int n0 = blockIdx.x * 32, k0 = blockIdx.y * 32;
#pragma unroll
    for (int i = 0; i < 32; i += 8)
        t[threadIdx.y + i][threadIdx.x] =
            W[(size_t)(k0 + threadIdx.y + i) * 2048 + n0 + threadIdx.x];
    __syncthreads();
#pragma unroll
    for (int i = 0; i < 32; i += 8) {
        float v = t[threadIdx.x][threadIdx.y + i];
        __nv_bfloat16 h; float l;
        split1(v, h, l);
        size_t o = (size_t)(n0 + threadIdx.y + i) * 2048 + k0 + threadIdx.x;
        Thi[o] = h;
        Tlo[o] = __float2bfloat16(l);
    }
}

// ---------------------------------------------------------------------------
// Launcher
// ---------------------------------------------------------------------------
extern "C" void kernel_launch(void* const* d_in, const int* in_sizes, int n_in,
                              void* d_out, int out_size) {
    const float* x  = (const float*)d_in[0];
    const float* Wq = (const float*)d_in[1];
    const float* Wk = (const float*)d_in[2];
    const float* Wv = (const float*)d_in[3];
    const float* Wo = (const float*)d_in[4];
    const float* qg = (const float*)d_in[5];
    const float* kg = (const float*)d_in[6];
    float* out = (float*)d_out;

    __nv_bfloat16 *xhi, *xlo, *wthi, *wtlo;
    __nv_bfloat16 *qhi, *qlo, *khi, *klo, *vhi, *vlo, *aohi, *aolo;
    cudaGetSymbolAddress((void**)&xhi,  g_xhi);
    cudaGetSymbolAddress((void**)&xlo,  g_xlo);
    cudaGetSymbolAddress((void**)&wthi, g_wthi);
    cudaGetSymbolAddress((void**)&wtlo, g_wtlo);
    cudaGetSymbolAddress((void**)&qhi,  g_qhi);
    cudaGetSymbolAddress((void**)&qlo,  g_qlo);
    cudaGetSymbolAddress((void**)&khi,  g_khi);
    cudaGetSymbolAddress((void**)&klo,  g_klo);
    cudaGetSymbolAddress((void**)&vhi,  g_vhi);
    cudaGetSymbolAddress((void**)&vlo,  g_vlo);
    cudaGetSymbolAddress((void**)&aohi, g_aohi);
    cudaGetSymbolAddress((void**)&aolo, g_aolo);
    const size_t WSZ = (size_t)DMODEL * INNER;

    // 1. Split x
    int n4x = ROWS * DMODEL / 4;
    split_kernel<<<n4x / 256, 256>>>((const float4*)x, xhi, xlo, n4x);

    // 2. Transpose+split weights
    dim3 tb(32, 8), tg(64, 64);
    transpose_split_kernel<<<tg, tb>>>(Wq, wthi + 0*WSZ, wtlo + 0*WSZ);
    transpose_split_kernel<<<tg, tb>>>(Wk, wthi + 1*WSZ, wtlo + 1*WSZ);
    transpose_split_kernel<<<tg, tb>>>(Wv, wthi + 2*WSZ, wtlo + 2*WSZ);
    transpose_split_kernel<<<tg, tb>>>(Wo, wthi + 3*WSZ, wtlo + 3*WSZ);

    // 3. QKV projections with fused epilogues
    cudaFuncSetAttribute(gemm_mma_kernel<0>, cudaFuncAttributeMaxDynamicSharedMemorySize, GEMM_SMEM);
    cudaFuncSetAttribute(gemm_mma_kernel<1>, cudaFuncAttributeMaxDynamicSharedMemorySize, GEMM_SMEM);
    cudaFuncSetAttribute(gemm_mma_kernel<2>, cudaFuncAttributeMaxDynamicSharedMemorySize, GEMM_SMEM);
    dim3 gg(INNER / G_BN, ROWS / G_BM);
    gemm_mma_kernel<2><<<gg, 256, GEMM_SMEM>>>(xhi, xlo, wthi + 0*WSZ, wtlo + 0*WSZ,
                                               nullptr, qhi, qlo, qg,
                                               ROWS, INNER, DMODEL);
    gemm_mma_kernel<2><<<gg, 256, GEMM_SMEM>>>(xhi, xlo, wthi + 1*WSZ, wtlo + 1*WSZ,
                                               nullptr, khi, klo, kg,
                                               ROWS, INNER, DMODEL);
    gemm_mma_kernel<1><<<gg, 256, GEMM_SMEM>>>(xhi, xlo, wthi + 2*WSZ, wtlo + 2*WSZ,
                                               nullptr, vhi, vlo, nullptr,
                                               ROWS, INNER, DMODEL);

    // 4. Flash attention -> aohi/aolo
    cudaFuncSetAttribute(flash_mma_kernel, cudaFuncAttributeMaxDynamicSharedMemorySize,
                         FLASH_SMEM);
    dim3 gridF(S_LEN / 128, NHEAD, BATCH);
    flash_mma_kernel<<<gridF, 256, FLASH_SMEM>>>(qhi, qlo, khi, klo, vhi, vlo,
                                                 aohi, aolo);

    // 5. Output projection -> d_out (fp32)
    gemm_mma_kernel<0><<<gg, 256, GEMM_SMEM>>>(aohi, aolo, wthi + 3*WSZ, wtlo + 3*WSZ,
                                               out, nullptr, nullptr, nullptr,
                                               ROWS, DMODEL, INNER);
}

// round 7
// speedup vs baseline: 1.1221x; 1.1221x over previous
#include <cuda_runtime.h>
#include <cuda_bf16.h>
#include <stdint.h>
#include <math.h>

// Problem constants
#define S_LEN   2048
#define BATCH   2
#define NHEAD   16
#define HDIM    128
#define DMODEL  2048
#define INNER   2048          // NHEAD*HDIM
#define ROWS    (BATCH*S_LEN) // 4096

// Scratch (allocation forbidden -> __device__ globals)
__device__ __nv_bfloat16 g_xhi[(size_t)ROWS * DMODEL];
__device__ __nv_bfloat16 g_xlo[(size_t)ROWS * DMODEL];
__device__ __nv_bfloat16 g_wthi[4][(size_t)DMODEL * INNER];  // W^T per matrix, [N,K]
__device__ __nv_bfloat16 g_wtlo[4][(size_t)DMODEL * INNER];
__device__ __nv_bfloat16 g_qhi[(size_t)ROWS * INNER];
__device__ __nv_bfloat16 g_qlo[(size_t)ROWS * INNER];
__device__ __nv_bfloat16 g_khi[(size_t)ROWS * INNER];
__device__ __nv_bfloat16 g_klo[(size_t)ROWS * INNER];
__device__ __nv_bfloat16 g_vhi[(size_t)ROWS * INNER];
__device__ __nv_bfloat16 g_vlo[(size_t)ROWS * INNER];
__device__ __nv_bfloat16 g_aohi[(size_t)ROWS * INNER];
__device__ __nv_bfloat16 g_aolo[(size_t)ROWS * INNER];

// ---------------------------------------------------------------------------
// Helpers (base PTX only: cp.async / ldmatrix / mma.sync)
// ---------------------------------------------------------------------------
__device__ __forceinline__ uint32_t smem_u32(const void* p) {
    uint32_t a;
    asm("{ .reg .u64 t; cvta.to.shared.u64 t, %1; cvt.u32.u64 %0, t; }"
        : "=r"(a) : "l"(p));
    return a;
}
__device__ __forceinline__ void cp16(uint32_t dst, const void* src) {
    asm volatile("cp.async.cg.shared.global [%0], [%1], 16;" :: "r"(dst), "l"(src));
}
__device__ __forceinline__ void cp_commit() { asm volatile("cp.async.commit_group;"); }
template<int N> __device__ __forceinline__ void cp_wait() {
    asm volatile("cp.async.wait_group %0;" :: "n"(N));
}
__device__ __forceinline__ void ldm_x4(uint32_t* r, uint32_t addr) {
    asm volatile("ldmatrix.sync.aligned.m8n8.x4.shared.b16 {%0,%1,%2,%3}, [%4];"
                 : "=r"(r[0]), "=r"(r[1]), "=r"(r[2]), "=r"(r[3]) : "r"(addr));
}
__device__ __forceinline__ void ldm_x4t(uint32_t* r, uint32_t addr) {
    asm volatile("ldmatrix.sync.aligned.m8n8.x4.trans.shared.b16 {%0,%1,%2,%3}, [%4];"
                 : "=r"(r[0]), "=r"(r[1]), "=r"(r[2]), "=r"(r[3]) : "r"(addr));
}
__device__ __forceinline__ void mma16816(float* c, const uint32_t* a, const uint32_t* b) {
    asm volatile(
        "mma.sync.aligned.m16n8k16.row.col.f32.bf16.bf16.f32 "
        "{%0,%1,%2,%3}, {%4,%5,%6,%7}, {%8,%9}, {%0,%1,%2,%3};"
        : "+f"(c[0]), "+f"(c[1]), "+f"(c[2]), "+f"(c[3])
        : "r"(a[0]), "r"(a[1]), "r"(a[2]), "r"(a[3]), "r"(b[0]), "r"(b[1]));
}
__device__ __forceinline__ uint32_t pack_bf2(float a, float b) {
    __nv_bfloat162 t = __floats2bfloat162_rn(a, b);
    return *(uint32_t*)&t;
}
__device__ __forceinline__ void split1(float v, __nv_bfloat16& h, float& r) {
    h = __float2bfloat16(v);
    r = v - __bfloat162float(h);
}

// ---------------------------------------------------------------------------
// bf16 hi/lo split GEMM: C = A[M,K] @ Bt[N,K]^T (hh+hl+lh).
// CTA tile 256x128, BK=32, 256 threads (8 warps as 4x2, warp tile 64x64),
// 2-stage cp.async pipeline. MODE 0: fp32 C. MODE 1: split C. MODE 2: RMS+split.
// ---------------------------------------------------------------------------
#define G_BM 256
#define G_BN 128
#define G_BK 32
#define ROWB 80
#define A_TILEB (256 * ROWB)          // 20480
#define B_TILEB (128 * ROWB)          // 10240
#define STAGEB (2 * A_TILEB + 2 * B_TILEB)   // 61440
#define GEMM_SMEM (2 * STAGEB)        // 122880

template<int MODE>
__global__ __launch_bounds__(256, 1)
void gemm_mma_kernel(const __nv_bfloat16* __restrict__ Ahi,
                     const __nv_bfloat16* __restrict__ Alo,
                     const __nv_bfloat16* __restrict__ Bhi,
                     const __nv_bfloat16* __restrict__ Blo,
                     float* __restrict__ C,
                     __nv_bfloat16* __restrict__ Chi,
                     __nv_bfloat16* __restrict__ Clo,
                     const float* __restrict__ gamma,
                     int M, int N, int K)
{
    extern __shared__ char smem[];
    const uint32_t sbase = smem_u32(smem);
    const int tid  = threadIdx.x;
    const int warp = tid >> 5;
    const int lane = tid & 31;
    const int wm = warp >> 1;          // 0..3 -> 64 rows each
    const int wn = warp & 1;           // 0..1 -> 64 cols each

    const int row0 = blockIdx.y * G_BM;
    const int col0 = blockIdx.x * G_BN;
    const size_t Kb = (size_t)K * 2;

    const char* gpA[2] = {
        (const char*)Ahi + (size_t)row0 * Kb,
        (const char*)Alo + (size_t)row0 * Kb
    };
    const char* gpB[2] = {
        (const char*)Bhi + (size_t)col0 * Kb,
        (const char*)Blo + (size_t)col0 * Kb
    };

    float acc[4][8][4];
#pragma unroll
    for (int mt = 0; mt < 4; mt++)
#pragma unroll
        for (int nt = 0; nt < 8; nt++)
#pragma unroll
            for (int r = 0; r < 4; r++) acc[mt][nt][r] = 0.0f;

    const int NCH = K / G_BK;

    // Per-warp invariant pieces of the ldmatrix addresses
    const uint32_t a_rowbase = (wm * 64 + (lane & 15)) * ROWB;
    const uint32_t b_rowbase = (wn * 64 + (lane & 7) + 8 * (lane >> 4)) * ROWB;
    const uint32_t a_klane   = 16 * (lane >> 4);          // bytes: 8 cols * 2B
    const uint32_t b_klane   = 16 * ((lane >> 3) & 1);

    auto load_chunk = [&](int c, int s) {
        size_t koff = (size_t)c * (G_BK * 2);
        uint32_t stb = sbase + s * STAGEB;
#pragma unroll
        for (int t = 0; t < 2; t++) {          // A hi/lo: 256 rows
            uint32_t tb = stb + t * A_TILEB;
            const char* g = gpA[t];
#pragma unroll
            for (int i = 0; i < 4; i++) {
                int idx = i * 256 + tid;       // 0..1023
                int row = idx >> 2;
                int ks  = idx & 3;
                cp16(tb + row * ROWB + ks * 16,
                     g + (size_t)row * Kb + koff + ks * 16);
            }
        }
#pragma unroll
        for (int t = 0; t < 2; t++) {          // B hi/lo: 128 rows
            uint32_t tb = stb + 2 * A_TILEB + t * B_TILEB;
            const char* g = gpB[t];
#pragma unroll
            for (int i = 0; i < 2; i++) {
                int idx = i * 256 + tid;       // 0..511
                int row = idx >> 2;
                int ks  = idx & 3;
                cp16(tb + row * ROWB + ks * 16,
                     g + (size_t)row * Kb + koff + ks * 16);
            }
        }
    };

    load_chunk(0, 0);
    cp_commit();

    for (int c = 0; c < NCH; ++c) {
        const int buf = c & 1;
        cp_wait<0>();
        __syncthreads();
        if (c + 1 < NCH) {
            load_chunk(c + 1, buf ^ 1);
            cp_commit();
        }

        const uint32_t base  = sbase + buf * STAGEB;
        const uint32_t baseB = base + 2 * A_TILEB;
#pragma unroll
        for (int ks = 0; ks < 2; ks++) {
            uint32_t ah[4][4], al[4][4];
#pragma unroll
            for (int mt = 0; mt < 4; mt++) {
                uint32_t aoff = a_rowbase + mt * (16 * ROWB) + ks * 32 + a_klane;
                ldm_x4(ah[mt], base + aoff);
                ldm_x4(al[mt], base + A_TILEB + aoff);
            }
            uint32_t bh[8][2], bl[8][2];
#pragma unroll
            for (int p = 0; p < 4; p++) {
                uint32_t boff = b_rowbase + p * (16 * ROWB) + ks * 32 + b_klane;
                uint32_t t0[4], t1[4];
                ldm_x4(t0, baseB + boff);
                ldm_x4(t1, baseB + B_TILEB + boff);
                bh[2*p][0]   = t0[0]; bh[2*p][1]   = t0[1];
                bh[2*p+1][0] = t0[2]; bh[2*p+1][1] = t0[3];
                bl[2*p][0]   = t1[0]; bl[2*p][1]   = t1[1];
                bl[2*p+1][0] = t1[2]; bl[2*p+1][1] = t1[3];
            }
#pragma unroll
            for (int mt = 0; mt < 4; mt++)
#pragma unroll
                for (int nt = 0; nt < 8; nt++) {
                    mma16816(acc[mt][nt], ah[mt], bh[nt]);
                    mma16816(acc[mt][nt], ah[mt], bl[nt]);
                    mma16816(acc[mt][nt], al[mt], bh[nt]);
                }
        }
        __syncthreads();
    }

    if (MODE == 0) {
#pragma unroll
        for (int mt = 0; mt < 4; mt++) {
            int r0 = row0 + wm * 64 + mt * 16 + (lane >> 2);
#pragma unroll
            for (int nt = 0; nt < 8; nt++) {
                int cc = col0 + wn * 64 + nt * 8 + (lane & 3) * 2;
                *(float2*)(C + (size_t)r0 * N + cc) =
                    make_float2(acc[mt][nt][0], acc[mt][nt][1]);
                *(float2*)(C + (size_t)(r0 + 8) * N + cc) =
                    make_float2(acc[mt][nt][2], acc[mt][nt][3]);
            }
        }
    } else if (MODE == 1) {
#pragma unroll
        for (int mt = 0; mt < 4; mt++) {
            int r0 = row0 + wm * 64 + mt * 16 + (lane >> 2);
#pragma unroll
            for (int nt = 0; nt < 8; nt++) {
                int cc = col0 + wn * 64 + nt * 8 + (lane & 3) * 2;
                __nv_bfloat16 h0, h1; float l0, l1;
                split1(acc[mt][nt][0], h0, l0);
                split1(acc[mt][nt][1], h1, l1);
                __nv_bfloat162 hp; hp.x = h0; hp.y = h1;
                *(uint32_t*)(Chi + (size_t)r0 * N + cc) = *(uint32_t*)&hp;
                *(uint32_t*)(Clo + (size_t)r0 * N + cc) = pack_bf2(l0, l1);
                split1(acc[mt][nt][2], h0, l0);
                split1(acc[mt][nt][3], h1, l1);
                __nv_bfloat162 hq; hq.x = h0; hq.y = h1;
                *(uint32_t*)(Chi + (size_t)(r0 + 8) * N + cc) = *(uint32_t*)&hq;
                *(uint32_t*)(Clo + (size_t)(r0 + 8) * N + cc) = pack_bf2(l0, l1);
            }
        }
    } else {
        // MODE 2: two half-passes of 128 rows; per-row (=head) RMSNorm + split
        float* CS = (float*)smem;      // 128 x 132 fp32 = 67584 B
        float4 g4 = *(const float4*)(gamma + lane * 4);
#pragma unroll
        for (int half = 0; half < 2; half++) {
            __syncthreads();
            if ((wm >> 1) == half) {
                int rbase = (wm & 1) * 64;
#pragma unroll
                for (int mt = 0; mt < 4; mt++) {
                    int r = rbase + mt * 16 + (lane >> 2);
#pragma unroll
                    for (int nt = 0; nt < 8; nt++) {
                        int cc = wn * 64 + nt * 8 + (lane & 3) * 2;
                        CS[r * 132 + cc]         = acc[mt][nt][0];
                        CS[r * 132 + cc + 1]     = acc[mt][nt][1];
                        CS[(r+8) * 132 + cc]     = acc[mt][nt][2];
                        CS[(r+8) * 132 + cc + 1] = acc[mt][nt][3];
                    }
                }
            }
            __syncthreads();
#pragma unroll
            for (int rr = 0; rr < 16; rr++) {
                int row = warp * 16 + rr;          // 0..127 local
                float4 v = *(float4*)&CS[row * 132 + lane * 4];
                float ss = v.x*v.x + v.y*v.y + v.z*v.z + v.w*v.w;
#pragma unroll
                for (int o = 16; o > 0; o >>= 1)
                    ss += __shfl_xor_sync(0xffffffffu, ss, o);
                float rn = rsqrtf(ss * (1.0f / 128.0f) + 1e-6f);
                float f[4] = { v.x*rn*g4.x, v.y*rn*g4.y, v.z*rn*g4.z, v.w*rn*g4.w };
                __nv_bfloat16 h[4]; float l[4];
#pragma unroll
                for (int j = 0; j < 4; j++) split1(f[j], h[j], l[j]);
                size_t o = (size_t)(row0 + half * 128 + row) * N + col0 + lane * 4;
                *(uint2*)(Chi + o) = *(uint2*)h;
                uint2 lp; lp.x = pack_bf2(l[0], l[1]); lp.y = pack_bf2(l[2], l[3]);
                *(uint2*)(Clo + o) = lp;
            }
        }
    }
}

// ---------------------------------------------------------------------------
// Flash attention, mma.sync bf16 hi/lo (R4-proven shape: 64x64, 128 thr, occ 2)
// ---------------------------------------------------------------------------
#define F_ROWB 272
#define FT_BYTES (64 * F_ROWB)          // 17408
#define FLASH_SMEM (6 * FT_BYTES)       // 104448

__global__ __launch_bounds__(128, 2)
void flash_mma_kernel(const __nv_bfloat16* __restrict__ Qhi,
                      const __nv_bfloat16* __restrict__ Qlo,
                      const __nv_bfloat16* __restrict__ Khi,
                      const __nv_bfloat16* __restrict__ Klo,
                      const __nv_bfloat16* __restrict__ Vhi,
                      const __nv_bfloat16* __restrict__ Vlo,
                      __nv_bfloat16* __restrict__ Ohi,
                      __nv_bfloat16* __restrict__ Olo)
{
    extern __shared__ char sm_raw[];
    const uint32_t sb = smem_u32(sm_raw);
    const uint32_t sQh = sb,                sQl = sb + FT_BYTES;
    const uint32_t sKh = sb + 2*FT_BYTES,   sKl = sb + 3*FT_BYTES;
    const uint32_t sVh = sb + 4*FT_BYTES,   sVl = sb + 5*FT_BYTES;

    const int tid  = threadIdx.x;
    const int warp = tid >> 5;
    const int lane = tid & 31;
    const int lr   = lane >> 2;
    const int lc   = lane & 3;
    const int m0   = warp * 16;

    const int mblk = blockIdx.x, h = blockIdx.y, b = blockIdx.z;
    const size_t qoff = ((size_t)(b * S_LEN + mblk * 64)) * INNER + h * HDIM;
    const size_t koff = ((size_t)(b * S_LEN)) * INNER + h * HDIM;

#pragma unroll
    for (int i = 0; i < 8; i++) {
        int idx = i * 128 + tid;
        int r = idx >> 4, s = idx & 15;
        uint32_t so = r * F_ROWB + s * 16;
        const size_t go = qoff + (size_t)r * INNER + s * 8;
        cp16(sQh + so, Qhi + go);
        cp16(sQl + so, Qlo + go);
    }
    cp_commit();

    float o[16][4];
#pragma unroll
    for (int nt = 0; nt < 16; nt++)
#pragma unroll
        for (int r = 0; r < 4; r++) o[nt][r] = 0.0f;
    float s_m[2] = { -1e30f, -1e30f };
    float s_l[2] = { 0.0f, 0.0f };
    const float scale = 0.08838834764831845f;

    const uint32_t a_row = m0 + (lane & 15);
    const uint32_t lhalf = 8 * (lane >> 4);

    for (int n0 = 0; n0 < S_LEN; n0 += 64) {
#pragma unroll
        for (int i = 0; i < 8; i++) {
            int idx = i * 128 + tid;
            int r = idx >> 4, s = idx & 15;
            uint32_t so = r * F_ROWB + s * 16;
            const size_t go = koff + (size_t)(n0 + r) * INNER + s * 8;
            cp16(sKh + so, Khi + go);
            cp16(sKl + so, Klo + go);
            cp16(sVh + so, Vhi + go);
            cp16(sVl + so, Vlo + go);
        }
        cp_commit();
        cp_wait<0>();
        __syncthreads();

        float s[8][4];
#pragma unroll
        for (int j = 0; j < 8; j++)
#pragma unroll
            for (int r = 0; r < 4; r++) s[j][r] = 0.0f;

#pragma unroll
        for (int t = 0; t < 8; t++) {
            const int d0 = t * 16;
            uint32_t ah[4], al[4];
            uint32_t aoff = a_row * F_ROWB + (d0 + lhalf) * 2;
            ldm_x4(ah, sQh + aoff);
            ldm_x4(al, sQl + aoff);
#pragma unroll
            for (int p = 0; p < 4; p++) {
                uint32_t bh[4], bl[4];
                uint32_t boff = (p * 16 + (lane & 15)) * F_ROWB + (d0 + lhalf) * 2;
                ldm_x4(bh, sKh + boff);
                ldm_x4(bl, sKl + boff);
                uint32_t b0h[2] = { bh[0], bh[2] }, b1h[2] = { bh[1], bh[3] };
                uint32_t b0l[2] = { bl[0], bl[2] }, b1l[2] = { bl[1], bl[3] };
                mma16816(s[2*p],   ah, b0h);
                mma16816(s[2*p],   ah, b0l);
                mma16816(s[2*p],   al, b0h);
                mma16816(s[2*p+1], ah, b1h);
                mma16816(s[2*p+1], ah, b1l);
                mma16816(s[2*p+1], al, b1h);
            }
        }

#pragma unroll
        for (int j = 0; j < 8; j++)
#pragma unroll
            for (int r = 0; r < 4; r++) s[j][r] *= scale;

        float mx0 = -1e30f, mx1 = -1e30f;
#pragma unroll
        for (int j = 0; j < 8; j++) {
            mx0 = fmaxf(mx0, fmaxf(s[j][0], s[j][1]));
            mx1 = fmaxf(mx1, fmaxf(s[j][2], s[j][3]));
        }
        mx0 = fmaxf(mx0, __shfl_xor_sync(0xffffffffu, mx0, 1));
        mx0 = fmaxf(mx0, __shfl_xor_sync(0xffffffffu, mx0, 2));
        mx1 = fmaxf(mx1, __shfl_xor_sync(0xffffffffu, mx1, 1));
        mx1 = fmaxf(mx1, __shfl_xor_sync(0xffffffffu, mx1, 2));

        float mn0 = fmaxf(s_m[0], mx0), mn1 = fmaxf(s_m[1], mx1);
        float al0 = __expf(s_m[0] - mn0), al1 = __expf(s_m[1] - mn1);
        s_m[0] = mn0; s_m[1] = mn1;

        float rs0 = 0.0f, rs1 = 0.0f;
#pragma unroll
        for (int j = 0; j < 8; j++) {
            s[j][0] = __expf(s[j][0] - mn0);
            s[j][1] = __expf(s[j][1] - mn0);
            s[j][2] = __expf(s[j][2] - mn1);
            s[j][3] = __expf(s[j][3] - mn1);
            rs0 += s[j][0] + s[j][1];
            rs1 += s[j][2] + s[j][3];
        }
        rs0 += __shfl_xor_sync(0xffffffffu, rs0, 1);
        rs0 += __shfl_xor_sync(0xffffffffu, rs0, 2);
        rs1 += __shfl_xor_sync(0xffffffffu, rs1, 1);
        rs1 += __shfl_xor_sync(0xffffffffu, rs1, 2);
        s_l[0] = s_l[0] * al0 + rs0;
        s_l[1] = s_l[1] * al1 + rs1;

#pragma unroll
        for (int nt = 0; nt < 16; nt++) {
            o[nt][0] *= al0; o[nt][1] *= al0;
            o[nt][2] *= al1; o[nt][3] *= al1;
        }

        uint32_t ph[4][4], pl[4][4];
#pragma unroll
        for (int t = 0; t < 4; t++) {
#pragma unroll
            for (int q = 0; q < 4; q++) {
                int j = 2 * t + (q >> 1);
                int cc = (q & 1) * 2;
                float v0 = s[j][cc], v1 = s[j][cc + 1];
                __nv_bfloat16 h0, h1; float r0, r1;
                split1(v0, h0, r0);
                split1(v1, h1, r1);
                __nv_bfloat162 hp; hp.x = h0; hp.y = h1;
                ph[t][q] = *(uint32_t*)&hp;
                pl[t][q] = pack_bf2(r0, r1);
            }
        }

#pragma unroll
        for (int t = 0; t < 4; t++) {
#pragma unroll
            for (int np = 0; np < 8; np++) {
                uint32_t vh[4], vl[4];
                uint32_t voff = (t * 16 + (lane & 15)) * F_ROWB + (np * 16 + lhalf) * 2;
                ldm_x4t(vh, sVh + voff);
                ldm_x4t(vl, sVl + voff);
                uint32_t b0h[2] = { vh[0], vh[1] }, b1h[2] = { vh[2], vh[3] };
                uint32_t b0l[2] = { vl[0], vl[1] }, b1l[2] = { vl[2], vl[3] };
                mma16816(o[2*np],   ph[t], b0h);
                mma16816(o[2*np],   ph[t], b0l);
                mma16816(o[2*np],   pl[t], b0h);
                mma16816(o[2*np+1], ph[t], b1h);
                mma16816(o[2*np+1], ph[t], b1l);
                mma16816(o[2*np+1], pl[t], b1h);
            }
        }
        __syncthreads();
    }

    float inv0 = 1.0f / s_l[0];
    float inv1 = 1.0f / s_l[1];
    size_t or0 = ((size_t)(b * S_LEN + mblk * 64 + m0 + lr)) * INNER + h * HDIM;
    size_t or1 = or0 + 8 * (size_t)INNER;
#pragma unroll
    for (int nt = 0; nt < 16; nt++) {
        int col = nt * 8 + lc * 2;
        float a0 = o[nt][0] * inv0, a1 = o[nt][1] * inv0;
        float b0 = o[nt][2] * inv1, b1 = o[nt][3] * inv1;
        __nv_bfloat16 h00, h01, h10, h11; float l00, l01, l10, l11;
        split1(a0, h00, l00); split1(a1, h01, l01);
        split1(b0, h10, l10); split1(b1, h11, l11);
        __nv_bfloat162 hp0; hp0.x = h00; hp0.y = h01;
        __nv_bfloat162 hp1; hp1.x = h10; hp1.y = h11;
        *(uint32_t*)(Ohi + or0 + col) = *(uint32_t*)&hp0;
        *(uint32_t*)(Ohi + or1 + col) = *(uint32_t*)&hp1;
        *(uint32_t*)(Olo + or0 + col) = pack_bf2(l00, l01);
        *(uint32_t*)(Olo + or1 + col) = pack_bf2(l10, l11);
    }
}

// ---------------------------------------------------------------------------
// fp32 -> bf16 hi/lo split (elementwise)
// ---------------------------------------------------------------------------
__global__ void split_kernel(const float4* __restrict__ in,
                             __nv_bfloat16* __restrict__ hi,
                             __nv_bfloat16* __restrict__ lo, int n4) {
    int i = blockIdx.x * blockDim.x + threadIdx.x;
    if (i >= n4) return;
    float4 v = in[i];
    float f[4] = { v.x, v.y, v.z, v.w };
    __nv_bfloat16 h[4]; float l[4];
#pragma unroll
    for (int j = 0; j < 4; j++) split1(f[j], h[j], l[j]);
    *(uint2*)(hi + 4 * (size_t)i) = *(uint2*)h;
    uint2 lp; lp.x = pack_bf2(l[0], l[1]); lp.y = pack_bf2(l[2], l[3]);
    *(uint2*)(lo + 4 * (size_t)i) = lp;
}

// ---------------------------------------------------------------------------
// Transpose + split: W[K, N] fp32 -> T{hi,lo}[N, K] bf16
// ---------------------------------------------------------------------------
__global__ void transpose_split_kernel(const float* __restrict__ W,
                                       __nv_bfloat16* __restrict__ Thi,
                                       __nv_bfloat16* __restrict__ Tlo) {
    __shared__ float t[32][33];
    int n0 = blockIdx.x * 32, k0 = blockIdx.y * 32;
#pragma unroll
    for (int i = 0; i < 32; i += 8)
        t[threadIdx.y + i][threadIdx.x] =
            W[(size_t)(k0 + threadIdx.y + i) * 2048 + n0 + threadIdx.x];
    __syncthreads();
#pragma unroll
    for (int i = 0; i < 32; i += 8) {
        float v = t[threadIdx.x][threadIdx.y + i];
        __nv_bfloat16 h; float l;
        split1(v, h, l);
        size_t o = (size_t)(n0 + threadIdx.y + i) * 2048 + k0 + threadIdx.x;
        Thi[o] = h;
        Tlo[o] = __float2bfloat16(l);
    }
}

// ---------------------------------------------------------------------------
// Launcher  (launch order arranged so the ncu capture slot hits a GEMM)
// ---------------------------------------------------------------------------
extern "C" void kernel_launch(void* const* d_in, const int* in_sizes, int n_in,
                              void* d_out, int out_size) {
    const float* x  = (const float*)d_in[0];
    const float* Wq = (const float*)d_in[1];
    const float* Wk = (const float*)d_in[2];
    const float* Wv = (const float*)d_in[3];
    const float* Wo = (const float*)d_in[4];
    const float* qg = (const float*)d_in[5];
    const float* kg = (const float*)d_in[6];
    float* out = (float*)d_out;

    __nv_bfloat16 *xhi, *xlo, *wthi, *wtlo;
    __nv_bfloat16 *qhi, *qlo, *khi, *klo, *vhi, *vlo, *aohi, *aolo;
    cudaGetSymbolAddress((void**)&xhi,  g_xhi);
    cudaGetSymbolAddress((void**)&xlo,  g_xlo);
    cudaGetSymbolAddress((void**)&wthi, g_wthi);
    cudaGetSymbolAddress((void**)&wtlo, g_wtlo);
    cudaGetSymbolAddress((void**)&qhi,  g_qhi);
    cudaGetSymbolAddress((void**)&qlo,  g_qlo);
    cudaGetSymbolAddress((void**)&khi,  g_khi);
    cudaGetSymbolAddress((void**)&klo,  g_klo);
    cudaGetSymbolAddress((void**)&vhi,  g_vhi);
    cudaGetSymbolAddress((void**)&vlo,  g_vlo);
    cudaGetSymbolAddress((void**)&aohi, g_aohi);
    cudaGetSymbolAddress((void**)&aolo, g_aolo);
    const size_t WSZ = (size_t)DMODEL * INNER;

    cudaFuncSetAttribute(gemm_mma_kernel<0>, cudaFuncAttributeMaxDynamicSharedMemorySize, GEMM_SMEM);
    cudaFuncSetAttribute(gemm_mma_kernel<1>, cudaFuncAttributeMaxDynamicSharedMemorySize, GEMM_SMEM);
    cudaFuncSetAttribute(gemm_mma_kernel<2>, cudaFuncAttributeMaxDynamicSharedMemorySize, GEMM_SMEM);
    cudaFuncSetAttribute(flash_mma_kernel, cudaFuncAttributeMaxDynamicSharedMemorySize, FLASH_SMEM);

    dim3 tb(32, 8), tg(64, 64);
    dim3 gg(INNER / G_BN, ROWS / G_BM);   // (16, 16)
    dim3 gridF(S_LEN / 64, NHEAD, BATCH);

    // launch 0: split x
    int n4x = ROWS * DMODEL / 4;
    split_kernel<<<n4x / 256, 256>>>((const float4*)x, xhi, xlo, n4x);
    // launches 1-3: transpose Wq, Wk, Wv
    transpose_split_kernel<<<tg, tb>>>(Wq, wthi + 0*WSZ, wtlo + 0*WSZ);
    transpose_split_kernel<<<tg, tb>>>(Wk, wthi + 1*WSZ, wtlo + 1*WSZ);
    transpose_split_kernel<<<tg, tb>>>(Wv, wthi + 2*WSZ, wtlo + 2*WSZ);
    // launch 4 (ncu capture slot): V projection
    gemm_mma_kernel<1><<<gg, 256, GEMM_SMEM>>>(xhi, xlo, wthi + 2*WSZ, wtlo + 2*WSZ,
                                               nullptr, vhi, vlo, nullptr,
                                               ROWS, INNER, DMODEL);
    // launch 5: transpose Wo
    transpose_split_kernel<<<tg, tb>>>(Wo, wthi + 3*WSZ, wtlo + 3*WSZ);
    // launches 6-7: Q, K projections with fused RMSNorm
    gemm_mma_kernel<2><<<gg, 256, GEMM_SMEM>>>(xhi, xlo, wthi + 0*WSZ, wtlo + 0*WSZ,
                                               nullptr, qhi, qlo, qg,
                                               ROWS, INNER, DMODEL);
    gemm_mma_kernel<2><<<gg, 256, GEMM_SMEM>>>(xhi, xlo, wthi + 1*WSZ, wtlo + 1*WSZ,
                                               nullptr, khi, klo, kg,
                                               ROWS, INNER, DMODEL);
    // launch 8: flash attention
    flash_mma_kernel<<<gridF, 128, FLASH_SMEM>>>(qhi, qlo, khi, klo, vhi, vlo,
                                                 aohi, aolo);
    // launch 9: output projection
    gemm_mma_kernel<0><<<gg, 256, GEMM_SMEM>>>(aohi, aolo, wthi + 3*WSZ, wtlo + 3*WSZ,
                                               out, nullptr, nullptr, nullptr,
                                               ROWS, DMODEL, INNER);
}

// round 9
// speedup vs baseline: 1.3701x; 1.2211x over previous
#include <cuda_runtime.h>
#include <cuda_bf16.h>
#include <stdint.h>
#include <math.h>

// Problem constants
#define S_LEN   2048
#define BATCH   2
#define NHEAD   16
#define HDIM    128
#define DMODEL  2048
#define INNER   2048          // NHEAD*HDIM
#define ROWS    (BATCH*S_LEN) // 4096

// Scratch (allocation forbidden -> __device__ globals)
// xhi/xlo, wthi/wtlo, aohi/aolo are stored in TILED+SWIZZLED layouts (below),
// 1024B-aligned because cp.async.bulk requires >=16B-aligned global addresses.
// q/k/v hi/lo stay row-major [ROWS, INNER] for the flash kernel.
__device__ __align__(1024) __nv_bfloat16 g_xhi[(size_t)ROWS * DMODEL];
__device__ __align__(1024) __nv_bfloat16 g_xlo[(size_t)ROWS * DMODEL];
__device__ __align__(1024) __nv_bfloat16 g_wthi[4][(size_t)DMODEL * INNER];
__device__ __align__(1024) __nv_bfloat16 g_wtlo[4][(size_t)DMODEL * INNER];
__device__ __align__(1024) __nv_bfloat16 g_qhi[(size_t)ROWS * INNER];
__device__ __align__(1024) __nv_bfloat16 g_qlo[(size_t)ROWS * INNER];
__device__ __align__(1024) __nv_bfloat16 g_khi[(size_t)ROWS * INNER];
__device__ __align__(1024) __nv_bfloat16 g_klo[(size_t)ROWS * INNER];
__device__ __align__(1024) __nv_bfloat16 g_vhi[(size_t)ROWS * INNER];
__device__ __align__(1024) __nv_bfloat16 g_vlo[(size_t)ROWS * INNER];
__device__ __align__(1024) __nv_bfloat16 g_aohi[(size_t)ROWS * INNER];
__device__ __align__(1024) __nv_bfloat16 g_aolo[(size_t)ROWS * INNER];

// ---------------------------------------------------------------------------
// Tiled layouts (element offsets in bf16 units).
// A-tiled: 256-row blocks x 32-col chunks; tile = 256x32 = 8192 elems (16KB).
//   within tile: elem (rl, kl) at rl*32 + ((ch ^ ((rl>>1)&3))<<3) + w,
//   ch = kl>>3, w = kl&7.  (XOR swizzle -> conflict-free ldmatrix @64B rows)
// B-tiled: 128-row blocks; tile = 128x32 = 4096 elems (8KB), same swizzle.
// ---------------------------------------------------------------------------
__device__ __forceinline__ size_t a_tile_off(int rg, int k, int K) {
    int rb = rg >> 8, rl = rg & 255, c = k >> 5, kl = k & 31;
    int ch = kl >> 3, w = kl & 7;
    return ((size_t)(rb * (K >> 5) + c) << 13) + rl * 32 +
           (((ch ^ ((rl >> 1) & 3)) << 3) + w);
}
__device__ __forceinline__ size_t b_tile_off(int n, int k, int K) {
    int nb = n >> 7, nl = n & 127, c = k >> 5, kl = k & 31;
    int ch = kl >> 3, w = kl & 7;
    return ((size_t)(nb * (K >> 5) + c) << 12) + nl * 32 +
           (((ch ^ ((nl >> 1) & 3)) << 3) + w);
}

// ---------------------------------------------------------------------------
// PTX helpers
// ---------------------------------------------------------------------------
__device__ __forceinline__ uint32_t smem_u32(const void* p) {
    uint32_t a;
    asm("{ .reg .u64 t; cvta.to.shared.u64 t, %1; cvt.u32.u64 %0, t; }"
        : "=r"(a) : "l"(p));
    return a;
}
__device__ __forceinline__ void cp16(uint32_t dst, const void* src) {
    asm volatile("cp.async.cg.shared.global [%0], [%1], 16;" :: "r"(dst), "l"(src));
}
__device__ __forceinline__ void cp_commit() { asm volatile("cp.async.commit_group;"); }
template<int N> __device__ __forceinline__ void cp_wait() {
    asm volatile("cp.async.wait_group %0;" :: "n"(N));
}
__device__ __forceinline__ void bulkcp(uint32_t dst, const void* src,
                                       uint32_t bytes, uint32_t mbar) {
    asm volatile(
        "cp.async.bulk.shared::cluster.global.mbarrier::complete_tx::bytes "
        "[%0], [%1], %2, [%3];"
        :: "r"(dst), "l"(src), "r"(bytes), "r"(mbar) : "memory");
}
__device__ __forceinline__ void mbar_init(uint32_t a, uint32_t c) {
    asm volatile("mbarrier.init.shared.b64 [%0], %1;" :: "r"(a), "r"(c) : "memory");
}
__device__ __forceinline__ void mbar_expect(uint32_t mbar, uint32_t bytes) {
    asm volatile("mbarrier.arrive.expect_tx.shared.b64 _, [%0], %1;"
                 :: "r"(mbar), "r"(bytes) : "memory");
}
__device__ __forceinline__ void mbar_wait(uint32_t mbar, uint32_t parity) {
    asm volatile(
        "{\n\t.reg .pred P;\n\t"
        "WL_%=:\n\t"
        "mbarrier.try_wait.parity.shared.b64 P, [%0], %1;\n\t"
        "@P bra.uni WD_%=;\n\t"
        "bra.uni WL_%=;\n\t"
        "WD_%=:\n\t}"
        :: "r"(mbar), "r"(parity) : "memory");
}
__device__ __forceinline__ void fence_async() {
    asm volatile("fence.proxy.async.shared::cta;" ::: "memory");
}
__device__ __forceinline__ void ldm_x4(uint32_t* r, uint32_t addr) {
    asm volatile("ldmatrix.sync.aligned.m8n8.x4.shared.b16 {%0,%1,%2,%3}, [%4];"
                 : "=r"(r[0]), "=r"(r[1]), "=r"(r[2]), "=r"(r[3]) : "r"(addr));
}
__device__ __forceinline__ void ldm_x4t(uint32_t* r, uint32_t addr) {
    asm volatile("ldmatrix.sync.aligned.m8n8.x4.trans.shared.b16 {%0,%1,%2,%3}, [%4];"
                 : "=r"(r[0]), "=r"(r[1]), "=r"(r[2]), "=r"(r[3]) : "r"(addr));
}
__device__ __forceinline__ void mma16816(float* c, const uint32_t* a, const uint32_t* b) {
    asm volatile(
        "mma.sync.aligned.m16n8k16.row.col.f32.bf16.bf16.f32 "
        "{%0,%1,%2,%3}, {%4,%5,%6,%7}, {%8,%9}, {%0,%1,%2,%3};"
        : "+f"(c[0]), "+f"(c[1]), "+f"(c[2]), "+f"(c[3])
        : "r"(a[0]), "r"(a[1]), "r"(a[2]), "r"(a[3]), "r"(b[0]), "r"(b[1]));
}
__device__ __forceinline__ uint32_t pack_bf2(float a, float b) {
    __nv_bfloat162 t = __floats2bfloat162_rn(a, b);
    return *(uint32_t*)&t;
}
__device__ __forceinline__ void split1(float v, __nv_bfloat16& h, float& r) {
    h = __float2bfloat16(v);
    r = v - __bfloat162float(h);
}

// ---------------------------------------------------------------------------
// bf16 hi/lo split GEMM with cp.async.bulk tile loads.
// CTA 256x128, BK=32, 256 threads (warp tile 64x64), 3-stage mbarrier pipeline.
// Inputs A (tiled 256x32 blocks) and B (tiled 128x32 blocks), pre-swizzled.
// MODE 0: fp32 C.  MODE 1: bf16 split C.  MODE 2: RMSNorm + split C.
// ---------------------------------------------------------------------------
#define G_BM 256
#define G_BN 128
#define A_TB 16384               // bytes per A tile (hi or lo)
#define B_TB 8192
#define STAGEB (2 * A_TB + 2 * B_TB)   // 49152
#define NSTAGE 3
#define GEMM_SMEM (NSTAGE * STAGEB + 64)   // 147520

template<int MODE>
__global__ __launch_bounds__(256, 1)
void gemm_mma_kernel(const __nv_bfloat16* __restrict__ Ahi,
                     const __nv_bfloat16* __restrict__ Alo,
                     const __nv_bfloat16* __restrict__ Bhi,
                     const __nv_bfloat16* __restrict__ Blo,
                     float* __restrict__ C,
                     __nv_bfloat16* __restrict__ Chi,
                     __nv_bfloat16* __restrict__ Clo,
                     const float* __restrict__ gamma,
                     int M, int N, int K)
{
    extern __shared__ char smem[];
    const uint32_t sbase = smem_u32(smem);
    const uint32_t mbar0 = sbase + NSTAGE * STAGEB;
    const int tid  = threadIdx.x;
    const int warp = tid >> 5;
    const int lane = tid & 31;
    const int wm = warp >> 1;
    const int wn = warp & 1;

    const int rowblk = blockIdx.y;       // 256-row block
    const int colblk = blockIdx.x;       // 128-col block
    const int row0 = rowblk * G_BM;
    const int col0 = colblk * G_BN;
    const int KC = K >> 5;               // # of 32-col chunks

    if (tid == 0) {
#pragma unroll
        for (int s = 0; s < NSTAGE; s++) mbar_init(mbar0 + s * 8, 1);
        fence_async();
    }
    __syncthreads();

    float acc[4][8][4];
#pragma unroll
    for (int mt = 0; mt < 4; mt++)
#pragma unroll
        for (int nt = 0; nt < 8; nt++)
#pragma unroll
            for (int r = 0; r < 4; r++) acc[mt][nt][r] = 0.0f;

    auto issue = [&](int c, int s) {
        uint32_t stb = sbase + s * STAGEB;
        uint32_t mb = mbar0 + s * 8;
        const char* ah = (const char*)Ahi + (((size_t)(rowblk * KC + c)) << 14);
        const char* al = (const char*)Alo + (((size_t)(rowblk * KC + c)) << 14);
        const char* bh = (const char*)Bhi + (((size_t)(colblk * KC + c)) << 13);
        const char* bl = (const char*)Blo + (((size_t)(colblk * KC + c)) << 13);
        mbar_expect(mb, STAGEB);
        bulkcp(stb,            ah, A_TB, mb);
        bulkcp(stb + A_TB,     al, A_TB, mb);
        bulkcp(stb + 2 * A_TB, bh, B_TB, mb);
        bulkcp(stb + 2 * A_TB + B_TB, bl, B_TB, mb);
    };

    if (tid == 0) { issue(0, 0); issue(1, 1); }

    // per-lane invariant address pieces
    const int arow_l = (lane & 15);
    const int brow_l = (lane & 7) + 8 * (lane >> 4);
    const int a_chl  = lane >> 4;
    const int b_chl  = (lane >> 3) & 1;

    for (int c = 0; c < KC; ++c) {
        const int s = c % NSTAGE;
        if (tid == 0 && c + 2 < KC) issue(c + 2, (c + 2) % NSTAGE);
        mbar_wait(mbar0 + s * 8, (c / NSTAGE) & 1);

        const uint32_t sA  = sbase + s * STAGEB;
        const uint32_t sAl = sA + A_TB;
        const uint32_t sB  = sA + 2 * A_TB;
        const uint32_t sBl = sB + B_TB;
#pragma unroll
        for (int ks = 0; ks < 2; ks++) {
            uint32_t ah[4][4], al[4][4];
#pragma unroll
            for (int mt = 0; mt < 4; mt++) {
                int arow = wm * 64 + mt * 16 + arow_l;
                int ch = (2 * ks + a_chl) ^ ((arow >> 1) & 3);
                uint32_t aoff = arow * 64 + ch * 16;
                ldm_x4(ah[mt], sA  + aoff);
                ldm_x4(al[mt], sAl + aoff);
            }
            uint32_t bh[8][2], bl[8][2];
#pragma unroll
            for (int p = 0; p < 4; p++) {
                int brow = wn * 64 + p * 16 + brow_l;
                int ch = (2 * ks + b_chl) ^ ((brow >> 1) & 3);
                uint32_t boff = brow * 64 + ch * 16;
                uint32_t t0[4], t1[4];
                ldm_x4(t0, sB  + boff);
                ldm_x4(t1, sBl + boff);
                bh[2*p][0]   = t0[0]; bh[2*p][1]   = t0[1];
                bh[2*p+1][0] = t0[2]; bh[2*p+1][1] = t0[3];
                bl[2*p][0]   = t1[0]; bl[2*p][1]   = t1[1];
                bl[2*p+1][0] = t1[2]; bl[2*p+1][1] = t1[3];
            }
#pragma unroll
            for (int mt = 0; mt < 4; mt++)
#pragma unroll
                for (int nt = 0; nt < 8; nt++) {
                    mma16816(acc[mt][nt], ah[mt], bh[nt]);
                    mma16816(acc[mt][nt], ah[mt], bl[nt]);
                    mma16816(acc[mt][nt], al[mt], bh[nt]);
                }
        }
        __syncthreads();
    }

    if (MODE == 0) {
#pragma unroll
        for (int mt = 0; mt < 4; mt++) {
            int r0 = row0 + wm * 64 + mt * 16 + (lane >> 2);
#pragma unroll
            for (int nt = 0; nt < 8; nt++) {
                int cc = col0 + wn * 64 + nt * 8 + (lane & 3) * 2;
                *(float2*)(C + (size_t)r0 * N + cc) =
                    make_float2(acc[mt][nt][0], acc[mt][nt][1]);
                *(float2*)(C + (size_t)(r0 + 8) * N + cc) =
                    make_float2(acc[mt][nt][2], acc[mt][nt][3]);
            }
        }
    } else if (MODE == 1) {
        // row-major bf16 hi/lo output (consumed by flash)
#pragma unroll
        for (int mt = 0; mt < 4; mt++) {
            int r0 = row0 + wm * 64 + mt * 16 + (lane >> 2);
#pragma unroll
            for (int nt = 0; nt < 8; nt++) {
                int cc = col0 + wn * 64 + nt * 8 + (lane & 3) * 2;
                __nv_bfloat16 h0, h1; float l0, l1;
                split1(acc[mt][nt][0], h0, l0);
                split1(acc[mt][nt][1], h1, l1);
                __nv_bfloat162 hp; hp.x = h0; hp.y = h1;
                *(uint32_t*)(Chi + (size_t)r0 * N + cc) = *(uint32_t*)&hp;
                *(uint32_t*)(Clo + (size_t)r0 * N + cc) = pack_bf2(l0, l1);
                split1(acc[mt][nt][2], h0, l0);
                split1(acc[mt][nt][3], h1, l1);
                __nv_bfloat162 hq; hq.x = h0; hq.y = h1;
                *(uint32_t*)(Chi + (size_t)(r0 + 8) * N + cc) = *(uint32_t*)&hq;
                *(uint32_t*)(Clo + (size_t)(r0 + 8) * N + cc) = pack_bf2(l0, l1);
            }
        }
    } else {
        // MODE 2: per-row (=head) RMSNorm + split, row-major output
        float* CS = (float*)smem;      // 128 x 132 fp32
        float4 g4 = *(const float4*)(gamma + lane * 4);
#pragma unroll
        for (int half = 0; half < 2; half++) {
            __syncthreads();
            if ((wm >> 1) == half) {
                int rbase = (wm & 1) * 64;
#pragma unroll
                for (int mt = 0; mt < 4; mt++) {
                    int r = rbase + mt * 16 + (lane >> 2);
#pragma unroll
                    for (int nt = 0; nt < 8; nt++) {
                        int cc = wn * 64 + nt * 8 + (lane & 3) * 2;
                        CS[r * 132 + cc]         = acc[mt][nt][0];
                        CS[r * 132 + cc + 1]     = acc[mt][nt][1];
                        CS[(r+8) * 132 + cc]     = acc[mt][nt][2];
                        CS[(r+8) * 132 + cc + 1] = acc[mt][nt][3];
                    }
                }
            }
            __syncthreads();
#pragma unroll
            for (int rr = 0; rr < 16; rr++) {
                int row = warp * 16 + rr;
                float4 v = *(float4*)&CS[row * 132 + lane * 4];
                float ss = v.x*v.x + v.y*v.y + v.z*v.z + v.w*v.w;
#pragma unroll
                for (int o = 16; o > 0; o >>= 1)
                    ss += __shfl_xor_sync(0xffffffffu, ss, o);
                float rn = rsqrtf(ss * (1.0f / 128.0f) + 1e-6f);
                float f[4] = { v.x*rn*g4.x, v.y*rn*g4.y, v.z*rn*g4.z, v.w*rn*g4.w };
                __nv_bfloat16 h[4]; float l[4];
#pragma unroll
                for (int j = 0; j < 4; j++) split1(f[j], h[j], l[j]);
                size_t o = (size_t)(row0 + half * 128 + row) * N + col0 + lane * 4;
                *(uint2*)(Chi + o) = *(uint2*)h;
                uint2 lp; lp.x = pack_bf2(l[0], l[1]); lp.y = pack_bf2(l[2], l[3]);
                *(uint2*)(Clo + o) = lp;
            }
        }
    }
}

// ---------------------------------------------------------------------------
// Flash attention (R4/R7-proven shape: 64x64, 128 thr, occ 2, cp.async).
// Epilogue writes aohi/aolo in GEMM A-tiled layout.
// ---------------------------------------------------------------------------
#define F_ROWB 272
#define FT_BYTES (64 * F_ROWB)
#define FLASH_SMEM (6 * FT_BYTES)

__global__ __launch_bounds__(128, 2)
void flash_mma_kernel(const __nv_bfloat16* __restrict__ Qhi,
                      const __nv_bfloat16* __restrict__ Qlo,
                      const __nv_bfloat16* __restrict__ Khi,
                      const __nv_bfloat16* __restrict__ Klo,
                      const __nv_bfloat16* __restrict__ Vhi,
                      const __nv_bfloat16* __restrict__ Vlo,
                      __nv_bfloat16* __restrict__ Ohi,
                      __nv_bfloat16* __restrict__ Olo)
{
    extern __shared__ char sm_raw[];
    const uint32_t sb = smem_u32(sm_raw);
    const uint32_t sQh = sb,                sQl = sb + FT_BYTES;
    const uint32_t sKh = sb + 2*FT_BYTES,   sKl = sb + 3*FT_BYTES;
    const uint32_t sVh = sb + 4*FT_BYTES,   sVl = sb + 5*FT_BYTES;

    const int tid  = threadIdx.x;
    const int warp = tid >> 5;
    const int lane = tid & 31;
    const int lr   = lane >> 2;
    const int lc   = lane & 3;
    const int m0   = warp * 16;

    const int mblk = blockIdx.x, h = blockIdx.y, b = blockIdx.z;
    const size_t qoff = ((size_t)(b * S_LEN + mblk * 64)) * INNER + h * HDIM;
    const size_t koff = ((size_t)(b * S_LEN)) * INNER + h * HDIM;

#pragma unroll
    for (int i = 0; i < 8; i++) {
        int idx = i * 128 + tid;
        int r = idx >> 4, s = idx & 15;
        uint32_t so = r * F_ROWB + s * 16;
        const size_t go = qoff + (size_t)r * INNER + s * 8;
        cp16(sQh + so, Qhi + go);
        cp16(sQl + so, Qlo + go);
    }
    cp_commit();

    float o[16][4];
#pragma unroll
    for (int nt = 0; nt < 16; nt++)
#pragma unroll
        for (int r = 0; r < 4; r++) o[nt][r] = 0.0f;
    float s_m[2] = { -1e30f, -1e30f };
    float s_l[2] = { 0.0f, 0.0f };
    const float scale = 0.08838834764831845f;

    const uint32_t a_row = m0 + (lane & 15);
    const uint32_t lhalf = 8 * (lane >> 4);

    for (int n0 = 0; n0 < S_LEN; n0 += 64) {
#pragma unroll
        for (int i = 0; i < 8; i++) {
            int idx = i * 128 + tid;
            int r = idx >> 4, s = idx & 15;
            uint32_t so = r * F_ROWB + s * 16;
            const size_t go = koff + (size_t)(n0 + r) * INNER + s * 8;
            cp16(sKh + so, Khi + go);
            cp16(sKl + so, Klo + go);
            cp16(sVh + so, Vhi + go);
            cp16(sVl + so, Vlo + go);
        }
        cp_commit();
        cp_wait<0>();
        __syncthreads();

        float s[8][4];
#pragma unroll
        for (int j = 0; j < 8; j++)
#pragma unroll
            for (int r = 0; r < 4; r++) s[j][r] = 0.0f;

#pragma unroll
        for (int t = 0; t < 8; t++) {
            const int d0 = t * 16;
            uint32_t ah[4], al[4];
            uint32_t aoff = a_row * F_ROWB + (d0 + lhalf) * 2;
            ldm_x4(ah, sQh + aoff);
            ldm_x4(al, sQl + aoff);
#pragma unroll
            for (int p = 0; p < 4; p++) {
                uint32_t bh[4], bl[4];
                uint32_t boff = (p * 16 + (lane & 15)) * F_ROWB + (d0 + lhalf) * 2;
                ldm_x4(bh, sKh + boff);
                ldm_x4(bl, sKl + boff);
                uint32_t b0h[2] = { bh[0], bh[2] }, b1h[2] = { bh[1], bh[3] };
                uint32_t b0l[2] = { bl[0], bl[2] }, b1l[2] = { bl[1], bl[3] };
                mma16816(s[2*p],   ah, b0h);
                mma16816(s[2*p],   ah, b0l);
                mma16816(s[2*p],   al, b0h);
                mma16816(s[2*p+1], ah, b1h);
                mma16816(s[2*p+1], ah, b1l);
                mma16816(s[2*p+1], al, b1h);
            }
        }

#pragma unroll
        for (int j = 0; j < 8; j++)
#pragma unroll
            for (int r = 0; r < 4; r++) s[j][r] *= scale;

        float mx0 = -1e30f, mx1 = -1e30f;
#pragma unroll
        for (int j = 0; j < 8; j++) {
            mx0 = fmaxf(mx0, fmaxf(s[j][0], s[j][1]));
            mx1 = fmaxf(mx1, fmaxf(s[j][2], s[j][3]));
        }
        mx0 = fmaxf(mx0, __shfl_xor_sync(0xffffffffu, mx0, 1));
        mx0 = fmaxf(mx0, __shfl_xor_sync(0xffffffffu, mx0, 2));
        mx1 = fmaxf(mx1, __shfl_xor_sync(0xffffffffu, mx1, 1));
        mx1 = fmaxf(mx1, __shfl_xor_sync(0xffffffffu, mx1, 2));

        float mn0 = fmaxf(s_m[0], mx0), mn1 = fmaxf(s_m[1], mx1);
        float al0 = __expf(s_m[0] - mn0), al1 = __expf(s_m[1] - mn1);
        s_m[0] = mn0; s_m[1] = mn1;

        float rs0 = 0.0f, rs1 = 0.0f;
#pragma unroll
        for (int j = 0; j < 8; j++) {
            s[j][0] = __expf(s[j][0] - mn0);
            s[j][1] = __expf(s[j][1] - mn0);
            s[j][2] = __expf(s[j][2] - mn1);
            s[j][3] = __expf(s[j][3] - mn1);
            rs0 += s[j][0] + s[j][1];
            rs1 += s[j][2] + s[j][3];
        }
        rs0 += __shfl_xor_sync(0xffffffffu, rs0, 1);
        rs0 += __shfl_xor_sync(0xffffffffu, rs0, 2);
        rs1 += __shfl_xor_sync(0xffffffffu, rs1, 1);
        rs1 += __shfl_xor_sync(0xffffffffu, rs1, 2);
        s_l[0] = s_l[0] * al0 + rs0;
        s_l[1] = s_l[1] * al1 + rs1;

#pragma unroll
        for (int nt = 0; nt < 16; nt++) {
            o[nt][0] *= al0; o[nt][1] *= al0;
            o[nt][2] *= al1; o[nt][3] *= al1;
        }

        uint32_t ph[4][4], pl[4][4];
#pragma unroll
        for (int t = 0; t < 4; t++) {
#pragma unroll
            for (int q = 0; q < 4; q++) {
                int j = 2 * t + (q >> 1);
                int cc = (q & 1) * 2;
                float v0 = s[j][cc], v1 = s[j][cc + 1];
                __nv_bfloat16 h0, h1; float r0, r1;
                split1(v0, h0, r0);
                split1(v1, h1, r1);
                __nv_bfloat162 hp; hp.x = h0; hp.y = h1;
                ph[t][q] = *(uint32_t*)&hp;
                pl[t][q] = pack_bf2(r0, r1);
            }
        }

#pragma unroll
        for (int t = 0; t < 4; t++) {
#pragma unroll
            for (int np = 0; np < 8; np++) {
                uint32_t vh[4], vl[4];
                uint32_t voff = (t * 16 + (lane & 15)) * F_ROWB + (np * 16 + lhalf) * 2;
                ldm_x4t(vh, sVh + voff);
                ldm_x4t(vl, sVl + voff);
                uint32_t b0h[2] = { vh[0], vh[1] }, b1h[2] = { vh[2], vh[3] };
                uint32_t b0l[2] = { vl[0], vl[1] }, b1l[2] = { vl[2], vl[3] };
                mma16816(o[2*np],   ph[t], b0h);
                mma16816(o[2*np],   ph[t], b0l);
                mma16816(o[2*np],   pl[t], b0h);
                mma16816(o[2*np+1], ph[t], b1h);
                mma16816(o[2*np+1], ph[t], b1l);
                mma16816(o[2*np+1], pl[t], b1h);
            }
        }
        __syncthreads();
    }

    // epilogue: normalize, split, store in GEMM A-tiled layout
    float inv0 = 1.0f / s_l[0];
    float inv1 = 1.0f / s_l[1];
    int row0g = b * S_LEN + mblk * 64 + m0 + lr;
    int row1g = row0g + 8;
#pragma unroll
    for (int nt = 0; nt < 16; nt++) {
        int col = h * HDIM + nt * 8 + lc * 2;
        size_t o0 = a_tile_off(row0g, col, INNER);
        size_t o1 = a_tile_off(row1g, col, INNER);
        float a0 = o[nt][0] * inv0, a1 = o[nt][1] * inv0;
        float b0 = o[nt][2] * inv1, b1 = o[nt][3] * inv1;
        __nv_bfloat16 h00, h01, h10, h11; float l00, l01, l10, l11;
        split1(a0, h00, l00); split1(a1, h01, l01);
        split1(b0, h10, l10); split1(b1, h11, l11);
        __nv_bfloat162 hp0; hp0.x = h00; hp0.y = h01;
        __nv_bfloat162 hp1; hp1.x = h10; hp1.y = h11;
        *(uint32_t*)(Ohi + o0) = *(uint32_t*)&hp0;
        *(uint32_t*)(Ohi + o1) = *(uint32_t*)&hp1;
        *(uint32_t*)(Olo + o0) = pack_bf2(l00, l01);
        *(uint32_t*)(Olo + o1) = pack_bf2(l10, l11);
    }
}

// ---------------------------------------------------------------------------
// fp32 -> bf16 hi/lo split, writing A-tiled swizzled layout
// ---------------------------------------------------------------------------
__global__ void split_kernel(const float4* __restrict__ in,
                             __nv_bfloat16* __restrict__ hi,
                             __nv_bfloat16* __restrict__ lo, int n4, int K) {
    int i = blockIdx.x * blockDim.x + threadIdx.x;
    if (i >= n4) return;
    float4 v = in[i];
    float f[4] = { v.x, v.y, v.z, v.w };
    __nv_bfloat16 h[4]; float l[4];
#pragma unroll
    for (int j = 0; j < 4; j++) split1(f[j], h[j], l[j]);
    int rg = (i * 4) / K;
    int k0 = (i * 4) % K;
    size_t o = a_tile_off(rg, k0, K);   // 4 consecutive k share a 16B chunk
    *(uint2*)(hi + o) = *(uint2*)h;
    uint2 lp; lp.x = pack_bf2(l[0], l[1]); lp.y = pack_bf2(l[2], l[3]);
    *(uint2*)(lo + o) = lp;
}

// ---------------------------------------------------------------------------
// Transpose + split: W[K, N] fp32 -> B-tiled swizzled T{hi,lo}[N, K] bf16
// ---------------------------------------------------------------------------
__global__ void transpose_split_kernel(const float* __restrict__ W,
                                       __nv_bfloat16* __restrict__ Thi,
                                       __nv_bfloat16* __restrict__ Tlo) {
    __shared__ float t[32][33];
    int n0 = blockIdx.x * 32, k0 = blockIdx.y * 32;
#pragma unroll
    for (int i = 0; i < 32; i += 8)
        t[threadIdx.y + i][threadIdx.x] =
            W[(size_t)(k0 + threadIdx.y + i) * 2048 + n0 + threadIdx.x];
    __syncthreads();
#pragma unroll
    for (int i = 0; i < 32; i += 8) {
        float v = t[threadIdx.x][threadIdx.y + i];
        __nv_bfloat16 h; float l;
        split1(v, h, l);
        size_t o = b_tile_off(n0 + threadIdx.y + i, k0 + threadIdx.x, 2048);
        Thi[o] = h;
        Tlo[o] = __float2bfloat16(l);
    }
}

// ---------------------------------------------------------------------------
// Launcher (ncu capture slot = launch 4 = GEMM)
// ---------------------------------------------------------------------------
extern "C" void kernel_launch(void* const* d_in, const int* in_sizes, int n_in,
                              void* d_out, int out_size) {
    const float* x  = (const float*)d_in[0];
    const float* Wq = (const float*)d_in[1];
    const float* Wk = (const float*)d_in[2];
    const float* Wv = (const float*)d_in[3];
    const float* Wo = (const float*)d_in[4];
    const float* qg = (const float*)d_in[5];
    const float* kg = (const float*)d_in[6];
    float* out = (float*)d_out;

    __nv_bfloat16 *xhi, *xlo, *wthi, *wtlo;
    __nv_bfloat16 *qhi, *qlo, *khi, *klo, *vhi, *vlo, *aohi, *aolo;
    cudaGetSymbolAddress((void**)&xhi,  g_xhi);
    cudaGetSymbolAddress((void**)&xlo,  g_xlo);
    cudaGetSymbolAddress((void**)&wthi, g_wthi);
    cudaGetSymbolAddress((void**)&wtlo, g_wtlo);
    cudaGetSymbolAddress((void**)&qhi,  g_qhi);
    cudaGetSymbolAddress((void**)&qlo,  g_qlo);
    cudaGetSymbolAddress((void**)&khi,  g_khi);
    cudaGetSymbolAddress((void**)&klo,  g_klo);
    cudaGetSymbolAddress((void**)&vhi,  g_vhi);
    cudaGetSymbolAddress((void**)&vlo,  g_vlo);
    cudaGetSymbolAddress((void**)&aohi, g_aohi);
    cudaGetSymbolAddress((void**)&aolo, g_aolo);
    const size_t WSZ = (size_t)DMODEL * INNER;

    cudaFuncSetAttribute(gemm_mma_kernel<0>, cudaFuncAttributeMaxDynamicSharedMemorySize, GEMM_SMEM);
    cudaFuncSetAttribute(gemm_mma_kernel<1>, cudaFuncAttributeMaxDynamicSharedMemorySize, GEMM_SMEM);
    cudaFuncSetAttribute(gemm_mma_kernel<2>, cudaFuncAttributeMaxDynamicSharedMemorySize, GEMM_SMEM);
    cudaFuncSetAttribute(flash_mma_kernel, cudaFuncAttributeMaxDynamicSharedMemorySize, FLASH_SMEM);

    dim3 tb(32, 8), tg(64, 64);
    dim3 gg(INNER / G_BN, ROWS / G_BM);   // (16, 16)
    dim3 gridF(S_LEN / 64, NHEAD, BATCH);

    // launch 0: split x (tiled)
    int n4x = ROWS * DMODEL / 4;
    split_kernel<<<n4x / 256, 256>>>((const float4*)x, xhi, xlo, n4x, DMODEL);
    // launches 1-3: transpose Wq, Wk, Wv (tiled)
    transpose_split_kernel<<<tg, tb>>>(Wq, wthi + 0*WSZ, wtlo + 0*WSZ);
    transpose_split_kernel<<<tg, tb>>>(Wk, wthi + 1*WSZ, wtlo + 1*WSZ);
    transpose_split_kernel<<<tg, tb>>>(Wv, wthi + 2*WSZ, wtlo + 2*WSZ);
    // launch 4 (ncu capture slot): V projection
    gemm_mma_kernel<1><<<gg, 256, GEMM_SMEM>>>(xhi, xlo, wthi + 2*WSZ, wtlo + 2*WSZ,
                                               nullptr, vhi, vlo, nullptr,
                                               ROWS, INNER, DMODEL);
    // launch 5: transpose Wo
    transpose_split_kernel<<<tg, tb>>>(Wo, wthi + 3*WSZ, wtlo + 3*WSZ);
    // launches 6-7: Q, K projections with fused RMSNorm
    gemm_mma_kernel<2><<<gg, 256, GEMM_SMEM>>>(xhi, xlo, wthi + 0*WSZ, wtlo + 0*WSZ,
                                               nullptr, qhi, qlo, qg,
                                               ROWS, INNER, DMODEL);
    gemm_mma_kernel<2><<<gg, 256, GEMM_SMEM>>>(xhi, xlo, wthi + 1*WSZ, wtlo + 1*WSZ,
                                               nullptr, khi, klo, kg,
                                               ROWS, INNER, DMODEL);
    // launch 8: flash attention (epilogue writes tiled ao)
    flash_mma_kernel<<<gridF, 128, FLASH_SMEM>>>(qhi, qlo, khi, klo, vhi, vlo,
                                                 aohi, aolo);
    // launch 9: output projection
    gemm_mma_kernel<0><<<gg, 256, GEMM_SMEM>>>(aohi, aolo, wthi + 3*WSZ, wtlo + 3*WSZ,
                                               out, nullptr, nullptr, nullptr,
                                               ROWS, DMODEL, INNER);
}

// round 10
// speedup vs baseline: 1.4004x; 1.0221x over previous
#include <cuda_runtime.h>
#include <cuda_bf16.h>
#include <stdint.h>
#include <math.h>

// Problem constants
#define S_LEN   2048
#define BATCH   2
#define NHEAD   16
#define HDIM    128
#define DMODEL  2048
#define INNER   2048          // NHEAD*HDIM
#define ROWS    (BATCH*S_LEN) // 4096

// Scratch (allocation forbidden -> __device__ globals)
// xhi/xlo, wthi/wtlo, aohi/aolo are stored in TILED+SWIZZLED layouts (below),
// 1024B-aligned (cp.async.bulk requires >=16B-aligned global addresses).
// q/k/v hi/lo stay row-major [ROWS, INNER] for the flash kernel.
__device__ __align__(1024) __nv_bfloat16 g_xhi[(size_t)ROWS * DMODEL];
__device__ __align__(1024) __nv_bfloat16 g_xlo[(size_t)ROWS * DMODEL];
__device__ __align__(1024) __nv_bfloat16 g_wthi[4][(size_t)DMODEL * INNER];
__device__ __align__(1024) __nv_bfloat16 g_wtlo[4][(size_t)DMODEL * INNER];
__device__ __align__(1024) __nv_bfloat16 g_qhi[(size_t)ROWS * INNER];
__device__ __align__(1024) __nv_bfloat16 g_qlo[(size_t)ROWS * INNER];
__device__ __align__(1024) __nv_bfloat16 g_khi[(size_t)ROWS * INNER];
__device__ __align__(1024) __nv_bfloat16 g_klo[(size_t)ROWS * INNER];
__device__ __align__(1024) __nv_bfloat16 g_vhi[(size_t)ROWS * INNER];
__device__ __align__(1024) __nv_bfloat16 g_vlo[(size_t)ROWS * INNER];
__device__ __align__(1024) __nv_bfloat16 g_aohi[(size_t)ROWS * INNER];
__device__ __align__(1024) __nv_bfloat16 g_aolo[(size_t)ROWS * INNER];

// ---------------------------------------------------------------------------
// Tiled layouts (element offsets in bf16 units).
// A-tiled: 256-row blocks x 32-col chunks; tile = 256x32 = 8192 elems (16KB).
//   within tile: elem (rl, kl) at rl*32 + ((ch ^ ((rl>>1)&3))<<3) + w,
//   ch = kl>>3, w = kl&7.  (XOR swizzle -> conflict-free ldmatrix @64B rows)
// B-tiled: 128-row blocks; tile = 128x32 = 4096 elems (8KB), same swizzle.
// A 128-row CTA half of a 256-row block is a contiguous 8KB span.
// ---------------------------------------------------------------------------
__device__ __forceinline__ size_t a_tile_off(int rg, int k, int K) {
    int rb = rg >> 8, rl = rg & 255, c = k >> 5, kl = k & 31;
    int ch = kl >> 3, w = kl & 7;
    return ((size_t)(rb * (K >> 5) + c) << 13) + rl * 32 +
           (((ch ^ ((rl >> 1) & 3)) << 3) + w);
}
__device__ __forceinline__ size_t b_tile_off(int n, int k, int K) {
    int nb = n >> 7, nl = n & 127, c = k >> 5, kl = k & 31;
    int ch = kl >> 3, w = kl & 7;
    return ((size_t)(nb * (K >> 5) + c) << 12) + nl * 32 +
           (((ch ^ ((nl >> 1) & 3)) << 3) + w);
}

// ---------------------------------------------------------------------------
// PTX helpers
// ---------------------------------------------------------------------------
__device__ __forceinline__ uint32_t smem_u32(const void* p) {
    uint32_t a;
    asm("{ .reg .u64 t; cvta.to.shared.u64 t, %1; cvt.u32.u64 %0, t; }"
        : "=r"(a) : "l"(p));
    return a;
}
__device__ __forceinline__ void cp16(uint32_t dst, const void* src) {
    asm volatile("cp.async.cg.shared.global [%0], [%1], 16;" :: "r"(dst), "l"(src));
}
__device__ __forceinline__ void cp_commit() { asm volatile("cp.async.commit_group;"); }
template<int N> __device__ __forceinline__ void cp_wait() {
    asm volatile("cp.async.wait_group %0;" :: "n"(N));
}
__device__ __forceinline__ void bulkcp(uint32_t dst, const void* src,
                                       uint32_t bytes, uint32_t mbar) {
    asm volatile(
        "cp.async.bulk.shared::cluster.global.mbarrier::complete_tx::bytes "
        "[%0], [%1], %2, [%3];"
        :: "r"(dst), "l"(src), "r"(bytes), "r"(mbar) : "memory");
}
__device__ __forceinline__ void mbar_init(uint32_t a, uint32_t c) {
    asm volatile("mbarrier.init.shared.b64 [%0], %1;" :: "r"(a), "r"(c) : "memory");
}
__device__ __forceinline__ void mbar_expect(uint32_t mbar, uint32_t bytes) {
    asm volatile("mbarrier.arrive.expect_tx.shared.b64 _, [%0], %1;"
                 :: "r"(mbar), "r"(bytes) : "memory");
}
__device__ __forceinline__ void mbar_wait(uint32_t mbar, uint32_t parity) {
    asm volatile(
        "{\n\t.reg .pred P;\n\t"
        "WL_%=:\n\t"
        "mbarrier.try_wait.parity.shared.b64 P, [%0], %1;\n\t"
        "@P bra.uni WD_%=;\n\t"
        "bra.uni WL_%=;\n\t"
        "WD_%=:\n\t}"
        :: "r"(mbar), "r"(parity) : "memory");
}
__device__ __forceinline__ void fence_async() {
    asm volatile("fence.proxy.async.shared::cta;" ::: "memory");
}
__device__ __forceinline__ void ldm_x4(uint32_t* r, uint32_t addr) {
    asm volatile("ldmatrix.sync.aligned.m8n8.x4.shared.b16 {%0,%1,%2,%3}, [%4];"
                 : "=r"(r[0]), "=r"(r[1]), "=r"(r[2]), "=r"(r[3]) : "r"(addr));
}
__device__ __forceinline__ void ldm_x4t(uint32_t* r, uint32_t addr) {
    asm volatile("ldmatrix.sync.aligned.m8n8.x4.trans.shared.b16 {%0,%1,%2,%3}, [%4];"
                 : "=r"(r[0]), "=r"(r[1]), "=r"(r[2]), "=r"(r[3]) : "r"(addr));
}
__device__ __forceinline__ void mma16816(float* c, const uint32_t* a, const uint32_t* b) {
    asm volatile(
        "mma.sync.aligned.m16n8k16.row.col.f32.bf16.bf16.f32 "
        "{%0,%1,%2,%3}, {%4,%5,%6,%7}, {%8,%9}, {%0,%1,%2,%3};"
        : "+f"(c[0]), "+f"(c[1]), "+f"(c[2]), "+f"(c[3])
        : "r"(a[0]), "r"(a[1]), "r"(a[2]), "r"(a[3]), "r"(b[0]), "r"(b[1]));
}
__device__ __forceinline__ uint32_t pack_bf2(float a, float b) {
    __nv_bfloat162 t = __floats2bfloat162_rn(a, b);
    return *(uint32_t*)&t;
}
__device__ __forceinline__ void split1(float v, __nv_bfloat16& h, float& r) {
    h = __float2bfloat16(v);
    r = v - __bfloat162float(h);
}

// ---------------------------------------------------------------------------
// bf16 hi/lo split GEMM with cp.async.bulk tile loads.
// CTA 128x128, BK=32, 128 threads (4 warps, warp tile 64x64), 3-stage
// mbarrier pipeline, occupancy 2 (flash-proven shape).
// MODE 0: fp32 C.  MODE 1: bf16 split C.  MODE 2: RMSNorm + split C.
// ---------------------------------------------------------------------------
#define G_BM 128
#define G_BN 128
#define A_TB 8192                // bytes per 128-row A half-tile (hi or lo)
#define B_TB 8192
#define STAGEB (2 * A_TB + 2 * B_TB)   // 32768
#define NSTAGE 3
#define GEMM_SMEM (NSTAGE * STAGEB + 64)   // 98368

template<int MODE>
__global__ __launch_bounds__(128, 2)
void gemm_mma_kernel(const __nv_bfloat16* __restrict__ Ahi,
                     const __nv_bfloat16* __restrict__ Alo,
                     const __nv_bfloat16* __restrict__ Bhi,
                     const __nv_bfloat16* __restrict__ Blo,
                     float* __restrict__ C,
                     __nv_bfloat16* __restrict__ Chi,
                     __nv_bfloat16* __restrict__ Clo,
                     const float* __restrict__ gamma,
                     int M, int N, int K)
{
    extern __shared__ char smem[];
    const uint32_t sbase = smem_u32(smem);
    const uint32_t mbar0 = sbase + NSTAGE * STAGEB;
    const int tid  = threadIdx.x;
    const int warp = tid >> 5;
    const int lane = tid & 31;
    const int wm = warp >> 1;          // 0..1 -> 64 rows each
    const int wn = warp & 1;           // 0..1 -> 64 cols each

    const int rowblk = blockIdx.y;       // 128-row block
    const int colblk = blockIdx.x;       // 128-col block
    const int row0 = rowblk * G_BM;
    const int col0 = colblk * G_BN;
    const int KC = K >> 5;

    if (tid == 0) {
#pragma unroll
        for (int s = 0; s < NSTAGE; s++) mbar_init(mbar0 + s * 8, 1);
        fence_async();
    }
    __syncthreads();

    float acc[4][8][4];
#pragma unroll
    for (int mt = 0; mt < 4; mt++)
#pragma unroll
        for (int nt = 0; nt < 8; nt++)
#pragma unroll
            for (int r = 0; r < 4; r++) acc[mt][nt][r] = 0.0f;

    // A global addressing: 256-row blocks; this CTA uses one 8KB half.
    const int arb  = rowblk >> 1;
    const size_t ahalf = (size_t)(rowblk & 1) * 8192;

    auto issue = [&](int c, int s) {
        uint32_t stb = sbase + s * STAGEB;
        uint32_t mb = mbar0 + s * 8;
        const char* ah = (const char*)Ahi + (((size_t)(arb * KC + c)) << 14) + ahalf;
        const char* al = (const char*)Alo + (((size_t)(arb * KC + c)) << 14) + ahalf;
        const char* bh = (const char*)Bhi + (((size_t)(colblk * KC + c)) << 13);
        const char* bl = (const char*)Blo + (((size_t)(colblk * KC + c)) << 13);
        mbar_expect(mb, STAGEB);
        bulkcp(stb,            ah, A_TB, mb);
        bulkcp(stb + A_TB,     al, A_TB, mb);
        bulkcp(stb + 2 * A_TB, bh, B_TB, mb);
        bulkcp(stb + 2 * A_TB + B_TB, bl, B_TB, mb);
    };

    if (tid == 0) { issue(0, 0); issue(1, 1); }

    // per-lane invariant address pieces
    const int arow_l = (lane & 15);
    const int brow_l = (lane & 7) + 8 * (lane >> 4);
    const int a_chl  = lane >> 4;
    const int b_chl  = (lane >> 3) & 1;

    for (int c = 0; c < KC; ++c) {
        const int s = c % NSTAGE;
        if (tid == 0 && c + 2 < KC) issue(c + 2, (c + 2) % NSTAGE);
        mbar_wait(mbar0 + s * 8, (c / NSTAGE) & 1);

        const uint32_t sA  = sbase + s * STAGEB;
        const uint32_t sAl = sA + A_TB;
        const uint32_t sB  = sA + 2 * A_TB;
        const uint32_t sBl = sB + B_TB;
#pragma unroll
        for (int ks = 0; ks < 2; ks++) {
            uint32_t ah[4][4], al[4][4];
#pragma unroll
            for (int mt = 0; mt < 4; mt++) {
                int arow = wm * 64 + mt * 16 + arow_l;      // 0..127 local
                int ch = (2 * ks + a_chl) ^ ((arow >> 1) & 3);
                uint32_t aoff = arow * 64 + ch * 16;
                ldm_x4(ah[mt], sA  + aoff);
                ldm_x4(al[mt], sAl + aoff);
            }
            uint32_t bh[8][2], bl[8][2];
#pragma unroll
            for (int p = 0; p < 4; p++) {
                int brow = wn * 64 + p * 16 + brow_l;
                int ch = (2 * ks + b_chl) ^ ((brow >> 1) & 3);
                uint32_t boff = brow * 64 + ch * 16;
                uint32_t t0[4], t1[4];
                ldm_x4(t0, sB  + boff);
                ldm_x4(t1, sBl + boff);
                bh[2*p][0]   = t0[0]; bh[2*p][1]   = t0[1];
                bh[2*p+1][0] = t0[2]; bh[2*p+1][1] = t0[3];
                bl[2*p][0]   = t1[0]; bl[2*p][1]   = t1[1];
                bl[2*p+1][0] = t1[2]; bl[2*p+1][1] = t1[3];
            }
#pragma unroll
            for (int mt = 0; mt < 4; mt++)
#pragma unroll
                for (int nt = 0; nt < 8; nt++) {
                    mma16816(acc[mt][nt], ah[mt], bh[nt]);
                    mma16816(acc[mt][nt], ah[mt], bl[nt]);
                    mma16816(acc[mt][nt], al[mt], bh[nt]);
                }
        }
        __syncthreads();
    }

    if (MODE == 0) {
#pragma unroll
        for (int mt = 0; mt < 4; mt++) {
            int r0 = row0 + wm * 64 + mt * 16 + (lane >> 2);
#pragma unroll
            for (int nt = 0; nt < 8; nt++) {
                int cc = col0 + wn * 64 + nt * 8 + (lane & 3) * 2;
                *(float2*)(C + (size_t)r0 * N + cc) =
                    make_float2(acc[mt][nt][0], acc[mt][nt][1]);
                *(float2*)(C + (size_t)(r0 + 8) * N + cc) =
                    make_float2(acc[mt][nt][2], acc[mt][nt][3]);
            }
        }
    } else if (MODE == 1) {
        // row-major bf16 hi/lo output (consumed by flash)
#pragma unroll
        for (int mt = 0; mt < 4; mt++) {
            int r0 = row0 + wm * 64 + mt * 16 + (lane >> 2);
#pragma unroll
            for (int nt = 0; nt < 8; nt++) {
                int cc = col0 + wn * 64 + nt * 8 + (lane & 3) * 2;
                __nv_bfloat16 h0, h1; float l0, l1;
                split1(acc[mt][nt][0], h0, l0);
                split1(acc[mt][nt][1], h1, l1);
                __nv_bfloat162 hp; hp.x = h0; hp.y = h1;
                *(uint32_t*)(Chi + (size_t)r0 * N + cc) = *(uint32_t*)&hp;
                *(uint32_t*)(Clo + (size_t)r0 * N + cc) = pack_bf2(l0, l1);
                split1(acc[mt][nt][2], h0, l0);
                split1(acc[mt][nt][3], h1, l1);
                __nv_bfloat162 hq; hq.x = h0; hq.y = h1;
                *(uint32_t*)(Chi + (size_t)(r0 + 8) * N + cc) = *(uint32_t*)&hq;
                *(uint32_t*)(Clo + (size_t)(r0 + 8) * N + cc) = pack_bf2(l0, l1);
            }
        }
    } else {
        // MODE 2: per-row (=head) RMSNorm + split, row-major output
        float* CS = (float*)smem;      // 128 x 132 fp32 = 67584 B < 98304
        float4 g4 = *(const float4*)(gamma + lane * 4);
#pragma unroll
        for (int mt = 0; mt < 4; mt++) {
            int r = wm * 64 + mt * 16 + (lane >> 2);
#pragma unroll
            for (int nt = 0; nt < 8; nt++) {
                int cc = wn * 64 + nt * 8 + (lane & 3) * 2;
                CS[r * 132 + cc]         = acc[mt][nt][0];
                CS[r * 132 + cc + 1]     = acc[mt][nt][1];
                CS[(r+8) * 132 + cc]     = acc[mt][nt][2];
                CS[(r+8) * 132 + cc + 1] = acc[mt][nt][3];
            }
        }
        __syncthreads();
#pragma unroll
        for (int rr = 0; rr < 32; rr++) {
            int row = warp * 32 + rr;          // 0..127 local
            float4 v = *(float4*)&CS[row * 132 + lane * 4];
            float ss = v.x*v.x + v.y*v.y + v.z*v.z + v.w*v.w;
#pragma unroll
            for (int o = 16; o > 0; o >>= 1)
                ss += __shfl_xor_sync(0xffffffffu, ss, o);
            float rn = rsqrtf(ss * (1.0f / 128.0f) + 1e-6f);
            float f[4] = { v.x*rn*g4.x, v.y*rn*g4.y, v.z*rn*g4.z, v.w*rn*g4.w };
            __nv_bfloat16 h[4]; float l[4];
#pragma unroll
            for (int j = 0; j < 4; j++) split1(f[j], h[j], l[j]);
            size_t o = (size_t)(row0 + row) * N + col0 + lane * 4;
            *(uint2*)(Chi + o) = *(uint2*)h;
            uint2 lp; lp.x = pack_bf2(l[0], l[1]); lp.y = pack_bf2(l[2], l[3]);
            *(uint2*)(Clo + o) = lp;
        }
    }
}

// ---------------------------------------------------------------------------
// Flash attention (R4/R7/R9-proven shape: 64x64, 128 thr, occ 2, cp.async).
// Epilogue writes aohi/aolo in GEMM A-tiled layout.
// ---------------------------------------------------------------------------
#define F_ROWB 272
#define FT_BYTES (64 * F_ROWB)
#define FLASH_SMEM (6 * FT_BYTES)

__global__ __launch_bounds__(128, 2)
void flash_mma_kernel(const __nv_bfloat16* __restrict__ Qhi,
                      const __nv_bfloat16* __restrict__ Qlo,
                      const __nv_bfloat16* __restrict__ Khi,
                      const __nv_bfloat16* __restrict__ Klo,
                      const __nv_bfloat16* __restrict__ Vhi,
                      const __nv_bfloat16* __restrict__ Vlo,
                      __nv_bfloat16* __restrict__ Ohi,
                      __nv_bfloat16* __restrict__ Olo)
{
    extern __shared__ char sm_raw[];
    const uint32_t sb = smem_u32(sm_raw);
    const uint32_t sQh = sb,                sQl = sb + FT_BYTES;
    const uint32_t sKh = sb + 2*FT_BYTES,   sKl = sb + 3*FT_BYTES;
    const uint32_t sVh = sb + 4*FT_BYTES,   sVl = sb + 5*FT_BYTES;

    const int tid  = threadIdx.x;
    const int warp = tid >> 5;
    const int lane = tid & 31;
    const int lr   = lane >> 2;
    const int lc   = lane & 3;
    const int m0   = warp * 16;

    const int mblk = blockIdx.x, h = blockIdx.y, b = blockIdx.z;
    const size_t qoff = ((size_t)(b * S_LEN + mblk * 64)) * INNER + h * HDIM;
    const size_t koff = ((size_t)(b * S_LEN)) * INNER + h * HDIM;

#pragma unroll
    for (int i = 0; i < 8; i++) {
        int idx = i * 128 + tid;
        int r = idx >> 4, s = idx & 15;
        uint32_t so = r * F_ROWB + s * 16;
        const size_t go = qoff + (size_t)r * INNER + s * 8;
        cp16(sQh + so, Qhi + go);
        cp16(sQl + so, Qlo + go);
    }
    cp_commit();

    float o[16][4];
#pragma unroll
    for (int nt = 0; nt < 16; nt++)
#pragma unroll
        for (int r = 0; r < 4; r++) o[nt][r] = 0.0f;
    float s_m[2] = { -1e30f, -1e30f };
    float s_l[2] = { 0.0f, 0.0f };
    const float scale = 0.08838834764831845f;

    const uint32_t a_row = m0 + (lane & 15);
    const uint32_t lhalf = 8 * (lane >> 4);

    for (int n0 = 0; n0 < S_LEN; n0 += 64) {
#pragma unroll
        for (int i = 0; i < 8; i++) {
            int idx = i * 128 + tid;
            int r = idx >> 4, s = idx & 15;
            uint32_t so = r * F_ROWB + s * 16;
            const size_t go = koff + (size_t)(n0 + r) * INNER + s * 8;
            cp16(sKh + so, Khi + go);
            cp16(sKl + so, Klo + go);
            cp16(sVh + so, Vhi + go);
            cp16(sVl + so, Vlo + go);
        }
        cp_commit();
        cp_wait<0>();
        __syncthreads();

        float s[8][4];
#pragma unroll
        for (int j = 0; j < 8; j++)
#pragma unroll
            for (int r = 0; r < 4; r++) s[j][r] = 0.0f;

#pragma unroll
        for (int t = 0; t < 8; t++) {
            const int d0 = t * 16;
            uint32_t ah[4], al[4];
            uint32_t aoff = a_row * F_ROWB + (d0 + lhalf) * 2;
            ldm_x4(ah, sQh + aoff);
            ldm_x4(al, sQl + aoff);
#pragma unroll
            for (int p = 0; p < 4; p++) {
                uint32_t bh[4], bl[4];
                uint32_t boff = (p * 16 + (lane & 15)) * F_ROWB + (d0 + lhalf) * 2;
                ldm_x4(bh, sKh + boff);
                ldm_x4(bl, sKl + boff);
                uint32_t b0h[2] = { bh[0], bh[2] }, b1h[2] = { bh[1], bh[3] };
                uint32_t b0l[2] = { bl[0], bl[2] }, b1l[2] = { bl[1], bl[3] };
                mma16816(s[2*p],   ah, b0h);
                mma16816(s[2*p],   ah, b0l);
                mma16816(s[2*p],   al, b0h);
                mma16816(s[2*p+1], ah, b1h);
                mma16816(s[2*p+1], ah, b1l);
                mma16816(s[2*p+1], al, b1h);
            }
        }

#pragma unroll
        for (int j = 0; j < 8; j++)
#pragma unroll
            for (int r = 0; r < 4; r++) s[j][r] *= scale;

        float mx0 = -1e30f, mx1 = -1e30f;
#pragma unroll
        for (int j = 0; j < 8; j++) {
            mx0 = fmaxf(mx0, fmaxf(s[j][0], s[j][1]));
            mx1 = fmaxf(mx1, fmaxf(s[j][2], s[j][3]));
        }
        mx0 = fmaxf(mx0, __shfl_xor_sync(0xffffffffu, mx0, 1));
        mx0 = fmaxf(mx0, __shfl_xor_sync(0xffffffffu, mx0, 2));
        mx1 = fmaxf(mx1, __shfl_xor_sync(0xffffffffu, mx1, 1));
        mx1 = fmaxf(mx1, __shfl_xor_sync(0xffffffffu, mx1, 2));

        float mn0 = fmaxf(s_m[0], mx0), mn1 = fmaxf(s_m[1], mx1);
        float al0 = __expf(s_m[0] - mn0), al1 = __expf(s_m[1] - mn1);
        s_m[0] = mn0; s_m[1] = mn1;

        float rs0 = 0.0f, rs1 = 0.0f;
#pragma unroll
        for (int j = 0; j < 8; j++) {
            s[j][0] = __expf(s[j][0] - mn0);
            s[j][1] = __expf(s[j][1] - mn0);
            s[j][2] = __expf(s[j][2] - mn1);
            s[j][3] = __expf(s[j][3] - mn1);
            rs0 += s[j][0] + s[j][1];
            rs1 += s[j][2] + s[j][3];
        }
        rs0 += __shfl_xor_sync(0xffffffffu, rs0, 1);
        rs0 += __shfl_xor_sync(0xffffffffu, rs0, 2);
        rs1 += __shfl_xor_sync(0xffffffffu, rs1, 1);
        rs1 += __shfl_xor_sync(0xffffffffu, rs1, 2);
        s_l[0] = s_l[0] * al0 + rs0;
        s_l[1] = s_l[1] * al1 + rs1;

#pragma unroll
        for (int nt = 0; nt < 16; nt++) {
            o[nt][0] *= al0; o[nt][1] *= al0;
            o[nt][2] *= al1; o[nt][3] *= al1;
        }

        uint32_t ph[4][4], pl[4][4];
#pragma unroll
        for (int t = 0; t < 4; t++) {
#pragma unroll
            for (int q = 0; q < 4; q++) {
                int j = 2 * t + (q >> 1);
                int cc = (q & 1) * 2;
                float v0 = s[j][cc], v1 = s[j][cc + 1];
                __nv_bfloat16 h0, h1; float r0, r1;
                split1(v0, h0, r0);
                split1(v1, h1, r1);
                __nv_bfloat162 hp; hp.x = h0; hp.y = h1;
                ph[t][q] = *(uint32_t*)&hp;
                pl[t][q] = pack_bf2(r0, r1);
            }
        }

#pragma unroll
        for (int t = 0; t < 4; t++) {
#pragma unroll
            for (int np = 0; np < 8; np++) {
                uint32_t vh[4], vl[4];
                uint32_t voff = (t * 16 + (lane & 15)) * F_ROWB + (np * 16 + lhalf) * 2;
                ldm_x4t(vh, sVh + voff);
                ldm_x4t(vl, sVl + voff);
                uint32_t b0h[2] = { vh[0], vh[1] }, b1h[2] = { vh[2], vh[3] };
                uint32_t b0l[2] = { vl[0], vl[1] }, b1l[2] = { vl[2], vl[3] };
                mma16816(o[2*np],   ph[t], b0h);
                mma16816(o[2*np],   ph[t], b0l);
                mma16816(o[2*np],   pl[t], b0h);
                mma16816(o[2*np+1], ph[t], b1h);
                mma16816(o[2*np+1], ph[t], b1l);
                mma16816(o[2*np+1], pl[t], b1h);
            }
        }
        __syncthreads();
    }

    // epilogue: normalize, split, store in GEMM A-tiled layout
    float inv0 = 1.0f / s_l[0];
    float inv1 = 1.0f / s_l[1];
    int row0g = b * S_LEN + mblk * 64 + m0 + lr;
    int row1g = row0g + 8;
#pragma unroll
    for (int nt = 0; nt < 16; nt++) {
        int col = h * HDIM + nt * 8 + lc * 2;
        size_t o0 = a_tile_off(row0g, col, INNER);
        size_t o1 = a_tile_off(row1g, col, INNER);
        float a0 = o[nt][0] * inv0, a1 = o[nt][1] * inv0;
        float b0 = o[nt][2] * inv1, b1 = o[nt][3] * inv1;
        __nv_bfloat16 h00, h01, h10, h11; float l00, l01, l10, l11;
        split1(a0, h00, l00); split1(a1, h01, l01);
        split1(b0, h10, l10); split1(b1, h11, l11);
        __nv_bfloat162 hp0; hp0.x = h00; hp0.y = h01;
        __nv_bfloat162 hp1; hp1.x = h10; hp1.y = h11;
        *(uint32_t*)(Ohi + o0) = *(uint32_t*)&hp0;
        *(uint32_t*)(Ohi + o1) = *(uint32_t*)&hp1;
        *(uint32_t*)(Olo + o0) = pack_bf2(l00, l01);
        *(uint32_t*)(Olo + o1) = pack_bf2(l10, l11);
    }
}

// ---------------------------------------------------------------------------
// fp32 -> bf16 hi/lo split, writing A-tiled swizzled layout
// ---------------------------------------------------------------------------
__global__ void split_kernel(const float4* __restrict__ in,
                             __nv_bfloat16* __restrict__ hi,
                             __nv_bfloat16* __restrict__ lo, int n4, int K) {
    int i = blockIdx.x * blockDim.x + threadIdx.x;
    if (i >= n4) return;
    float4 v = in[i];
    float f[4] = { v.x, v.y, v.z, v.w };
    __nv_bfloat16 h[4]; float l[4];
#pragma unroll
    for (int j = 0; j < 4; j++) split1(f[j], h[j], l[j]);
    int rg = (i * 4) / K;
    int k0 = (i * 4) % K;
    size_t o = a_tile_off(rg, k0, K);
    *(uint2*)(hi + o) = *(uint2*)h;
    uint2 lp; lp.x = pack_bf2(l[0], l[1]); lp.y = pack_bf2(l[2], l[3]);
    *(uint2*)(lo + o) = lp;
}

// ---------------------------------------------------------------------------
// Transpose + split: W[K, N] fp32 -> B-tiled swizzled T{hi,lo}[N, K] bf16
// ---------------------------------------------------------------------------
__global__ void transpose_split_kernel(const float* __restrict__ W,
                                       __nv_bfloat16* __restrict__ Thi,
                                       __nv_bfloat16* __restrict__ Tlo) {
    __shared__ float t[32][33];
    int n0 = blockIdx.x * 32, k0 = blockIdx.y * 32;
#pragma unroll
    for (int i = 0; i < 32; i += 8)
        t[threadIdx.y + i][threadIdx.x] =
            W[(size_t)(k0 + threadIdx.y + i) * 2048 + n0 + threadIdx.x];
    __syncthreads();
#pragma unroll
    for (int i = 0; i < 32; i += 8) {
        float v = t[threadIdx.x][threadIdx.y + i];
        __nv_bfloat16 h; float l;
        split1(v, h, l);
        size_t o = b_tile_off(n0 + threadIdx.y + i, k0 + threadIdx.x, 2048);
        Thi[o] = h;
        Tlo[o] = __float2bfloat16(l);
    }
}

// ---------------------------------------------------------------------------
// Launcher (ncu capture slot = launch 4 = GEMM)
// ---------------------------------------------------------------------------
extern "C" void kernel_launch(void* const* d_in, const int* in_sizes, int n_in,
                              void* d_out, int out_size) {
    const float* x  = (const float*)d_in[0];
    const float* Wq = (const float*)d_in[1];
    const float* Wk = (const float*)d_in[2];
    const float* Wv = (const float*)d_in[3];
    const float* Wo = (const float*)d_in[4];
    const float* qg = (const float*)d_in[5];
    const float* kg = (const float*)d_in[6];
    float* out = (float*)d_out;

    __nv_bfloat16 *xhi, *xlo, *wthi, *wtlo;
    __nv_bfloat16 *qhi, *qlo, *khi, *klo, *vhi, *vlo, *aohi, *aolo;
    cudaGetSymbolAddress((void**)&xhi,  g_xhi);
    cudaGetSymbolAddress((void**)&xlo,  g_xlo);
    cudaGetSymbolAddress((void**)&wthi, g_wthi);
    cudaGetSymbolAddress((void**)&wtlo, g_wtlo);
    cudaGetSymbolAddress((void**)&qhi,  g_qhi);
    cudaGetSymbolAddress((void**)&qlo,  g_qlo);
    cudaGetSymbolAddress((void**)&khi,  g_khi);
    cudaGetSymbolAddress((void**)&klo,  g_klo);
    cudaGetSymbolAddress((void**)&vhi,  g_vhi);
    cudaGetSymbolAddress((void**)&vlo,  g_vlo);
    cudaGetSymbolAddress((void**)&aohi, g_aohi);
    cudaGetSymbolAddress((void**)&aolo, g_aolo);
    const size_t WSZ = (size_t)DMODEL * INNER;

    cudaFuncSetAttribute(gemm_mma_kernel<0>, cudaFuncAttributeMaxDynamicSharedMemorySize, GEMM_SMEM);
    cudaFuncSetAttribute(gemm_mma_kernel<1>, cudaFuncAttributeMaxDynamicSharedMemorySize, GEMM_SMEM);
    cudaFuncSetAttribute(gemm_mma_kernel<2>, cudaFuncAttributeMaxDynamicSharedMemorySize, GEMM_SMEM);
    cudaFuncSetAttribute(flash_mma_kernel, cudaFuncAttributeMaxDynamicSharedMemorySize, FLASH_SMEM);

    dim3 tb(32, 8), tg(64, 64);
    dim3 gg(INNER / G_BN, ROWS / G_BM);   // (16, 32) -> 512 CTAs
    dim3 gridF(S_LEN / 64, NHEAD, BATCH);

    // launch 0: split x (tiled)
    int n4x = ROWS * DMODEL / 4;
    split_kernel<<<n4x / 256, 256>>>((const float4*)x, xhi, xlo, n4x, DMODEL);
    // launches 1-3: transpose Wq, Wk, Wv (tiled)
    transpose_split_kernel<<<tg, tb>>>(Wq, wthi + 0*WSZ, wtlo + 0*WSZ);
    transpose_split_kernel<<<tg, tb>>>(Wk, wthi + 1*WSZ, wtlo + 1*WSZ);
    transpose_split_kernel<<<tg, tb>>>(Wv, wthi + 2*WSZ, wtlo + 2*WSZ);
    // launch 4 (ncu capture slot): V projection
    gemm_mma_kernel<1><<<gg, 128, GEMM_SMEM>>>(xhi, xlo, wthi + 2*WSZ, wtlo + 2*WSZ,
                                               nullptr, vhi, vlo, nullptr,
                                               ROWS, INNER, DMODEL);
    // launch 5: transpose Wo
    transpose_split_kernel<<<tg, tb>>>(Wo, wthi + 3*WSZ, wtlo + 3*WSZ);
    // launches 6-7: Q, K projections with fused RMSNorm
    gemm_mma_kernel<2><<<gg, 128, GEMM_SMEM>>>(xhi, xlo, wthi + 0*WSZ, wtlo + 0*WSZ,
                                               nullptr, qhi, qlo, qg,
                                               ROWS, INNER, DMODEL);
    gemm_mma_kernel<2><<<gg, 128, GEMM_SMEM>>>(xhi, xlo, wthi + 1*WSZ, wtlo + 1*WSZ,
                                               nullptr, khi, klo, kg,
                                               ROWS, INNER, DMODEL);
    // launch 8: flash attention (epilogue writes tiled ao)
    flash_mma_kernel<<<gridF, 128, FLASH_SMEM>>>(qhi, qlo, khi, klo, vhi, vlo,
                                                 aohi, aolo);
    // launch 9: output projection
    gemm_mma_kernel<0><<<gg, 128, GEMM_SMEM>>>(aohi, aolo, wthi + 3*WSZ, wtlo + 3*WSZ,
                                               out, nullptr, nullptr, nullptr,
                                               ROWS, DMODEL, INNER);
}

// round 11
// speedup vs baseline: 1.4005x; 1.0000x over previous
#include <cuda_runtime.h>
#include <cuda_bf16.h>
#include <stdint.h>
#include <math.h>

// Problem constants
#define S_LEN   2048
#define BATCH   2
#define NHEAD   16
#define HDIM    128
#define DMODEL  2048
#define INNER   2048          // NHEAD*HDIM
#define ROWS    (BATCH*S_LEN) // 4096

// Scratch (allocation forbidden -> __device__ globals)
// xhi/xlo, wthi/wtlo, aohi/aolo are stored in TILED+SWIZZLED layouts (below),
// 1024B-aligned (cp.async.bulk requires >=16B-aligned global addresses).
// q/k/v hi/lo stay row-major [ROWS, INNER] for the flash kernel.
__device__ __align__(1024) __nv_bfloat16 g_xhi[(size_t)ROWS * DMODEL];
__device__ __align__(1024) __nv_bfloat16 g_xlo[(size_t)ROWS * DMODEL];
__device__ __align__(1024) __nv_bfloat16 g_wthi[4][(size_t)DMODEL * INNER];
__device__ __align__(1024) __nv_bfloat16 g_wtlo[4][(size_t)DMODEL * INNER];
__device__ __align__(1024) __nv_bfloat16 g_qhi[(size_t)ROWS * INNER];
__device__ __align__(1024) __nv_bfloat16 g_qlo[(size_t)ROWS * INNER];
__device__ __align__(1024) __nv_bfloat16 g_khi[(size_t)ROWS * INNER];
__device__ __align__(1024) __nv_bfloat16 g_klo[(size_t)ROWS * INNER];
__device__ __align__(1024) __nv_bfloat16 g_vhi[(size_t)ROWS * INNER];
__device__ __align__(1024) __nv_bfloat16 g_vlo[(size_t)ROWS * INNER];
__device__ __align__(1024) __nv_bfloat16 g_aohi[(size_t)ROWS * INNER];
__device__ __align__(1024) __nv_bfloat16 g_aolo[(size_t)ROWS * INNER];

// ---------------------------------------------------------------------------
// Tiled layouts (element offsets in bf16 units).
// A-tiled: 256-row blocks x 32-col chunks; tile = 256x32 = 8192 elems (16KB).
//   within tile: elem (rl, kl) at rl*32 + ((ch ^ ((rl>>1)&3))<<3) + w,
//   ch = kl>>3, w = kl&7.  (XOR swizzle -> conflict-free ldmatrix @64B rows)
// B-tiled: 128-row blocks; tile = 128x32 = 4096 elems (8KB), same swizzle.
// A 128-row CTA half of a 256-row block is a contiguous 8KB span.
// ---------------------------------------------------------------------------
__device__ __forceinline__ size_t a_tile_off(int rg, int k, int K) {
    int rb = rg >> 8, rl = rg & 255, c = k >> 5, kl = k & 31;
    int ch = kl >> 3, w = kl & 7;
    return ((size_t)(rb * (K >> 5) + c) << 13) + rl * 32 +
           (((ch ^ ((rl >> 1) & 3)) << 3) + w);
}
__device__ __forceinline__ size_t b_tile_off(int n, int k, int K) {
    int nb = n >> 7, nl = n & 127, c = k >> 5, kl = k & 31;
    int ch = kl >> 3, w = kl & 7;
    return ((size_t)(nb * (K >> 5) + c) << 12) + nl * 32 +
           (((ch ^ ((nl >> 1) & 3)) << 3) + w);
}

// ---------------------------------------------------------------------------
// PTX helpers
// ---------------------------------------------------------------------------
__device__ __forceinline__ uint32_t smem_u32(const void* p) {
    uint32_t a;
    asm("{ .reg .u64 t; cvta.to.shared.u64 t, %1; cvt.u32.u64 %0, t; }"
        : "=r"(a) : "l"(p));
    return a;
}
__device__ __forceinline__ void cp16(uint32_t dst, const void* src) {
    asm volatile("cp.async.cg.shared.global [%0], [%1], 16;" :: "r"(dst), "l"(src));
}
__device__ __forceinline__ void cp_commit() { asm volatile("cp.async.commit_group;"); }
template<int N> __device__ __forceinline__ void cp_wait() {
    asm volatile("cp.async.wait_group %0;" :: "n"(N));
}
__device__ __forceinline__ void bulkcp(uint32_t dst, const void* src,
                                       uint32_t bytes, uint32_t mbar) {
    asm volatile(
        "cp.async.bulk.shared::cluster.global.mbarrier::complete_tx::bytes "
        "[%0], [%1], %2, [%3];"
        :: "r"(dst), "l"(src), "r"(bytes), "r"(mbar) : "memory");
}
__device__ __forceinline__ void mbar_init(uint32_t a, uint32_t c) {
    asm volatile("mbarrier.init.shared.b64 [%0], %1;" :: "r"(a), "r"(c) : "memory");
}
__device__ __forceinline__ void mbar_expect(uint32_t mbar, uint32_t bytes) {
    asm volatile("mbarrier.arrive.expect_tx.shared.b64 _, [%0], %1;"
                 :: "r"(mbar), "r"(bytes) : "memory");
}
__device__ __forceinline__ void mbar_wait(uint32_t mbar, uint32_t parity) {
    asm volatile(
        "{\n\t.reg .pred P;\n\t"
        "WL_%=:\n\t"
        "mbarrier.try_wait.parity.shared.b64 P, [%0], %1;\n\t"
        "@P bra.uni WD_%=;\n\t"
        "bra.uni WL_%=;\n\t"
        "WD_%=:\n\t}"
        :: "r"(mbar), "r"(parity) : "memory");
}
__device__ __forceinline__ void fence_async() {
    asm volatile("fence.proxy.async.shared::cta;" ::: "memory");
}
__device__ __forceinline__ void ldm_x4(uint32_t* r, uint32_t addr) {
    asm volatile("ldmatrix.sync.aligned.m8n8.x4.shared.b16 {%0,%1,%2,%3}, [%4];"
                 : "=r"(r[0]), "=r"(r[1]), "=r"(r[2]), "=r"(r[3]) : "r"(addr));
}
__device__ __forceinline__ void ldm_x4t(uint32_t* r, uint32_t addr) {
    asm volatile("ldmatrix.sync.aligned.m8n8.x4.trans.shared.b16 {%0,%1,%2,%3}, [%4];"
                 : "=r"(r[0]), "=r"(r[1]), "=r"(r[2]), "=r"(r[3]) : "r"(addr));
}
__device__ __forceinline__ void mma16816(float* c, const uint32_t* a, const uint32_t* b) {
    asm volatile(
        "mma.sync.aligned.m16n8k16.row.col.f32.bf16.bf16.f32 "
        "{%0,%1,%2,%3}, {%4,%5,%6,%7}, {%8,%9}, {%0,%1,%2,%3};"
        : "+f"(c[0]), "+f"(c[1]), "+f"(c[2]), "+f"(c[3])
        : "r"(a[0]), "r"(a[1]), "r"(a[2]), "r"(a[3]), "r"(b[0]), "r"(b[1]));
}
__device__ __forceinline__ uint32_t pack_bf2(float a, float b) {
    __nv_bfloat162 t = __floats2bfloat162_rn(a, b);
    return *(uint32_t*)&t;
}
__device__ __forceinline__ void split1(float v, __nv_bfloat16& h, float& r) {
    h = __float2bfloat16(v);
    r = v - __bfloat162float(h);
}

// ---------------------------------------------------------------------------
// bf16 hi/lo split GEMM with cp.async.bulk tile loads.
// CTA 128x128, BK=32, 128 threads (4 warps, warp tile 64x64), 3-stage
// mbarrier pipeline, occupancy 2 (flash-proven shape).
// MODE 0: fp32 C.  MODE 1: bf16 split C.  MODE 2: RMSNorm + split C.
// ---------------------------------------------------------------------------
#define G_BM 128
#define G_BN 128
#define A_TB 8192                // bytes per 128-row A half-tile (hi or lo)
#define B_TB 8192
#define STAGEB (2 * A_TB + 2 * B_TB)   // 32768
#define NSTAGE 3
#define GEMM_SMEM (NSTAGE * STAGEB + 64)   // 98368

template<int MODE>
__global__ __launch_bounds__(128, 2)
void gemm_mma_kernel(const __nv_bfloat16* __restrict__ Ahi,
                     const __nv_bfloat16* __restrict__ Alo,
                     const __nv_bfloat16* __restrict__ Bhi,
                     const __nv_bfloat16* __restrict__ Blo,
                     float* __restrict__ C,
                     __nv_bfloat16* __restrict__ Chi,
                     __nv_bfloat16* __restrict__ Clo,
                     const float* __restrict__ gamma,
                     int M, int N, int K)
{
    extern __shared__ char smem[];
    const uint32_t sbase = smem_u32(smem);
    const uint32_t mbar0 = sbase + NSTAGE * STAGEB;
    const int tid  = threadIdx.x;
    const int warp = tid >> 5;
    const int lane = tid & 31;
    const int wm = warp >> 1;          // 0..1 -> 64 rows each
    const int wn = warp & 1;           // 0..1 -> 64 cols each

    const int rowblk = blockIdx.y;       // 128-row block
    const int colblk = blockIdx.x;       // 128-col block
    const int row0 = rowblk * G_BM;
    const int col0 = colblk * G_BN;
    const int KC = K >> 5;

    if (tid == 0) {
#pragma unroll
        for (int s = 0; s < NSTAGE; s++) mbar_init(mbar0 + s * 8, 1);
        fence_async();
    }
    __syncthreads();

    float acc[4][8][4];
#pragma unroll
    for (int mt = 0; mt < 4; mt++)
#pragma unroll
        for (int nt = 0; nt < 8; nt++)
#pragma unroll
            for (int r = 0; r < 4; r++) acc[mt][nt][r] = 0.0f;

    // A global addressing: 256-row blocks; this CTA uses one 8KB half.
    const int arb  = rowblk >> 1;
    const size_t ahalf = (size_t)(rowblk & 1) * 8192;

    auto issue = [&](int c, int s) {
        uint32_t stb = sbase + s * STAGEB;
        uint32_t mb = mbar0 + s * 8;
        const char* ah = (const char*)Ahi + (((size_t)(arb * KC + c)) << 14) + ahalf;
        const char* al = (const char*)Alo + (((size_t)(arb * KC + c)) << 14) + ahalf;
        const char* bh = (const char*)Bhi + (((size_t)(colblk * KC + c)) << 13);
        const char* bl = (const char*)Blo + (((size_t)(colblk * KC + c)) << 13);
        mbar_expect(mb, STAGEB);
        bulkcp(stb,            ah, A_TB, mb);
        bulkcp(stb + A_TB,     al, A_TB, mb);
        bulkcp(stb + 2 * A_TB, bh, B_TB, mb);
        bulkcp(stb + 2 * A_TB + B_TB, bl, B_TB, mb);
    };

    if (tid == 0) { issue(0, 0); issue(1, 1); }

    // per-lane invariant address pieces
    const int arow_l = (lane & 15);
    const int brow_l = (lane & 7) + 8 * (lane >> 4);
    const int a_chl  = lane >> 4;
    const int b_chl  = (lane >> 3) & 1;

    for (int c = 0; c < KC; ++c) {
        const int s = c % NSTAGE;
        if (tid == 0 && c + 2 < KC) issue(c + 2, (c + 2) % NSTAGE);
        mbar_wait(mbar0 + s * 8, (c / NSTAGE) & 1);

        const uint32_t sA  = sbase + s * STAGEB;
        const uint32_t sAl = sA + A_TB;
        const uint32_t sB  = sA + 2 * A_TB;
        const uint32_t sBl = sB + B_TB;
#pragma unroll
        for (int ks = 0; ks < 2; ks++) {
            uint32_t ah[4][4], al[4][4];
#pragma unroll
            for (int mt = 0; mt < 4; mt++) {
                int arow = wm * 64 + mt * 16 + arow_l;      // 0..127 local
                int ch = (2 * ks + a_chl) ^ ((arow >> 1) & 3);
                uint32_t aoff = arow * 64 + ch * 16;
                ldm_x4(ah[mt], sA  + aoff);
                ldm_x4(al[mt], sAl + aoff);
            }
            uint32_t bh[8][2], bl[8][2];
#pragma unroll
            for (int p = 0; p < 4; p++) {
                int brow = wn * 64 + p * 16 + brow_l;
                int ch = (2 * ks + b_chl) ^ ((brow >> 1) & 3);
                uint32_t boff = brow * 64 + ch * 16;
                uint32_t t0[4], t1[4];
                ldm_x4(t0, sB  + boff);
                ldm_x4(t1, sBl + boff);
                bh[2*p][0]   = t0[0]; bh[2*p][1]   = t0[1];
                bh[2*p+1][0] = t0[2]; bh[2*p+1][1] = t0[3];
                bl[2*p][0]   = t1[0]; bl[2*p][1]   = t1[1];
                bl[2*p+1][0] = t1[2]; bl[2*p+1][1] = t1[3];
            }
#pragma unroll
            for (int mt = 0; mt < 4; mt++)
#pragma unroll
                for (int nt = 0; nt < 8; nt++) {
                    mma16816(acc[mt][nt], ah[mt], bh[nt]);
                    mma16816(acc[mt][nt], ah[mt], bl[nt]);
                    mma16816(acc[mt][nt], al[mt], bh[nt]);
                }
        }
        __syncthreads();
    }

    if (MODE == 0) {
#pragma unroll
        for (int mt = 0; mt < 4; mt++) {
            int r0 = row0 + wm * 64 + mt * 16 + (lane >> 2);
#pragma unroll
            for (int nt = 0; nt < 8; nt++) {
                int cc = col0 + wn * 64 + nt * 8 + (lane & 3) * 2;
                *(float2*)(C + (size_t)r0 * N + cc) =
                    make_float2(acc[mt][nt][0], acc[mt][nt][1]);
                *(float2*)(C + (size_t)(r0 + 8) * N + cc) =
                    make_float2(acc[mt][nt][2], acc[mt][nt][3]);
            }
        }
    } else if (MODE == 1) {
        // row-major bf16 hi/lo output (consumed by flash)
#pragma unroll
        for (int mt = 0; mt < 4; mt++) {
            int r0 = row0 + wm * 64 + mt * 16 + (lane >> 2);
#pragma unroll
            for (int nt = 0; nt < 8; nt++) {
                int cc = col0 + wn * 64 + nt * 8 + (lane & 3) * 2;
                __nv_bfloat16 h0, h1; float l0, l1;
                split1(acc[mt][nt][0], h0, l0);
                split1(acc[mt][nt][1], h1, l1);
                __nv_bfloat162 hp; hp.x = h0; hp.y = h1;
                *(uint32_t*)(Chi + (size_t)r0 * N + cc) = *(uint32_t*)&hp;
                *(uint32_t*)(Clo + (size_t)r0 * N + cc) = pack_bf2(l0, l1);
                split1(acc[mt][nt][2], h0, l0);
                split1(acc[mt][nt][3], h1, l1);
                __nv_bfloat162 hq; hq.x = h0; hq.y = h1;
                *(uint32_t*)(Chi + (size_t)(r0 + 8) * N + cc) = *(uint32_t*)&hq;
                *(uint32_t*)(Clo + (size_t)(r0 + 8) * N + cc) = pack_bf2(l0, l1);
            }
        }
    } else {
        // MODE 2: per-row (=head) RMSNorm + split, row-major output
        float* CS = (float*)smem;      // 128 x 132 fp32 = 67584 B < 98304
        float4 g4 = *(const float4*)(gamma + lane * 4);
#pragma unroll
        for (int mt = 0; mt < 4; mt++) {
            int r = wm * 64 + mt * 16 + (lane >> 2);
#pragma unroll
            for (int nt = 0; nt < 8; nt++) {
                int cc = wn * 64 + nt * 8 + (lane & 3) * 2;
                CS[r * 132 + cc]         = acc[mt][nt][0];
                CS[r * 132 + cc + 1]     = acc[mt][nt][1];
                CS[(r+8) * 132 + cc]     = acc[mt][nt][2];
                CS[(r+8) * 132 + cc + 1] = acc[mt][nt][3];
            }
        }
        __syncthreads();
#pragma unroll
        for (int rr = 0; rr < 32; rr++) {
            int row = warp * 32 + rr;          // 0..127 local
            float4 v = *(float4*)&CS[row * 132 + lane * 4];
            float ss = v.x*v.x + v.y*v.y + v.z*v.z + v.w*v.w;
#pragma unroll
            for (int o = 16; o > 0; o >>= 1)
                ss += __shfl_xor_sync(0xffffffffu, ss, o);
            float rn = rsqrtf(ss * (1.0f / 128.0f) + 1e-6f);
            float f[4] = { v.x*rn*g4.x, v.y*rn*g4.y, v.z*rn*g4.z, v.w*rn*g4.w };
            __nv_bfloat16 h[4]; float l[4];
#pragma unroll
            for (int j = 0; j < 4; j++) split1(f[j], h[j], l[j]);
            size_t o = (size_t)(row0 + row) * N + col0 + lane * 4;
            *(uint2*)(Chi + o) = *(uint2*)h;
            uint2 lp; lp.x = pack_bf2(l[0], l[1]); lp.y = pack_bf2(l[2], l[3]);
            *(uint2*)(Clo + o) = lp;
        }
    }
}

// ---------------------------------------------------------------------------
// Flash attention (R4/R7/R9-proven shape: 64x64, 128 thr, occ 2, cp.async).
// Epilogue writes aohi/aolo in GEMM A-tiled layout.
// ---------------------------------------------------------------------------
#define F_ROWB 272
#define FT_BYTES (64 * F_ROWB)
#define FLASH_SMEM (6 * FT_BYTES)

__global__ __launch_bounds__(128, 2)
void flash_mma_kernel(const __nv_bfloat16* __restrict__ Qhi,
                      const __nv_bfloat16* __restrict__ Qlo,
                      const __nv_bfloat16* __restrict__ Khi,
                      const __nv_bfloat16* __restrict__ Klo,
                      const __nv_bfloat16* __restrict__ Vhi,
                      const __nv_bfloat16* __restrict__ Vlo,
                      __nv_bfloat16* __restrict__ Ohi,
                      __nv_bfloat16* __restrict__ Olo)
{
    extern __shared__ char sm_raw[];
    const uint32_t sb = smem_u32(sm_raw);
    const uint32_t sQh = sb,                sQl = sb + FT_BYTES;
    const uint32_t sKh = sb + 2*FT_BYTES,   sKl = sb + 3*FT_BYTES;
    const uint32_t sVh = sb + 4*FT_BYTES,   sVl = sb + 5*FT_BYTES;

    const int tid  = threadIdx.x;
    const int warp = tid >> 5;
    const int lane = tid & 31;
    const int lr   = lane >> 2;
    const int lc   = lane & 3;
    const int m0   = warp * 16;

    const int mblk = blockIdx.x, h = blockIdx.y, b = blockIdx.z;
    const size_t qoff = ((size_t)(b * S_LEN + mblk * 64)) * INNER + h * HDIM;
    const size_t koff = ((size_t)(b * S_LEN)) * INNER + h * HDIM;

#pragma unroll
    for (int i = 0; i < 8; i++) {
        int idx = i * 128 + tid;
        int r = idx >> 4, s = idx & 15;
        uint32_t so = r * F_ROWB + s * 16;
        const size_t go = qoff + (size_t)r * INNER + s * 8;
        cp16(sQh + so, Qhi + go);
        cp16(sQl + so, Qlo + go);
    }
    cp_commit();

    float o[16][4];
#pragma unroll
    for (int nt = 0; nt < 16; nt++)
#pragma unroll
        for (int r = 0; r < 4; r++) o[nt][r] = 0.0f;
    float s_m[2] = { -1e30f, -1e30f };
    float s_l[2] = { 0.0f, 0.0f };
    const float scale = 0.08838834764831845f;

    const uint32_t a_row = m0 + (lane & 15);
    const uint32_t lhalf = 8 * (lane >> 4);

    for (int n0 = 0; n0 < S_LEN; n0 += 64) {
#pragma unroll
        for (int i = 0; i < 8; i++) {
            int idx = i * 128 + tid;
            int r = idx >> 4, s = idx & 15;
            uint32_t so = r * F_ROWB + s * 16;
            const size_t go = koff + (size_t)(n0 + r) * INNER + s * 8;
            cp16(sKh + so, Khi + go);
            cp16(sKl + so, Klo + go);
            cp16(sVh + so, Vhi + go);
            cp16(sVl + so, Vlo + go);
        }
        cp_commit();
        cp_wait<0>();
        __syncthreads();

        float s[8][4];
#pragma unroll
        for (int j = 0; j < 8; j++)
#pragma unroll
            for (int r = 0; r < 4; r++) s[j][r] = 0.0f;

#pragma unroll
        for (int t = 0; t < 8; t++) {
            const int d0 = t * 16;
            uint32_t ah[4], al[4];
            uint32_t aoff = a_row * F_ROWB + (d0 + lhalf) * 2;
            ldm_x4(ah, sQh + aoff);
            ldm_x4(al, sQl + aoff);
#pragma unroll
            for (int p = 0; p < 4; p++) {
                uint32_t bh[4], bl[4];
                uint32_t boff = (p * 16 + (lane & 15)) * F_ROWB + (d0 + lhalf) * 2;
                ldm_x4(bh, sKh + boff);
                ldm_x4(bl, sKl + boff);
                uint32_t b0h[2] = { bh[0], bh[2] }, b1h[2] = { bh[1], bh[3] };
                uint32_t b0l[2] = { bl[0], bl[2] }, b1l[2] = { bl[1], bl[3] };
                mma16816(s[2*p],   ah, b0h);
                mma16816(s[2*p],   ah, b0l);
                mma16816(s[2*p],   al, b0h);
                mma16816(s[2*p+1], ah, b1h);
                mma16816(s[2*p+1], ah, b1l);
                mma16816(s[2*p+1], al, b1h);
            }
        }

#pragma unroll
        for (int j = 0; j < 8; j++)
#pragma unroll
            for (int r = 0; r < 4; r++) s[j][r] *= scale;

        float mx0 = -1e30f, mx1 = -1e30f;
#pragma unroll
        for (int j = 0; j < 8; j++) {
            mx0 = fmaxf(mx0, fmaxf(s[j][0], s[j][1]));
            mx1 = fmaxf(mx1, fmaxf(s[j][2], s[j][3]));
        }
        mx0 = fmaxf(mx0, __shfl_xor_sync(0xffffffffu, mx0, 1));
        mx0 = fmaxf(mx0, __shfl_xor_sync(0xffffffffu, mx0, 2));
        mx1 = fmaxf(mx1, __shfl_xor_sync(0xffffffffu, mx1, 1));
        mx1 = fmaxf(mx1, __shfl_xor_sync(0xffffffffu, mx1, 2));

        float mn0 = fmaxf(s_m[0], mx0), mn1 = fmaxf(s_m[1], mx1);
        float al0 = __expf(s_m[0] - mn0), al1 = __expf(s_m[1] - mn1);
        s_m[0] = mn0; s_m[1] = mn1;

        float rs0 = 0.0f, rs1 = 0.0f;
#pragma unroll
        for (int j = 0; j < 8; j++) {
            s[j][0] = __expf(s[j][0] - mn0);
            s[j][1] = __expf(s[j][1] - mn0);
            s[j][2] = __expf(s[j][2] - mn1);
            s[j][3] = __expf(s[j][3] - mn1);
            rs0 += s[j][0] + s[j][1];
            rs1 += s[j][2] + s[j][3];
        }
        rs0 += __shfl_xor_sync(0xffffffffu, rs0, 1);
        rs0 += __shfl_xor_sync(0xffffffffu, rs0, 2);
        rs1 += __shfl_xor_sync(0xffffffffu, rs1, 1);
        rs1 += __shfl_xor_sync(0xffffffffu, rs1, 2);
        s_l[0] = s_l[0] * al0 + rs0;
        s_l[1] = s_l[1] * al1 + rs1;

#pragma unroll
        for (int nt = 0; nt < 16; nt++) {
            o[nt][0] *= al0; o[nt][1] *= al0;
            o[nt][2] *= al1; o[nt][3] *= al1;
        }

        uint32_t ph[4][4], pl[4][4];
#pragma unroll
        for (int t = 0; t < 4; t++) {
#pragma unroll
            for (int q = 0; q < 4; q++) {
                int j = 2 * t + (q >> 1);
                int cc = (q & 1) * 2;
                float v0 = s[j][cc], v1 = s[j][cc + 1];
                __nv_bfloat16 h0, h1; float r0, r1;
                split1(v0, h0, r0);
                split1(v1, h1, r1);
                __nv_bfloat162 hp; hp.x = h0; hp.y = h1;
                ph[t][q] = *(uint32_t*)&hp;
                pl[t][q] = pack_bf2(r0, r1);
            }
        }

#pragma unroll
        for (int t = 0; t < 4; t++) {
#pragma unroll
            for (int np = 0; np < 8; np++) {
                uint32_t vh[4], vl[4];
                uint32_t voff = (t * 16 + (lane & 15)) * F_ROWB + (np * 16 + lhalf) * 2;
                ldm_x4t(vh, sVh + voff);
                ldm_x4t(vl, sVl + voff);
                uint32_t b0h[2] = { vh[0], vh[1] }, b1h[2] = { vh[2], vh[3] };
                uint32_t b0l[2] = { vl[0], vl[1] }, b1l[2] = { vl[2], vl[3] };
                mma16816(o[2*np],   ph[t], b0h);
                mma16816(o[2*np],   ph[t], b0l);
                mma16816(o[2*np],   pl[t], b0h);
                mma16816(o[2*np+1], ph[t], b1h);
                mma16816(o[2*np+1], ph[t], b1l);
                mma16816(o[2*np+1], pl[t], b1h);
            }
        }
        __syncthreads();
    }

    // epilogue: normalize, split, store in GEMM A-tiled layout
    float inv0 = 1.0f / s_l[0];
    float inv1 = 1.0f / s_l[1];
    int row0g = b * S_LEN + mblk * 64 + m0 + lr;
    int row1g = row0g + 8;
#pragma unroll
    for (int nt = 0; nt < 16; nt++) {
        int col = h * HDIM + nt * 8 + lc * 2;
        size_t o0 = a_tile_off(row0g, col, INNER);
        size_t o1 = a_tile_off(row1g, col, INNER);
        float a0 = o[nt][0] * inv0, a1 = o[nt][1] * inv0;
        float b0 = o[nt][2] * inv1, b1 = o[nt][3] * inv1;
        __nv_bfloat16 h00, h01, h10, h11; float l00, l01, l10, l11;
        split1(a0, h00, l00); split1(a1, h01, l01);
        split1(b0, h10, l10); split1(b1, h11, l11);
        __nv_bfloat162 hp0; hp0.x = h00; hp0.y = h01;
        __nv_bfloat162 hp1; hp1.x = h10; hp1.y = h11;
        *(uint32_t*)(Ohi + o0) = *(uint32_t*)&hp0;
        *(uint32_t*)(Ohi + o1) = *(uint32_t*)&hp1;
        *(uint32_t*)(Olo + o0) = pack_bf2(l00, l01);
        *(uint32_t*)(Olo + o1) = pack_bf2(l10, l11);
    }
}

// ---------------------------------------------------------------------------
// fp32 -> bf16 hi/lo split, writing A-tiled swizzled layout
// ---------------------------------------------------------------------------
__global__ void split_kernel(const float4* __restrict__ in,
                             __nv_bfloat16* __restrict__ hi,
                             __nv_bfloat16* __restrict__ lo, int n4, int K) {
    int i = blockIdx.x * blockDim.x + threadIdx.x;
    if (i >= n4) return;
    float4 v = in[i];
    float f[4] = { v.x, v.y, v.z, v.w };
    __nv_bfloat16 h[4]; float l[4];
#pragma unroll
    for (int j = 0; j < 4; j++) split1(f[j], h[j], l[j]);
    int rg = (i * 4) / K;
    int k0 = (i * 4) % K;
    size_t o = a_tile_off(rg, k0, K);
    *(uint2*)(hi + o) = *(uint2*)h;
    uint2 lp; lp.x = pack_bf2(l[0], l[1]); lp.y = pack_bf2(l[2], l[3]);
    *(uint2*)(lo + o) = lp;
}

// ---------------------------------------------------------------------------
// Transpose + split: W[K, N] fp32 -> B-tiled swizzled T{hi,lo}[N, K] bf16
// ---------------------------------------------------------------------------
__global__ void transpose_split_kernel(const float* __restrict__ W,
                                       __nv_bfloat16* __restrict__ Thi,
                                       __nv_bfloat16* __restrict__ Tlo) {
    __shared__ float t[32][33];
    int n0 = blockIdx.x * 32, k0 = blockIdx.y * 32;
#pragma unroll
    for (int i = 0; i < 32; i += 8)
        t[threadIdx.y + i][threadIdx.x] =
            W[(size_t)(k0 + threadIdx.y + i) * 2048 + n0 + threadIdx.x];
    __syncthreads();
#pragma unroll
    for (int i = 0; i < 32; i += 8) {
        float v = t[threadIdx.x][threadIdx.y + i];
        __nv_bfloat16 h; float l;
        split1(v, h, l);
        size_t o = b_tile_off(n0 + threadIdx.y + i, k0 + threadIdx.x, 2048);
        Thi[o] = h;
        Tlo[o] = __float2bfloat16(l);
    }
}

// ---------------------------------------------------------------------------
// Launcher (ncu capture slot = launch 4 = GEMM)
// ---------------------------------------------------------------------------
extern "C" void kernel_launch(void* const* d_in, const int* in_sizes, int n_in,
                              void* d_out, int out_size) {
    const float* x  = (const float*)d_in[0];
    const float* Wq = (const float*)d_in[1];
    const float* Wk = (const float*)d_in[2];
    const float* Wv = (const float*)d_in[3];
    const float* Wo = (const float*)d_in[4];
    const float* qg = (const float*)d_in[5];
    const float* kg = (const float*)d_in[6];
    float* out = (float*)d_out;

    __nv_bfloat16 *xhi, *xlo, *wthi, *wtlo;
    __nv_bfloat16 *qhi, *qlo, *khi, *klo, *vhi, *vlo, *aohi, *aolo;
    cudaGetSymbolAddress((void**)&xhi,  g_xhi);
    cudaGetSymbolAddress((void**)&xlo,  g_xlo);
    cudaGetSymbolAddress((void**)&wthi, g_wthi);
    cudaGetSymbolAddress((void**)&wtlo, g_wtlo);
    cudaGetSymbolAddress((void**)&qhi,  g_qhi);
    cudaGetSymbolAddress((void**)&qlo,  g_qlo);
    cudaGetSymbolAddress((void**)&khi,  g_khi);
    cudaGetSymbolAddress((void**)&klo,  g_klo);
    cudaGetSymbolAddress((void**)&vhi,  g_vhi);
    cudaGetSymbolAddress((void**)&vlo,  g_vlo);
    cudaGetSymbolAddress((void**)&aohi, g_aohi);
    cudaGetSymbolAddress((void**)&aolo, g_aolo);
    const size_t WSZ = (size_t)DMODEL * INNER;

    cudaFuncSetAttribute(gemm_mma_kernel<0>, cudaFuncAttributeMaxDynamicSharedMemorySize, GEMM_SMEM);
    cudaFuncSetAttribute(gemm_mma_kernel<1>, cudaFuncAttributeMaxDynamicSharedMemorySize, GEMM_SMEM);
    cudaFuncSetAttribute(gemm_mma_kernel<2>, cudaFuncAttributeMaxDynamicSharedMemorySize, GEMM_SMEM);
    cudaFuncSetAttribute(flash_mma_kernel, cudaFuncAttributeMaxDynamicSharedMemorySize, FLASH_SMEM);

    dim3 tb(32, 8), tg(64, 64);
    dim3 gg(INNER / G_BN, ROWS / G_BM);   // (16, 32) -> 512 CTAs
    dim3 gridF(S_LEN / 64, NHEAD, BATCH);

    // launch 0: split x (tiled)
    int n4x = ROWS * DMODEL / 4;
    split_kernel<<<n4x / 256, 256>>>((const float4*)x, xhi, xlo, n4x, DMODEL);
    // launches 1-3: transpose Wq, Wk, Wv (tiled)
    transpose_split_kernel<<<tg, tb>>>(Wq, wthi + 0*WSZ, wtlo + 0*WSZ);
    transpose_split_kernel<<<tg, tb>>>(Wk, wthi + 1*WSZ, wtlo + 1*WSZ);
    transpose_split_kernel<<<tg, tb>>>(Wv, wthi + 2*WSZ, wtlo + 2*WSZ);
    // launch 4 (ncu capture slot): V projection
    gemm_mma_kernel<1><<<gg, 128, GEMM_SMEM>>>(xhi, xlo, wthi + 2*WSZ, wtlo + 2*WSZ,
                                               nullptr, vhi, vlo, nullptr,
                                               ROWS, INNER, DMODEL);
    // launch 5: transpose Wo
    transpose_split_kernel<<<tg, tb>>>(Wo, wthi + 3*WSZ, wtlo + 3*WSZ);
    // launches 6-7: Q, K projections with fused RMSNorm
    gemm_mma_kernel<2><<<gg, 128, GEMM_SMEM>>>(xhi, xlo, wthi + 0*WSZ, wtlo + 0*WSZ,
                                               nullptr, qhi, qlo, qg,
                                               ROWS, INNER, DMODEL);
    gemm_mma_kernel<2><<<gg, 128, GEMM_SMEM>>>(xhi, xlo, wthi + 1*WSZ, wtlo + 1*WSZ,
                                               nullptr, khi, klo, kg,
                                               ROWS, INNER, DMODEL);
    // launch 8: flash attention (epilogue writes tiled ao)
    flash_mma_kernel<<<gridF, 128, FLASH_SMEM>>>(qhi, qlo, khi, klo, vhi, vlo,
                                                 aohi, aolo);
    // launch 9: output projection
    gemm_mma_kernel<0><<<gg, 128, GEMM_SMEM>>>(aohi, aolo, wthi + 3*WSZ, wtlo + 3*WSZ,
                                               out, nullptr, nullptr, nullptr,
                                               ROWS, DMODEL, INNER);
}

// round 12
// speedup vs baseline: 1.4182x; 1.0127x over previous
#include <cuda_runtime.h>
#include <cuda_bf16.h>
#include <stdint.h>
#include <math.h>

// Problem constants
#define S_LEN   2048
#define BATCH   2
#define NHEAD   16
#define HDIM    128
#define DMODEL  2048
#define INNER   2048          // NHEAD*HDIM
#define ROWS    (BATCH*S_LEN) // 4096

// Scratch (allocation forbidden -> __device__ globals)
// x / weights / attention-output live in PAIRED-TILE layouts (hi+lo interleaved
// per 128x32 tile, see below), 1024B-aligned for cp.async.bulk.
// q/k/v hi/lo stay row-major [ROWS, INNER] for the flash kernel.
__device__ __align__(1024) __nv_bfloat16 g_xt[(size_t)2 * ROWS * DMODEL];
__device__ __align__(1024) __nv_bfloat16 g_wt[4][(size_t)2 * DMODEL * INNER];
__device__ __align__(1024) __nv_bfloat16 g_aot[(size_t)2 * ROWS * INNER];
__device__ __align__(1024) __nv_bfloat16 g_qhi[(size_t)ROWS * INNER];
__device__ __align__(1024) __nv_bfloat16 g_qlo[(size_t)ROWS * INNER];
__device__ __align__(1024) __nv_bfloat16 g_khi[(size_t)ROWS * INNER];
__device__ __align__(1024) __nv_bfloat16 g_klo[(size_t)ROWS * INNER];
__device__ __align__(1024) __nv_bfloat16 g_vhi[(size_t)ROWS * INNER];
__device__ __align__(1024) __nv_bfloat16 g_vlo[(size_t)ROWS * INNER];

// ---------------------------------------------------------------------------
// Paired-tile layout (element offsets in bf16 units).
// Tile = 128 rows x 32 cols. Pair = [hi tile 4096 elems][lo tile 4096 elems]
// stored contiguously (16 KB). Pair index = rowblk * (K/32) + chunk.
// Within a tile: elem (rl, kl) at rl*32 + ((ch ^ ((rl>>1)&3))<<3) + w,
//   ch = kl>>3, w = kl&7   (XOR swizzle -> conflict-free ldmatrix, 64B rows).
// lo part of the same element at +4096.
// ---------------------------------------------------------------------------
__device__ __forceinline__ size_t pair_off(int rg, int k, int K) {
    int rb = rg >> 7, rl = rg & 127, c = k >> 5, kl = k & 31;
    int ch = kl >> 3, w = kl & 7;
    return ((size_t)(rb * (K >> 5) + c) << 13) + rl * 32 +
           (((ch ^ ((rl >> 1) & 3)) << 3) + w);
}

// ---------------------------------------------------------------------------
// PTX helpers
// ---------------------------------------------------------------------------
__device__ __forceinline__ uint32_t smem_u32(const void* p) {
    uint32_t a;
    asm("{ .reg .u64 t; cvta.to.shared.u64 t, %1; cvt.u32.u64 %0, t; }"
        : "=r"(a) : "l"(p));
    return a;
}
__device__ __forceinline__ void cp16(uint32_t dst, const void* src) {
    asm volatile("cp.async.cg.shared.global [%0], [%1], 16;" :: "r"(dst), "l"(src));
}
__device__ __forceinline__ void cp_commit() { asm volatile("cp.async.commit_group;"); }
template<int N> __device__ __forceinline__ void cp_wait() {
    asm volatile("cp.async.wait_group %0;" :: "n"(N));
}
__device__ __forceinline__ void bulkcp(uint32_t dst, const void* src,
                                       uint32_t bytes, uint32_t mbar) {
    asm volatile(
        "cp.async.bulk.shared::cluster.global.mbarrier::complete_tx::bytes "
        "[%0], [%1], %2, [%3];"
        :: "r"(dst), "l"(src), "r"(bytes), "r"(mbar) : "memory");
}
__device__ __forceinline__ void mbar_init(uint32_t a, uint32_t c) {
    asm volatile("mbarrier.init.shared.b64 [%0], %1;" :: "r"(a), "r"(c) : "memory");
}
__device__ __forceinline__ void mbar_expect(uint32_t mbar, uint32_t bytes) {
    asm volatile("mbarrier.arrive.expect_tx.shared.b64 _, [%0], %1;"
                 :: "r"(mbar), "r"(bytes) : "memory");
}
__device__ __forceinline__ void mbar_wait(uint32_t mbar, uint32_t parity) {
    asm volatile(
        "{\n\t.reg .pred P;\n\t"
        "WL_%=:\n\t"
        "mbarrier.try_wait.parity.shared.b64 P, [%0], %1;\n\t"
        "@P bra.uni WD_%=;\n\t"
        "bra.uni WL_%=;\n\t"
        "WD_%=:\n\t}"
        :: "r"(mbar), "r"(parity) : "memory");
}
__device__ __forceinline__ void fence_async() {
    asm volatile("fence.proxy.async.shared::cta;" ::: "memory");
}
__device__ __forceinline__ void ldm_x4(uint32_t* r, uint32_t addr) {
    asm volatile("ldmatrix.sync.aligned.m8n8.x4.shared.b16 {%0,%1,%2,%3}, [%4];"
                 : "=r"(r[0]), "=r"(r[1]), "=r"(r[2]), "=r"(r[3]) : "r"(addr));
}
__device__ __forceinline__ void ldm_x4t(uint32_t* r, uint32_t addr) {
    asm volatile("ldmatrix.sync.aligned.m8n8.x4.trans.shared.b16 {%0,%1,%2,%3}, [%4];"
                 : "=r"(r[0]), "=r"(r[1]), "=r"(r[2]), "=r"(r[3]) : "r"(addr));
}
__device__ __forceinline__ void mma16816(float* c, const uint32_t* a, const uint32_t* b) {
    asm volatile(
        "mma.sync.aligned.m16n8k16.row.col.f32.bf16.bf16.f32 "
        "{%0,%1,%2,%3}, {%4,%5,%6,%7}, {%8,%9}, {%0,%1,%2,%3};"
        : "+f"(c[0]), "+f"(c[1]), "+f"(c[2]), "+f"(c[3])
        : "r"(a[0]), "r"(a[1]), "r"(a[2]), "r"(a[3]), "r"(b[0]), "r"(b[1]));
}
__device__ __forceinline__ uint32_t pack_bf2(float a, float b) {
    __nv_bfloat162 t = __floats2bfloat162_rn(a, b);
    return *(uint32_t*)&t;
}
__device__ __forceinline__ void split1(float v, __nv_bfloat16& h, float& r) {
    h = __float2bfloat16(v);
    r = v - __bfloat162float(h);
}

// ---------------------------------------------------------------------------
// bf16 hi/lo split GEMM with paired-tile cp.async.bulk loads (2 ops/chunk).
// CTA 128x128, BK=32, 128 threads (4 warps, warp tile 64x64), 3-stage
// mbarrier pipeline, occupancy 2.
// MODE 0: fp32 C.  MODE 1: bf16 split C.  MODE 2: RMSNorm + split C.
// ---------------------------------------------------------------------------
#define G_BM 128
#define G_BN 128
#define A_TB 8192                // bytes per A hi (or lo) tile
#define B_TB 8192
#define PAIRB 16384              // bytes per [hi][lo] pair
#define STAGEB (2 * PAIRB)       // 32768
#define NSTAGE 3
#define GEMM_SMEM (NSTAGE * STAGEB + 64)   // 98368

template<int MODE>
__global__ __launch_bounds__(128, 2)
void gemm_mma_kernel(const __nv_bfloat16* __restrict__ A,   // paired tiles
                     const __nv_bfloat16* __restrict__ B,   // paired tiles
                     float* __restrict__ C,
                     __nv_bfloat16* __restrict__ Chi,
                     __nv_bfloat16* __restrict__ Clo,
                     const float* __restrict__ gamma,
                     int M, int N, int K)
{
    extern __shared__ char smem[];
    const uint32_t sbase = smem_u32(smem);
    const uint32_t mbar0 = sbase + NSTAGE * STAGEB;
    const int tid  = threadIdx.x;
    const int warp = tid >> 5;
    const int lane = tid & 31;
    const int wm = warp >> 1;          // 0..1 -> 64 rows each
    const int wn = warp & 1;           // 0..1 -> 64 cols each

    const int rowblk = blockIdx.y;       // 128-row block
    const int colblk = blockIdx.x;       // 128-col block
    const int row0 = rowblk * G_BM;
    const int col0 = colblk * G_BN;
    const int KC = K >> 5;

    if (tid == 0) {
#pragma unroll
        for (int s = 0; s < NSTAGE; s++) mbar_init(mbar0 + s * 8, 1);
        fence_async();
    }
    __syncthreads();

    float acc[4][8][4];
#pragma unroll
    for (int mt = 0; mt < 4; mt++)
#pragma unroll
        for (int nt = 0; nt < 8; nt++)
#pragma unroll
            for (int r = 0; r < 4; r++) acc[mt][nt][r] = 0.0f;

    auto issue = [&](int c, int s) {
        uint32_t stb = sbase + s * STAGEB;
        uint32_t mb = mbar0 + s * 8;
        const char* ap = (const char*)A + (((size_t)(rowblk * KC + c)) << 14);
        const char* bp = (const char*)B + (((size_t)(colblk * KC + c)) << 14);
        mbar_expect(mb, STAGEB);
        bulkcp(stb,         ap, PAIRB, mb);   // lands [Ahi][Alo]
        bulkcp(stb + PAIRB, bp, PAIRB, mb);   // lands [Bhi][Blo]
    };

    if (tid == 0) { issue(0, 0); issue(1, 1); }

    // per-lane invariant address pieces
    const int arow_l = (lane & 15);
    const int brow_l = (lane & 7) + 8 * (lane >> 4);
    const int a_chl  = lane >> 4;
    const int b_chl  = (lane >> 3) & 1;

    for (int c = 0; c < KC; ++c) {
        const int s = c % NSTAGE;
        if (tid == 0 && c + 2 < KC) issue(c + 2, (c + 2) % NSTAGE);
        mbar_wait(mbar0 + s * 8, (c / NSTAGE) & 1);

        const uint32_t sA  = sbase + s * STAGEB;
        const uint32_t sAl = sA + A_TB;
        const uint32_t sB  = sA + PAIRB;
        const uint32_t sBl = sB + B_TB;
#pragma unroll
        for (int ks = 0; ks < 2; ks++) {
            uint32_t ah[4][4], al[4][4];
#pragma unroll
            for (int mt = 0; mt < 4; mt++) {
                int arow = wm * 64 + mt * 16 + arow_l;      // 0..127 local
                int ch = (2 * ks + a_chl) ^ ((arow >> 1) & 3);
                uint32_t aoff = arow * 64 + ch * 16;
                ldm_x4(ah[mt], sA  + aoff);
                ldm_x4(al[mt], sAl + aoff);
            }
            uint32_t bh[8][2], bl[8][2];
#pragma unroll
            for (int p = 0; p < 4; p++) {
                int brow = wn * 64 + p * 16 + brow_l;
                int ch = (2 * ks + b_chl) ^ ((brow >> 1) & 3);
                uint32_t boff = brow * 64 + ch * 16;
                uint32_t t0[4], t1[4];
                ldm_x4(t0, sB  + boff);
                ldm_x4(t1, sBl + boff);
                bh[2*p][0]   = t0[0]; bh[2*p][1]   = t0[1];
                bh[2*p+1][0] = t0[2]; bh[2*p+1][1] = t0[3];
                bl[2*p][0]   = t1[0]; bl[2*p][1]   = t1[1];
                bl[2*p+1][0] = t1[2]; bl[2*p+1][1] = t1[3];
            }
#pragma unroll
            for (int mt = 0; mt < 4; mt++)
#pragma unroll
                for (int nt = 0; nt < 8; nt++) {
                    mma16816(acc[mt][nt], ah[mt], bh[nt]);
                    mma16816(acc[mt][nt], ah[mt], bl[nt]);
                    mma16816(acc[mt][nt], al[mt], bh[nt]);
                }
        }
        __syncthreads();
    }

    if (MODE == 0) {
#pragma unroll
        for (int mt = 0; mt < 4; mt++) {
            int r0 = row0 + wm * 64 + mt * 16 + (lane >> 2);
#pragma unroll
            for (int nt = 0; nt < 8; nt++) {
                int cc = col0 + wn * 64 + nt * 8 + (lane & 3) * 2;
                *(float2*)(C + (size_t)r0 * N + cc) =
                    make_float2(acc[mt][nt][0], acc[mt][nt][1]);
                *(float2*)(C + (size_t)(r0 + 8) * N + cc) =
                    make_float2(acc[mt][nt][2], acc[mt][nt][3]);
            }
        }
    } else if (MODE == 1) {
        // row-major bf16 hi/lo output (consumed by flash)
#pragma unroll
        for (int mt = 0; mt < 4; mt++) {
            int r0 = row0 + wm * 64 + mt * 16 + (lane >> 2);
#pragma unroll
            for (int nt = 0; nt < 8; nt++) {
                int cc = col0 + wn * 64 + nt * 8 + (lane & 3) * 2;
                __nv_bfloat16 h0, h1; float l0, l1;
                split1(acc[mt][nt][0], h0, l0);
                split1(acc[mt][nt][1], h1, l1);
                __nv_bfloat162 hp; hp.x = h0; hp.y = h1;
                *(uint32_t*)(Chi + (size_t)r0 * N + cc) = *(uint32_t*)&hp;
                *(uint32_t*)(Clo + (size_t)r0 * N + cc) = pack_bf2(l0, l1);
                split1(acc[mt][nt][2], h0, l0);
                split1(acc[mt][nt][3], h1, l1);
                __nv_bfloat162 hq; hq.x = h0; hq.y = h1;
                *(uint32_t*)(Chi + (size_t)(r0 + 8) * N + cc) = *(uint32_t*)&hq;
                *(uint32_t*)(Clo + (size_t)(r0 + 8) * N + cc) = pack_bf2(l0, l1);
            }
        }
    } else {
        // MODE 2: per-row (=head) RMSNorm + split, row-major output
        float* CS = (float*)smem;      // 128 x 132 fp32 = 67584 B < 98304
        float4 g4 = *(const float4*)(gamma + lane * 4);
#pragma unroll
        for (int mt = 0; mt < 4; mt++) {
            int r = wm * 64 + mt * 16 + (lane >> 2);
#pragma unroll
            for (int nt = 0; nt < 8; nt++) {
                int cc = wn * 64 + nt * 8 + (lane & 3) * 2;
                CS[r * 132 + cc]         = acc[mt][nt][0];
                CS[r * 132 + cc + 1]     = acc[mt][nt][1];
                CS[(r+8) * 132 + cc]     = acc[mt][nt][2];
                CS[(r+8) * 132 + cc + 1] = acc[mt][nt][3];
            }
        }
        __syncthreads();
#pragma unroll
        for (int rr = 0; rr < 32; rr++) {
            int row = warp * 32 + rr;          // 0..127 local
            float4 v = *(float4*)&CS[row * 132 + lane * 4];
            float ss = v.x*v.x + v.y*v.y + v.z*v.z + v.w*v.w;
#pragma unroll
            for (int o = 16; o > 0; o >>= 1)
                ss += __shfl_xor_sync(0xffffffffu, ss, o);
            float rn = rsqrtf(ss * (1.0f / 128.0f) + 1e-6f);
            float f[4] = { v.x*rn*g4.x, v.y*rn*g4.y, v.z*rn*g4.z, v.w*rn*g4.w };
            __nv_bfloat16 h[4]; float l[4];
#pragma unroll
            for (int j = 0; j < 4; j++) split1(f[j], h[j], l[j]);
            size_t o = (size_t)(row0 + row) * N + col0 + lane * 4;
            *(uint2*)(Chi + o) = *(uint2*)h;
            uint2 lp; lp.x = pack_bf2(l[0], l[1]); lp.y = pack_bf2(l[2], l[3]);
            *(uint2*)(Clo + o) = lp;
        }
    }
}

// ---------------------------------------------------------------------------
// Flash attention (proven shape: 64x64, 128 thr, occ 2, cp.async).
// Epilogue writes ao into the paired-tile layout.
// ---------------------------------------------------------------------------
#define F_ROWB 272
#define FT_BYTES (64 * F_ROWB)
#define FLASH_SMEM (6 * FT_BYTES)

__global__ __launch_bounds__(128, 2)
void flash_mma_kernel(const __nv_bfloat16* __restrict__ Qhi,
                      const __nv_bfloat16* __restrict__ Qlo,
                      const __nv_bfloat16* __restrict__ Khi,
                      const __nv_bfloat16* __restrict__ Klo,
                      const __nv_bfloat16* __restrict__ Vhi,
                      const __nv_bfloat16* __restrict__ Vlo,
                      __nv_bfloat16* __restrict__ Ot)
{
    extern __shared__ char sm_raw[];
    const uint32_t sb = smem_u32(sm_raw);
    const uint32_t sQh = sb,                sQl = sb + FT_BYTES;
    const uint32_t sKh = sb + 2*FT_BYTES,   sKl = sb + 3*FT_BYTES;
    const uint32_t sVh = sb + 4*FT_BYTES,   sVl = sb + 5*FT_BYTES;

    const int tid  = threadIdx.x;
    const int warp = tid >> 5;
    const int lane = tid & 31;
    const int lr   = lane >> 2;
    const int lc   = lane & 3;
    const int m0   = warp * 16;

    const int mblk = blockIdx.x, h = blockIdx.y, b = blockIdx.z;
    const size_t qoff = ((size_t)(b * S_LEN + mblk * 64)) * INNER + h * HDIM;
    const size_t koff = ((size_t)(b * S_LEN)) * INNER + h * HDIM;

#pragma unroll
    for (int i = 0; i < 8; i++) {
        int idx = i * 128 + tid;
        int r = idx >> 4, s = idx & 15;
        uint32_t so = r * F_ROWB + s * 16;
        const size_t go = qoff + (size_t)r * INNER + s * 8;
        cp16(sQh + so, Qhi + go);
        cp16(sQl + so, Qlo + go);
    }
    cp_commit();

    float o[16][4];
#pragma unroll
    for (int nt = 0; nt < 16; nt++)
#pragma unroll
        for (int r = 0; r < 4; r++) o[nt][r] = 0.0f;
    float s_m[2] = { -1e30f, -1e30f };
    float s_l[2] = { 0.0f, 0.0f };
    const float scale = 0.08838834764831845f;

    const uint32_t a_row = m0 + (lane & 15);
    const uint32_t lhalf = 8 * (lane >> 4);

    for (int n0 = 0; n0 < S_LEN; n0 += 64) {
#pragma unroll
        for (int i = 0; i < 8; i++) {
            int idx = i * 128 + tid;
            int r = idx >> 4, s = idx & 15;
            uint32_t so = r * F_ROWB + s * 16;
            const size_t go = koff + (size_t)(n0 + r) * INNER + s * 8;
            cp16(sKh + so, Khi + go);
            cp16(sKl + so, Klo + go);
            cp16(sVh + so, Vhi + go);
            cp16(sVl + so, Vlo + go);
        }
        cp_commit();
        cp_wait<0>();
        __syncthreads();

        float s[8][4];
#pragma unroll
        for (int j = 0; j < 8; j++)
#pragma unroll
            for (int r = 0; r < 4; r++) s[j][r] = 0.0f;

#pragma unroll
        for (int t = 0; t < 8; t++) {
            const int d0 = t * 16;
            uint32_t ah[4], al[4];
            uint32_t aoff = a_row * F_ROWB + (d0 + lhalf) * 2;
            ldm_x4(ah, sQh + aoff);
            ldm_x4(al, sQl + aoff);
#pragma unroll
            for (int p = 0; p < 4; p++) {
                uint32_t bh[4], bl[4];
                uint32_t boff = (p * 16 + (lane & 15)) * F_ROWB + (d0 + lhalf) * 2;
                ldm_x4(bh, sKh + boff);
                ldm_x4(bl, sKl + boff);
                uint32_t b0h[2] = { bh[0], bh[2] }, b1h[2] = { bh[1], bh[3] };
                uint32_t b0l[2] = { bl[0], bl[2] }, b1l[2] = { bl[1], bl[3] };
                mma16816(s[2*p],   ah, b0h);
                mma16816(s[2*p],   ah, b0l);
                mma16816(s[2*p],   al, b0h);
                mma16816(s[2*p+1], ah, b1h);
                mma16816(s[2*p+1], ah, b1l);
                mma16816(s[2*p+1], al, b1h);
            }
        }

#pragma unroll
        for (int j = 0; j < 8; j++)
#pragma unroll
            for (int r = 0; r < 4; r++) s[j][r] *= scale;

        float mx0 = -1e30f, mx1 = -1e30f;
#pragma unroll
        for (int j = 0; j < 8; j++) {
            mx0 = fmaxf(mx0, fmaxf(s[j][0], s[j][1]));
            mx1 = fmaxf(mx1, fmaxf(s[j][2], s[j][3]));
        }
        mx0 = fmaxf(mx0, __shfl_xor_sync(0xffffffffu, mx0, 1));
        mx0 = fmaxf(mx0, __shfl_xor_sync(0xffffffffu, mx0, 2));
        mx1 = fmaxf(mx1, __shfl_xor_sync(0xffffffffu, mx1, 1));
        mx1 = fmaxf(mx1, __shfl_xor_sync(0xffffffffu, mx1, 2));

        float mn0 = fmaxf(s_m[0], mx0), mn1 = fmaxf(s_m[1], mx1);
        float al0 = __expf(s_m[0] - mn0), al1 = __expf(s_m[1] - mn1);
        s_m[0] = mn0; s_m[1] = mn1;

        float rs0 = 0.0f, rs1 = 0.0f;
#pragma unroll
        for (int j = 0; j < 8; j++) {
            s[j][0] = __expf(s[j][0] - mn0);
            s[j][1] = __expf(s[j][1] - mn0);
            s[j][2] = __expf(s[j][2] - mn1);
            s[j][3] = __expf(s[j][3] - mn1);
            rs0 += s[j][0] + s[j][1];
            rs1 += s[j][2] + s[j][3];
        }
        rs0 += __shfl_xor_sync(0xffffffffu, rs0, 1);
        rs0 += __shfl_xor_sync(0xffffffffu, rs0, 2);
        rs1 += __shfl_xor_sync(0xffffffffu, rs1, 1);
        rs1 += __shfl_xor_sync(0xffffffffu, rs1, 2);
        s_l[0] = s_l[0] * al0 + rs0;
        s_l[1] = s_l[1] * al1 + rs1;

#pragma unroll
        for (int nt = 0; nt < 16; nt++) {
            o[nt][0] *= al0; o[nt][1] *= al0;
            o[nt][2] *= al1; o[nt][3] *= al1;
        }

        uint32_t ph[4][4], pl[4][4];
#pragma unroll
        for (int t = 0; t < 4; t++) {
#pragma unroll
            for (int q = 0; q < 4; q++) {
                int j = 2 * t + (q >> 1);
                int cc = (q & 1) * 2;
                float v0 = s[j][cc], v1 = s[j][cc + 1];
                __nv_bfloat16 h0, h1; float r0, r1;
                split1(v0, h0, r0);
                split1(v1, h1, r1);
                __nv_bfloat162 hp; hp.x = h0; hp.y = h1;
                ph[t][q] = *(uint32_t*)&hp;
                pl[t][q] = pack_bf2(r0, r1);
            }
        }

#pragma unroll
        for (int t = 0; t < 4; t++) {
#pragma unroll
            for (int np = 0; np < 8; np++) {
                uint32_t vh[4], vl[4];
                uint32_t voff = (t * 16 + (lane & 15)) * F_ROWB + (np * 16 + lhalf) * 2;
                ldm_x4t(vh, sVh + voff);
                ldm_x4t(vl, sVl + voff);
                uint32_t b0h[2] = { vh[0], vh[1] }, b1h[2] = { vh[2], vh[3] };
                uint32_t b0l[2] = { vl[0], vl[1] }, b1l[2] = { vl[2], vl[3] };
                mma16816(o[2*np],   ph[t], b0h);
                mma16816(o[2*np],   ph[t], b0l);
                mma16816(o[2*np],   pl[t], b0h);
                mma16816(o[2*np+1], ph[t], b1h);
                mma16816(o[2*np+1], ph[t], b1l);
                mma16816(o[2*np+1], pl[t], b1h);
            }
        }
        __syncthreads();
    }

    // epilogue: normalize, split, store into paired-tile layout
    float inv0 = 1.0f / s_l[0];
    float inv1 = 1.0f / s_l[1];
    int row0g = b * S_LEN + mblk * 64 + m0 + lr;
    int row1g = row0g + 8;
#pragma unroll
    for (int nt = 0; nt < 16; nt++) {
        int col = h * HDIM + nt * 8 + lc * 2;
        size_t o0 = pair_off(row0g, col, INNER);
        size_t o1 = pair_off(row1g, col, INNER);
        float a0 = o[nt][0] * inv0, a1 = o[nt][1] * inv0;
        float b0 = o[nt][2] * inv1, b1 = o[nt][3] * inv1;
        __nv_bfloat16 h00, h01, h10, h11; float l00, l01, l10, l11;
        split1(a0, h00, l00); split1(a1, h01, l01);
        split1(b0, h10, l10); split1(b1, h11, l11);
        __nv_bfloat162 hp0; hp0.x = h00; hp0.y = h01;
        __nv_bfloat162 hp1; hp1.x = h10; hp1.y = h11;
        *(uint32_t*)(Ot + o0) = *(uint32_t*)&hp0;
        *(uint32_t*)(Ot + o1) = *(uint32_t*)&hp1;
        *(uint32_t*)(Ot + o0 + 4096) = pack_bf2(l00, l01);
        *(uint32_t*)(Ot + o1 + 4096) = pack_bf2(l10, l11);
    }
}

// ---------------------------------------------------------------------------
// fp32 -> bf16 hi/lo split, writing paired-tile layout
// ---------------------------------------------------------------------------
__global__ void split_kernel(const float4* __restrict__ in,
                             __nv_bfloat16* __restrict__ T, int n4, int K) {
    int i = blockIdx.x * blockDim.x + threadIdx.x;
    if (i >= n4) return;
    float4 v = in[i];
    float f[4] = { v.x, v.y, v.z, v.w };
    __nv_bfloat16 h[4]; float l[4];
#pragma unroll
    for (int j = 0; j < 4; j++) split1(f[j], h[j], l[j]);
    int rg = (i * 4) / K;
    int k0 = (i * 4) % K;
    size_t o = pair_off(rg, k0, K);
    *(uint2*)(T + o) = *(uint2*)h;
    uint2 lp; lp.x = pack_bf2(l[0], l[1]); lp.y = pack_bf2(l[2], l[3]);
    *(uint2*)(T + o + 4096) = lp;
}

// ---------------------------------------------------------------------------
// Transpose + split: W[K, N] fp32 -> paired-tile T[N, K]
// ---------------------------------------------------------------------------
__global__ void transpose_split_kernel(const float* __restrict__ W,
                                       __nv_bfloat16* __restrict__ T) {
    __shared__ float t[32][33];
    int n0 = blockIdx.x * 32, k0 = blockIdx.y * 32;
#pragma unroll
    for (int i = 0; i < 32; i += 8)
        t[threadIdx.y + i][threadIdx.x] =
            W[(size_t)(k0 + threadIdx.y + i) * 2048 + n0 + threadIdx.x];
    __syncthreads();
#pragma unroll
    for (int i = 0; i < 32; i += 8) {
        float v = t[threadIdx.x][threadIdx.y + i];
        __nv_bfloat16 h; float l;
        split1(v, h, l);
        size_t o = pair_off(n0 + threadIdx.y + i, k0 + threadIdx.x, 2048);
        T[o] = h;
        T[o + 4096] = __float2bfloat16(l);
    }
}

// ---------------------------------------------------------------------------
// Launcher (ncu capture slot = launch index 5 -> V GEMM)
// ---------------------------------------------------------------------------
extern "C" void kernel_launch(void* const* d_in, const int* in_sizes, int n_in,
                              void* d_out, int out_size) {
    const float* x  = (const float*)d_in[0];
    const float* Wq = (const float*)d_in[1];
    const float* Wk = (const float*)d_in[2];
    const float* Wv = (const float*)d_in[3];
    const float* Wo = (const float*)d_in[4];
    const float* qg = (const float*)d_in[5];
    const float* kg = (const float*)d_in[6];
    float* out = (float*)d_out;

    __nv_bfloat16 *xt, *wt, *aot;
    __nv_bfloat16 *qhi, *qlo, *khi, *klo, *vhi, *vlo;
    cudaGetSymbolAddress((void**)&xt,  g_xt);
    cudaGetSymbolAddress((void**)&wt,  g_wt);
    cudaGetSymbolAddress((void**)&aot, g_aot);
    cudaGetSymbolAddress((void**)&qhi, g_qhi);
    cudaGetSymbolAddress((void**)&qlo, g_qlo);
    cudaGetSymbolAddress((void**)&khi, g_khi);
    cudaGetSymbolAddress((void**)&klo, g_klo);
    cudaGetSymbolAddress((void**)&vhi, g_vhi);
    cudaGetSymbolAddress((void**)&vlo, g_vlo);
    const size_t WSZ = (size_t)2 * DMODEL * INNER;

    cudaFuncSetAttribute(gemm_mma_kernel<0>, cudaFuncAttributeMaxDynamicSharedMemorySize, GEMM_SMEM);
    cudaFuncSetAttribute(gemm_mma_kernel<1>, cudaFuncAttributeMaxDynamicSharedMemorySize, GEMM_SMEM);
    cudaFuncSetAttribute(gemm_mma_kernel<2>, cudaFuncAttributeMaxDynamicSharedMemorySize, GEMM_SMEM);
    cudaFuncSetAttribute(flash_mma_kernel, cudaFuncAttributeMaxDynamicSharedMemorySize, FLASH_SMEM);

    dim3 tb(32, 8), tg(64, 64);
    dim3 gg(INNER / G_BN, ROWS / G_BM);   // (16, 32) -> 512 CTAs
    dim3 gridF(S_LEN / 64, NHEAD, BATCH);

    // launch 0: split x (paired tiles)
    int n4x = ROWS * DMODEL / 4;
    split_kernel<<<n4x / 256, 256>>>((const float4*)x, xt, n4x, DMODEL);
    // launches 1-4: transpose Wq, Wk, Wv, Wo (paired tiles)
    transpose_split_kernel<<<tg, tb>>>(Wq, wt + 0*WSZ);
    transpose_split_kernel<<<tg, tb>>>(Wk, wt + 1*WSZ);
    transpose_split_kernel<<<tg, tb>>>(Wv, wt + 2*WSZ);
    transpose_split_kernel<<<tg, tb>>>(Wo, wt + 3*WSZ);
    // launch 5 (ncu capture slot): V projection
    gemm_mma_kernel<1><<<gg, 128, GEMM_SMEM>>>(xt, wt + 2*WSZ,
                                               nullptr, vhi, vlo, nullptr,
                                               ROWS, INNER, DMODEL);
    // launches 6-7: Q, K projections with fused RMSNorm
    gemm_mma_kernel<2><<<gg, 128, GEMM_SMEM>>>(xt, wt + 0*WSZ,
                                               nullptr, qhi, qlo, qg,
                                               ROWS, INNER, DMODEL);
    gemm_mma_kernel<2><<<gg, 128, GEMM_SMEM>>>(xt, wt + 1*WSZ,
                                               nullptr, khi, klo, kg,
                                               ROWS, INNER, DMODEL);
    // launch 8: flash attention (epilogue writes paired-tile ao)
    flash_mma_kernel<<<gridF, 128, FLASH_SMEM>>>(qhi, qlo, khi, klo, vhi, vlo,
                                                 aot);
    // launch 9: output projection
    gemm_mma_kernel<0><<<gg, 128, GEMM_SMEM>>>(aot, wt + 3*WSZ,
                                               out, nullptr, nullptr, nullptr,
                                               ROWS, DMODEL, INNER);
}

// round 14
// speedup vs baseline: 1.6668x; 1.1753x over previous
#include <cuda_runtime.h>
#include <cuda_fp16.h>
#include <stdint.h>
#include <math.h>

// Problem constants
#define S_LEN   2048
#define BATCH   2
#define NHEAD   16
#define HDIM    128
#define DMODEL  2048
#define INNER   2048          // NHEAD*HDIM
#define ROWS    (BATCH*S_LEN) // 4096

// Scratch (allocation forbidden -> __device__ globals)
// x / ao: paired-tile fp16 [hi 8KB][lo 8KB] per (128row x 32col) chunk.
// Wq,Wk: paired-tile fp16.  Wv,Wo: single-tile fp16 (2-term GEMMs).
// q/k hi+lo and v hi: row-major [ROWS, INNER] fp16 for the flash kernel.
__device__ __align__(1024) __half g_xt[(size_t)2 * ROWS * DMODEL];
__device__ __align__(1024) __half g_wqk[2][(size_t)2 * DMODEL * INNER];
__device__ __align__(1024) __half g_wvo[2][(size_t)DMODEL * INNER];
__device__ __align__(1024) __half g_aot[(size_t)2 * ROWS * INNER];
__device__ __align__(1024) __half g_qhi[(size_t)ROWS * INNER];
__device__ __align__(1024) __half g_qlo[(size_t)ROWS * INNER];
__device__ __align__(1024) __half g_khi[(size_t)ROWS * INNER];
__device__ __align__(1024) __half g_klo[(size_t)ROWS * INNER];
__device__ __align__(1024) __half g_vhi[(size_t)ROWS * INNER];

// ---------------------------------------------------------------------------
// Tiled layouts (element offsets in fp16 units).
// Tile = 128 rows x 32 cols, in-tile swizzle: elem (rl,kl) at
//   rl*32 + ((ch ^ ((rl>>1)&3))<<3) + w,  ch=kl>>3, w=kl&7.
// pair layout: [hi 4096][lo 4096] per chunk (16KB); single: 4096 elems (8KB).
// ---------------------------------------------------------------------------
__device__ __forceinline__ size_t pair_off(int rg, int k, int K) {
    int rb = rg >> 7, rl = rg & 127, c = k >> 5, kl = k & 31;
    int ch = kl >> 3, w = kl & 7;
    return ((size_t)(rb * (K >> 5) + c) << 13) + rl * 32 +
           (((ch ^ ((rl >> 1) & 3)) << 3) + w);
}
__device__ __forceinline__ size_t single_off(int rg, int k, int K) {
    int rb = rg >> 7, rl = rg & 127, c = k >> 5, kl = k & 31;
    int ch = kl >> 3, w = kl & 7;
    return ((size_t)(rb * (K >> 5) + c) << 12) + rl * 32 +
           (((ch ^ ((rl >> 1) & 3)) << 3) + w);
}

// ---------------------------------------------------------------------------
// PTX helpers
// ---------------------------------------------------------------------------
__device__ __forceinline__ uint32_t smem_u32(const void* p) {
    uint32_t a;
    asm("{ .reg .u64 t; cvta.to.shared.u64 t, %1; cvt.u32.u64 %0, t; }"
        : "=r"(a) : "l"(p));
    return a;
}
__device__ __forceinline__ void cp16(uint32_t dst, const void* src) {
    asm volatile("cp.async.cg.shared.global [%0], [%1], 16;" :: "r"(dst), "l"(src));
}
__device__ __forceinline__ void cp_commit() { asm volatile("cp.async.commit_group;"); }
template<int N> __device__ __forceinline__ void cp_wait() {
    asm volatile("cp.async.wait_group %0;" :: "n"(N));
}
__device__ __forceinline__ void bulkcp(uint32_t dst, const void* src,
                                       uint32_t bytes, uint32_t mbar) {
    asm volatile(
        "cp.async.bulk.shared::cluster.global.mbarrier::complete_tx::bytes "
        "[%0], [%1], %2, [%3];"
        :: "r"(dst), "l"(src), "r"(bytes), "r"(mbar) : "memory");
}
__device__ __forceinline__ void mbar_init(uint32_t a, uint32_t c) {
    asm volatile("mbarrier.init.shared.b64 [%0], %1;" :: "r"(a), "r"(c) : "memory");
}
__device__ __forceinline__ void mbar_expect(uint32_t mbar, uint32_t bytes) {
    asm volatile("mbarrier.arrive.expect_tx.shared.b64 _, [%0], %1;"
                 :: "r"(mbar), "r"(bytes) : "memory");
}
__device__ __forceinline__ void mbar_wait(uint32_t mbar, uint32_t parity) {
    asm volatile(
        "{\n\t.reg .pred P;\n\t"
        "WL_%=:\n\t"
        "mbarrier.try_wait.parity.shared.b64 P, [%0], %1;\n\t"
        "@P bra.uni WD_%=;\n\t"
        "bra.uni WL_%=;\n\t"
        "WD_%=:\n\t}"
        :: "r"(mbar), "r"(parity) : "memory");
}
__device__ __forceinline__ void fence_async() {
    asm volatile("fence.proxy.async.shared::cta;" ::: "memory");
}
__device__ __forceinline__ void ldm_x4(uint32_t* r, uint32_t addr) {
    asm volatile("ldmatrix.sync.aligned.m8n8.x4.shared.b16 {%0,%1,%2,%3}, [%4];"
                 : "=r"(r[0]), "=r"(r[1]), "=r"(r[2]), "=r"(r[3]) : "r"(addr));
}
__device__ __forceinline__ void ldm_x4t(uint32_t* r, uint32_t addr) {
    asm volatile("ldmatrix.sync.aligned.m8n8.x4.trans.shared.b16 {%0,%1,%2,%3}, [%4];"
                 : "=r"(r[0]), "=r"(r[1]), "=r"(r[2]), "=r"(r[3]) : "r"(addr));
}
__device__ __forceinline__ void mma16816(float* c, const uint32_t* a, const uint32_t* b) {
    asm volatile(
        "mma.sync.aligned.m16n8k16.row.col.f32.f16.f16.f32 "
        "{%0,%1,%2,%3}, {%4,%5,%6,%7}, {%8,%9}, {%0,%1,%2,%3};"
        : "+f"(c[0]), "+f"(c[1]), "+f"(c[2]), "+f"(c[3])
        : "r"(a[0]), "r"(a[1]), "r"(a[2]), "r"(a[3]), "r"(b[0]), "r"(b[1]));
}
__device__ __forceinline__ uint32_t pack_h2(float a, float b) {
    __half2 t = __floats2half2_rn(a, b);
    return *(uint32_t*)&t;
}
__device__ __forceinline__ void split1(float v, __half& h, float& r) {
    h = __float2half_rn(v);
    r = v - __half2float(h);
}

// ---------------------------------------------------------------------------
// fp16 split GEMM with paired-tile cp.async.bulk loads.
// NT=3: C = Ah*Bh + Ah*Bl + Al*Bh (B paired).  NT=2: C = Ah*Bh + Al*Bh (B single).
// CTA 128x128, BK=32, 128 threads (4 warps, warp tile 64x64), 3-stage
// pipeline, occupancy 2.
// MODE 0: fp32 C.  MODE 1: fp16 hi C.  MODE 2: RMSNorm + fp16 hi/lo C.
// ---------------------------------------------------------------------------
#define G_BM 128
#define G_BN 128
#define A_TB 8192
#define PAIRB 16384
#define NSTAGE 3

template<int MODE, int NT>
__global__ __launch_bounds__(128, 2)
void gemm_mma_kernel(const __half* __restrict__ A,   // paired tiles
                     const __half* __restrict__ B,   // paired (NT3) / single (NT2)
                     float* __restrict__ C,
                     __half* __restrict__ Chi,
                     __half* __restrict__ Clo,
                     const float* __restrict__ gamma,
                     int M, int N, int K)
{
    constexpr int STAGEB = (NT == 3) ? 32768 : 24576;
    extern __shared__ char smem[];
    const uint32_t sbase = smem_u32(smem);
    const uint32_t mbar0 = sbase + NSTAGE * STAGEB;
    const int tid  = threadIdx.x;
    const int warp = tid >> 5;
    const int lane = tid & 31;
    const int wm = warp >> 1;
    const int wn = warp & 1;

    const int rowblk = blockIdx.y;
    const int colblk = blockIdx.x;
    const int row0 = rowblk * G_BM;
    const int col0 = colblk * G_BN;
    const int KC = K >> 5;

    if (tid == 0) {
#pragma unroll
        for (int s = 0; s < NSTAGE; s++) mbar_init(mbar0 + s * 8, 1);
        fence_async();
    }
    __syncthreads();

    float acc[4][8][4];
#pragma unroll
    for (int mt = 0; mt < 4; mt++)
#pragma unroll
        for (int nt = 0; nt < 8; nt++)
#pragma unroll
            for (int r = 0; r < 4; r++) acc[mt][nt][r] = 0.0f;

    auto issue = [&](int c, int s) {
        uint32_t stb = sbase + s * STAGEB;
        uint32_t mb = mbar0 + s * 8;
        const char* ap = (const char*)A + (((size_t)(rowblk * KC + c)) << 14);
        mbar_expect(mb, STAGEB);
        bulkcp(stb, ap, PAIRB, mb);
        if (NT == 3) {
            const char* bp = (const char*)B + (((size_t)(colblk * KC + c)) << 14);
            bulkcp(stb + PAIRB, bp, PAIRB, mb);
        } else {
            const char* bp = (const char*)B + (((size_t)(colblk * KC + c)) << 13);
            bulkcp(stb + PAIRB, bp, A_TB, mb);
        }
    };

    if (tid == 0) { issue(0, 0); issue(1, 1); }

    const int arow_l = (lane & 15);
    const int brow_l = (lane & 7) + 8 * (lane >> 4);
    const int a_chl  = lane >> 4;
    const int b_chl  = (lane >> 3) & 1;

    for (int c = 0; c < KC; ++c) {
        const int s = c % NSTAGE;
        if (tid == 0 && c + 2 < KC) issue(c + 2, (c + 2) % NSTAGE);
        mbar_wait(mbar0 + s * 8, (c / NSTAGE) & 1);

        const uint32_t sA  = sbase + s * STAGEB;
        const uint32_t sAl = sA + A_TB;
        const uint32_t sB  = sA + PAIRB;
        const uint32_t sBl = sB + A_TB;   // NT3 only
#pragma unroll
        for (int ks = 0; ks < 2; ks++) {
            uint32_t ah[4][4], al[4][4];
#pragma unroll
            for (int mt = 0; mt < 4; mt++) {
                int arow = wm * 64 + mt * 16 + arow_l;
                int ch = (2 * ks + a_chl) ^ ((arow >> 1) & 3);
                uint32_t aoff = arow * 64 + ch * 16;
                ldm_x4(ah[mt], sA  + aoff);
                ldm_x4(al[mt], sAl + aoff);
            }
            uint32_t bh[8][2], bl[8][2];
#pragma unroll
            for (int p = 0; p < 4; p++) {
                int brow = wn * 64 + p * 16 + brow_l;
                int ch = (2 * ks + b_chl) ^ ((brow >> 1) & 3);
                uint32_t boff = brow * 64 + ch * 16;
                uint32_t t0[4];
                ldm_x4(t0, sB + boff);
                bh[2*p][0]   = t0[0]; bh[2*p][1]   = t0[1];
                bh[2*p+1][0] = t0[2]; bh[2*p+1][1] = t0[3];
                if (NT == 3) {
                    uint32_t t1[4];
                    ldm_x4(t1, sBl + boff);
                    bl[2*p][0]   = t1[0]; bl[2*p][1]   = t1[1];
                    bl[2*p+1][0] = t1[2]; bl[2*p+1][1] = t1[3];
                }
            }
#pragma unroll
            for (int mt = 0; mt < 4; mt++)
#pragma unroll
                for (int nt = 0; nt < 8; nt++) {
                    mma16816(acc[mt][nt], ah[mt], bh[nt]);
                    mma16816(acc[mt][nt], al[mt], bh[nt]);
                    if (NT == 3) mma16816(acc[mt][nt], ah[mt], bl[nt]);
                }
        }
        __syncthreads();
    }

    if (MODE == 0) {
#pragma unroll
        for (int mt = 0; mt < 4; mt++) {
            int r0 = row0 + wm * 64 + mt * 16 + (lane >> 2);
#pragma unroll
            for (int nt = 0; nt < 8; nt++) {
                int cc = col0 + wn * 64 + nt * 8 + (lane & 3) * 2;
                *(float2*)(C + (size_t)r0 * N + cc) =
                    make_float2(acc[mt][nt][0], acc[mt][nt][1]);
                *(float2*)(C + (size_t)(r0 + 8) * N + cc) =
                    make_float2(acc[mt][nt][2], acc[mt][nt][3]);
            }
        }
    } else if (MODE == 1) {
        // row-major fp16 hi output only (V for flash)
#pragma unroll
        for (int mt = 0; mt < 4; mt++) {
            int r0 = row0 + wm * 64 + mt * 16 + (lane >> 2);
#pragma unroll
            for (int nt = 0; nt < 8; nt++) {
                int cc = col0 + wn * 64 + nt * 8 + (lane & 3) * 2;
                *(uint32_t*)(Chi + (size_t)r0 * N + cc) =
                    pack_h2(acc[mt][nt][0], acc[mt][nt][1]);
                *(uint32_t*)(Chi + (size_t)(r0 + 8) * N + cc) =
                    pack_h2(acc[mt][nt][2], acc[mt][nt][3]);
            }
        }
    } else {
        // MODE 2: per-row (=head) RMSNorm + fp16 hi/lo split, row-major
        float* CS = (float*)smem;      // 128 x 132 fp32 = 67584 B
        float4 g4 = *(const float4*)(gamma + lane * 4);
#pragma unroll
        for (int mt = 0; mt < 4; mt++) {
            int r = wm * 64 + mt * 16 + (lane >> 2);
#pragma unroll
            for (int nt = 0; nt < 8; nt++) {
                int cc = wn * 64 + nt * 8 + (lane & 3) * 2;
                CS[r * 132 + cc]         = acc[mt][nt][0];
                CS[r * 132 + cc + 1]     = acc[mt][nt][1];
                CS[(r+8) * 132 + cc]     = acc[mt][nt][2];
                CS[(r+8) * 132 + cc + 1] = acc[mt][nt][3];
            }
        }
        __syncthreads();
#pragma unroll
        for (int rr = 0; rr < 32; rr++) {
            int row = warp * 32 + rr;
            float4 v = *(float4*)&CS[row * 132 + lane * 4];
            float ss = v.x*v.x + v.y*v.y + v.z*v.z + v.w*v.w;
#pragma unroll
            for (int o = 16; o > 0; o >>= 1)
                ss += __shfl_xor_sync(0xffffffffu, ss, o);
            float rn = rsqrtf(ss * (1.0f / 128.0f) + 1e-6f);
            float f[4] = { v.x*rn*g4.x, v.y*rn*g4.y, v.z*rn*g4.z, v.w*rn*g4.w };
            __half h[4]; float l[4];
#pragma unroll
            for (int j = 0; j < 4; j++) split1(f[j], h[j], l[j]);
            size_t o = (size_t)(row0 + row) * N + col0 + lane * 4;
            *(uint2*)(Chi + o) = *(uint2*)h;
            uint2 lp; lp.x = pack_h2(l[0], l[1]); lp.y = pack_h2(l[2], l[3]);
            *(uint2*)(Clo + o) = lp;
        }
    }
}
#define GEMM_SMEM3 (NSTAGE * 32768 + 64)
#define GEMM_SMEM2 (NSTAGE * 24576 + 64)

// ---------------------------------------------------------------------------
// Flash attention: S = 3-term (Q split x K split), PV = 2-term (P split x Vh).
// 64x64 tile, 128 thr, occ 2. smem: Qh Ql Kh Kl Vh (5 tiles).
// Epilogue writes ao into paired-tile fp16 layout.
// ---------------------------------------------------------------------------
#define F_ROWB 272
#define FT_BYTES (64 * F_ROWB)
#define FLASH_SMEM (5 * FT_BYTES)   // 87040

__global__ __launch_bounds__(128, 2)
void flash_mma_kernel(const __half* __restrict__ Qhi,
                      const __half* __restrict__ Qlo,
                      const __half* __restrict__ Khi,
                      const __half* __restrict__ Klo,
                      const __half* __restrict__ Vhi,
                      __half* __restrict__ Ot)
{
    extern __shared__ char sm_raw[];
    const uint32_t sb = smem_u32(sm_raw);
    const uint32_t sQh = sb,                sQl = sb + FT_BYTES;
    const uint32_t sKh = sb + 2*FT_BYTES,   sKl = sb + 3*FT_BYTES;
    const uint32_t sVh = sb + 4*FT_BYTES;

    const int tid  = threadIdx.x;
    const int warp = tid >> 5;
    const int lane = tid & 31;
    const int lr   = lane >> 2;
    const int lc   = lane & 3;
    const int m0   = warp * 16;

    const int mblk = blockIdx.x, h = blockIdx.y, b = blockIdx.z;
    const size_t qoff = ((size_t)(b * S_LEN + mblk * 64)) * INNER + h * HDIM;
    const size_t koff = ((size_t)(b * S_LEN)) * INNER + h * HDIM;

#pragma unroll
    for (int i = 0; i < 8; i++) {
        int idx = i * 128 + tid;
        int r = idx >> 4, s = idx & 15;
        uint32_t so = r * F_ROWB + s * 16;
        const size_t go = qoff + (size_t)r * INNER + s * 8;
        cp16(sQh + so, Qhi + go);
        cp16(sQl + so, Qlo + go);
    }
    cp_commit();

    float o[16][4];
#pragma unroll
    for (int nt = 0; nt < 16; nt++)
#pragma unroll
        for (int r = 0; r < 4; r++) o[nt][r] = 0.0f;
    float s_m[2] = { -1e30f, -1e30f };
    float s_l[2] = { 0.0f, 0.0f };
    const float scale = 0.08838834764831845f;

    const uint32_t a_row = m0 + (lane & 15);
    const uint32_t lhalf = 8 * (lane >> 4);

    for (int n0 = 0; n0 < S_LEN; n0 += 64) {
#pragma unroll
        for (int i = 0; i < 8; i++) {
            int idx = i * 128 + tid;
            int r = idx >> 4, s = idx & 15;
            uint32_t so = r * F_ROWB + s * 16;
            const size_t go = koff + (size_t)(n0 + r) * INNER + s * 8;
            cp16(sKh + so, Khi + go);
            cp16(sKl + so, Klo + go);
            cp16(sVh + so, Vhi + go);
        }
        cp_commit();
        cp_wait<0>();
        __syncthreads();

        // ---- S = Q @ K^T (3-term: qh*kh + qh*kl + ql*kh) ----
        float s[8][4];
#pragma unroll
        for (int j = 0; j < 8; j++)
#pragma unroll
            for (int r = 0; r < 4; r++) s[j][r] = 0.0f;

#pragma unroll
        for (int t = 0; t < 8; t++) {
            const int d0 = t * 16;
            uint32_t ah[4], al[4];
            uint32_t aoff = a_row * F_ROWB + (d0 + lhalf) * 2;
            ldm_x4(ah, sQh + aoff);
            ldm_x4(al, sQl + aoff);
#pragma unroll
            for (int p = 0; p < 4; p++) {
                uint32_t bh[4], bl[4];
                uint32_t boff = (p * 16 + (lane & 15)) * F_ROWB + (d0 + lhalf) * 2;
                ldm_x4(bh, sKh + boff);
                ldm_x4(bl, sKl + boff);
                uint32_t b0h[2] = { bh[0], bh[2] }, b1h[2] = { bh[1], bh[3] };
                uint32_t b0l[2] = { bl[0], bl[2] }, b1l[2] = { bl[1], bl[3] };
                mma16816(s[2*p],   ah, b0h);
                mma16816(s[2*p],   ah, b0l);
                mma16816(s[2*p],   al, b0h);
                mma16816(s[2*p+1], ah, b1h);
                mma16816(s[2*p+1], ah, b1l);
                mma16816(s[2*p+1], al, b1h);
            }
        }

        // ---- online softmax ----
#pragma unroll
        for (int j = 0; j < 8; j++)
#pragma unroll
            for (int r = 0; r < 4; r++) s[j][r] *= scale;

        float mx0 = -1e30f, mx1 = -1e30f;
#pragma unroll
        for (int j = 0; j < 8; j++) {
            mx0 = fmaxf(mx0, fmaxf(s[j][0], s[j][1]));
            mx1 = fmaxf(mx1, fmaxf(s[j][2], s[j][3]));
        }
        mx0 = fmaxf(mx0, __shfl_xor_sync(0xffffffffu, mx0, 1));
        mx0 = fmaxf(mx0, __shfl_xor_sync(0xffffffffu, mx0, 2));
        mx1 = fmaxf(mx1, __shfl_xor_sync(0xffffffffu, mx1, 1));
        mx1 = fmaxf(mx1, __shfl_xor_sync(0xffffffffu, mx1, 2));

        float mn0 = fmaxf(s_m[0], mx0), mn1 = fmaxf(s_m[1], mx1);
        float al0 = __expf(s_m[0] - mn0), al1 = __expf(s_m[1] - mn1);
        s_m[0] = mn0; s_m[1] = mn1;

        float rs0 = 0.0f, rs1 = 0.0f;
#pragma unroll
        for (int j = 0; j < 8; j++) {
            s[j][0] = __expf(s[j][0] - mn0);
            s[j][1] = __expf(s[j][1] - mn0);
            s[j][2] = __expf(s[j][2] - mn1);
            s[j][3] = __expf(s[j][3] - mn1);
            rs0 += s[j][0] + s[j][1];
            rs1 += s[j][2] + s[j][3];
        }
        rs0 += __shfl_xor_sync(0xffffffffu, rs0, 1);
        rs0 += __shfl_xor_sync(0xffffffffu, rs0, 2);
        rs1 += __shfl_xor_sync(0xffffffffu, rs1, 1);
        rs1 += __shfl_xor_sync(0xffffffffu, rs1, 2);
        s_l[0] = s_l[0] * al0 + rs0;
        s_l[1] = s_l[1] * al1 + rs1;

#pragma unroll
        for (int nt = 0; nt < 16; nt++) {
            o[nt][0] *= al0; o[nt][1] *= al0;
            o[nt][2] *= al1; o[nt][3] *= al1;
        }

        // ---- pack P into fp16 hi/lo A-frags ----
        uint32_t ph[4][4], pl[4][4];
#pragma unroll
        for (int t = 0; t < 4; t++) {
#pragma unroll
            for (int q = 0; q < 4; q++) {
                int j = 2 * t + (q >> 1);
                int cc = (q & 1) * 2;
                float v0 = s[j][cc], v1 = s[j][cc + 1];
                __half h0, h1; float r0, r1;
                split1(v0, h0, r0);
                split1(v1, h1, r1);
                __half2 hp; hp.x = h0; hp.y = h1;
                ph[t][q] = *(uint32_t*)&hp;
                pl[t][q] = pack_h2(r0, r1);
            }
        }

        // ---- O += P @ V (2-term: ph*vh + pl*vh) ----
#pragma unroll
        for (int t = 0; t < 4; t++) {
#pragma unroll
            for (int np = 0; np < 8; np++) {
                uint32_t vh[4];
                uint32_t voff = (t * 16 + (lane & 15)) * F_ROWB + (np * 16 + lhalf) * 2;
                ldm_x4t(vh, sVh + voff);
                uint32_t b0h[2] = { vh[0], vh[1] }, b1h[2] = { vh[2], vh[3] };
                mma16816(o[2*np],   ph[t], b0h);
                mma16816(o[2*np],   pl[t], b0h);
                mma16816(o[2*np+1], ph[t], b1h);
                mma16816(o[2*np+1], pl[t], b1h);
            }
        }
        __syncthreads();
    }

    // epilogue: normalize, fp16-split, store into paired-tile layout
    float inv0 = 1.0f / s_l[0];
    float inv1 = 1.0f / s_l[1];
    int row0g = b * S_LEN + mblk * 64 + m0 + lr;
    int row1g = row0g + 8;
#pragma unroll
    for (int nt = 0; nt < 16; nt++) {
        int col = h * HDIM + nt * 8 + lc * 2;
        size_t o0 = pair_off(row0g, col, INNER);
        size_t o1 = pair_off(row1g, col, INNER);
        float a0 = o[nt][0] * inv0, a1 = o[nt][1] * inv0;
        float b0 = o[nt][2] * inv1, b1 = o[nt][3] * inv1;
        __half h00, h01, h10, h11; float l00, l01, l10, l11;
        split1(a0, h00, l00); split1(a1, h01, l01);
        split1(b0, h10, l10); split1(b1, h11, l11);
        __half2 hp0; hp0.x = h00; hp0.y = h01;
        __half2 hp1; hp1.x = h10; hp1.y = h11;
        *(uint32_t*)(Ot + o0) = *(uint32_t*)&hp0;
        *(uint32_t*)(Ot + o1) = *(uint32_t*)&hp1;
        *(uint32_t*)(Ot + o0 + 4096) = pack_h2(l00, l01);
        *(uint32_t*)(Ot + o1 + 4096) = pack_h2(l10, l11);
    }
}

// ---------------------------------------------------------------------------
// fp32 -> fp16 hi/lo split, writing paired-tile layout (x)
// ---------------------------------------------------------------------------
__global__ void split_kernel(const float4* __restrict__ in,
                             __half* __restrict__ T, int n4, int K) {
    int i = blockIdx.x * blockDim.x + threadIdx.x;
    if (i >= n4) return;
    float4 v = in[i];
    float f[4] = { v.x, v.y, v.z, v.w };
    __half h[4]; float l[4];
#pragma unroll
    for (int j = 0; j < 4; j++) split1(f[j], h[j], l[j]);
    int rg = (i * 4) / K;
    int k0 = (i * 4) % K;
    size_t o = pair_off(rg, k0, K);
    *(uint2*)(T + o) = *(uint2*)h;
    uint2 lp; lp.x = pack_h2(l[0], l[1]); lp.y = pack_h2(l[2], l[3]);
    *(uint2*)(T + o + 4096) = lp;
}

// ---------------------------------------------------------------------------
// Transpose + split: W[K,N] fp32 -> paired-tile fp16 (Wq, Wk)
// ---------------------------------------------------------------------------
__global__ void transpose_split_pair_kernel(const float* __restrict__ W,
                                            __half* __restrict__ T) {
    __shared__ float t[32][33];
    int n0 = blockIdx.x * 32, k0 = blockIdx.y * 32;
#pragma unroll
    for (int i = 0; i < 32; i += 8)
        t[threadIdx.y + i][threadIdx.x] =
            W[(size_t)(k0 + threadIdx.y + i) * 2048 + n0 + threadIdx.x];
    __syncthreads();
#pragma unroll
    for (int i = 0; i < 32; i += 8) {
        float v = t[threadIdx.x][threadIdx.y + i];
        __half h; float l;
        split1(v, h, l);
        size_t o = pair_off(n0 + threadIdx.y + i, k0 + threadIdx.x, 2048);
        T[o] = h;
        T[o + 4096] = __float2half_rn(l);
    }
}

// ---------------------------------------------------------------------------
// Transpose: W[K,N] fp32 -> single-tile fp16 (Wv, Wo)
// ---------------------------------------------------------------------------
__global__ void transpose_single_kernel(const float* __restrict__ W,
                                        __half* __restrict__ T) {
    __shared__ float t[32][33];
    int n0 = blockIdx.x * 32, k0 = blockIdx.y * 32;
#pragma unroll
    for (int i = 0; i < 32; i += 8)
        t[threadIdx.y + i][threadIdx.x] =
            W[(size_t)(k0 + threadIdx.y + i) * 2048 + n0 + threadIdx.x];
    __syncthreads();
#pragma unroll
    for (int i = 0; i < 32; i += 8) {
        float v = t[threadIdx.x][threadIdx.y + i];
        size_t o = single_off(n0 + threadIdx.y + i, k0 + threadIdx.x, 2048);
        T[o] = __float2half_rn(v);
    }
}

// ---------------------------------------------------------------------------
// Launcher (ncu capture slot = launch index 5 -> V GEMM)
// ---------------------------------------------------------------------------
extern "C" void kernel_launch(void* const* d_in, const int* in_sizes, int n_in,
                              void* d_out, int out_size) {
    const float* x  = (const float*)d_in[0];
    const float* Wq = (const float*)d_in[1];
    const float* Wk = (const float*)d_in[2];
    const float* Wv = (const float*)d_in[3];
    const float* Wo = (const float*)d_in[4];
    const float* qg = (const float*)d_in[5];
    const float* kg = (const float*)d_in[6];
    float* out = (float*)d_out;

    __half *xt, *wqk, *wvo, *aot;
    __half *qhi, *qlo, *khi, *klo, *vhi;
    cudaGetSymbolAddress((void**)&xt,  g_xt);
    cudaGetSymbolAddress((void**)&wqk, g_wqk);
    cudaGetSymbolAddress((void**)&wvo, g_wvo);
    cudaGetSymbolAddress((void**)&aot, g_aot);
    cudaGetSymbolAddress((void**)&qhi, g_qhi);
    cudaGetSymbolAddress((void**)&qlo, g_qlo);
    cudaGetSymbolAddress((void**)&khi, g_khi);
    cudaGetSymbolAddress((void**)&klo, g_klo);
    cudaGetSymbolAddress((void**)&vhi, g_vhi);
    const size_t WPSZ = (size_t)2 * DMODEL * INNER;   // paired weight size
    const size_t WSSZ = (size_t)DMODEL * INNER;       // single weight size

    cudaFuncSetAttribute(gemm_mma_kernel<1,2>, cudaFuncAttributeMaxDynamicSharedMemorySize, GEMM_SMEM2);
    cudaFuncSetAttribute(gemm_mma_kernel<0,2>, cudaFuncAttributeMaxDynamicSharedMemorySize, GEMM_SMEM2);
    cudaFuncSetAttribute(gemm_mma_kernel<2,3>, cudaFuncAttributeMaxDynamicSharedMemorySize, GEMM_SMEM3);
    cudaFuncSetAttribute(flash_mma_kernel, cudaFuncAttributeMaxDynamicSharedMemorySize, FLASH_SMEM);

    dim3 tb(32, 8), tg(64, 64);
    dim3 gg(INNER / G_BN, ROWS / G_BM);   // (16, 32)
    dim3 gridF(S_LEN / 64, NHEAD, BATCH);

    // launch 0: split x (paired tiles, fp16)
    int n4x = ROWS * DMODEL / 4;
    split_kernel<<<n4x / 256, 256>>>((const float4*)x, xt, n4x, DMODEL);
    // launches 1-2: Wq, Wk paired
    transpose_split_pair_kernel<<<tg, tb>>>(Wq, wqk + 0*WPSZ);
    transpose_split_pair_kernel<<<tg, tb>>>(Wk, wqk + 1*WPSZ);
    // launches 3-4: Wv, Wo single
    transpose_single_kernel<<<tg, tb>>>(Wv, wvo + 0*WSSZ);
    transpose_single_kernel<<<tg, tb>>>(Wo, wvo + 1*WSSZ);
    // launch 5 (ncu capture slot): V projection (2-term)
    gemm_mma_kernel<1,2><<<gg, 128, GEMM_SMEM2>>>(xt, wvo + 0*WSSZ,
                                                  nullptr, vhi, nullptr, nullptr,
                                                  ROWS, INNER, DMODEL);
    // launches 6-7: Q, K projections (3-term) with fused RMSNorm
    gemm_mma_kernel<2,3><<<gg, 128, GEMM_SMEM3>>>(xt, wqk + 0*WPSZ,
                                                  nullptr, qhi, qlo, qg,
                                                  ROWS, INNER, DMODEL);
    gemm_mma_kernel<2,3><<<gg, 128, GEMM_SMEM3>>>(xt, wqk + 1*WPSZ,
                                                  nullptr, khi, klo, kg,
                                                  ROWS, INNER, DMODEL);
    // launch 8: flash attention (S 3-term, PV 2-term)
    flash_mma_kernel<<<gridF, 128, FLASH_SMEM>>>(qhi, qlo, khi, klo, vhi, aot);
    // launch 9: output projection (2-term)
    gemm_mma_kernel<0,2><<<gg, 128, GEMM_SMEM2>>>(aot, wvo + 1*WSSZ,
                                                  out, nullptr, nullptr, nullptr,
                                                  ROWS, DMODEL, INNER);
}

// round 15
// speedup vs baseline: 3.1930x; 1.9157x over previous
#include <cuda_runtime.h>
#include <cuda_fp16.h>
#include <stdint.h>
#include <math.h>

// Problem constants
#define S_LEN   2048
#define BATCH   2
#define NHEAD   16
#define HDIM    128
#define DMODEL  2048
#define INNER   2048          // NHEAD*HDIM
#define ROWS    (BATCH*S_LEN) // 4096

// Scratch (allocation forbidden -> __device__ globals)
// x / W / ao: single-tile fp16 swizzled layouts (below), 1024B-aligned for
// cp.async.bulk.  q/k/v: row-major [ROWS, INNER] fp16 for the flash kernel.
__device__ __align__(1024) __half g_xt[(size_t)ROWS * DMODEL];
__device__ __align__(1024) __half g_w[4][(size_t)DMODEL * INNER];
__device__ __align__(1024) __half g_aot[(size_t)ROWS * INNER];
__device__ __align__(1024) __half g_q[(size_t)ROWS * INNER];
__device__ __align__(1024) __half g_k[(size_t)ROWS * INNER];
__device__ __align__(1024) __half g_v[(size_t)ROWS * INNER];

// ---------------------------------------------------------------------------
// Single-tile layout (element offsets in fp16 units).
// Tile = 128 rows x 32 cols = 4096 elems (8KB); tile idx = rowblk*(K/32)+chunk.
// In-tile: elem (rl,kl) at rl*32 + ((ch ^ ((rl>>1)&3))<<3) + w,
//   ch = kl>>3, w = kl&7  (XOR swizzle -> conflict-free ldmatrix, 64B rows).
// ---------------------------------------------------------------------------
__device__ __forceinline__ size_t single_off(int rg, int k, int K) {
    int rb = rg >> 7, rl = rg & 127, c = k >> 5, kl = k & 31;
    int ch = kl >> 3, w = kl & 7;
    return ((size_t)(rb * (K >> 5) + c) << 12) + rl * 32 +
           (((ch ^ ((rl >> 1) & 3)) << 3) + w);
}

// ---------------------------------------------------------------------------
// PTX helpers
// ---------------------------------------------------------------------------
__device__ __forceinline__ uint32_t smem_u32(const void* p) {
    uint32_t a;
    asm("{ .reg .u64 t; cvta.to.shared.u64 t, %1; cvt.u32.u64 %0, t; }"
        : "=r"(a) : "l"(p));
    return a;
}
__device__ __forceinline__ void cp16(uint32_t dst, const void* src) {
    asm volatile("cp.async.cg.shared.global [%0], [%1], 16;" :: "r"(dst), "l"(src));
}
__device__ __forceinline__ void cp_commit() { asm volatile("cp.async.commit_group;"); }
template<int N> __device__ __forceinline__ void cp_wait() {
    asm volatile("cp.async.wait_group %0;" :: "n"(N));
}
__device__ __forceinline__ void bulkcp(uint32_t dst, const void* src,
                                       uint32_t bytes, uint32_t mbar) {
    asm volatile(
        "cp.async.bulk.shared::cluster.global.mbarrier::complete_tx::bytes "
        "[%0], [%1], %2, [%3];"
        :: "r"(dst), "l"(src), "r"(bytes), "r"(mbar) : "memory");
}
__device__ __forceinline__ void mbar_init(uint32_t a, uint32_t c) {
    asm volatile("mbarrier.init.shared.b64 [%0], %1;" :: "r"(a), "r"(c) : "memory");
}
__device__ __forceinline__ void mbar_expect(uint32_t mbar, uint32_t bytes) {
    asm volatile("mbarrier.arrive.expect_tx.shared.b64 _, [%0], %1;"
                 :: "r"(mbar), "r"(bytes) : "memory");
}
__device__ __forceinline__ void mbar_wait(uint32_t mbar, uint32_t parity) {
    asm volatile(
        "{\n\t.reg .pred P;\n\t"
        "WL_%=:\n\t"
        "mbarrier.try_wait.parity.shared.b64 P, [%0], %1;\n\t"
        "@P bra.uni WD_%=;\n\t"
        "bra.uni WL_%=;\n\t"
        "WD_%=:\n\t}"
        :: "r"(mbar), "r"(parity) : "memory");
}
__device__ __forceinline__ void fence_async() {
    asm volatile("fence.proxy.async.shared::cta;" ::: "memory");
}
__device__ __forceinline__ void ldm_x4(uint32_t* r, uint32_t addr) {
    asm volatile("ldmatrix.sync.aligned.m8n8.x4.shared.b16 {%0,%1,%2,%3}, [%4];"
                 : "=r"(r[0]), "=r"(r[1]), "=r"(r[2]), "=r"(r[3]) : "r"(addr));
}
__device__ __forceinline__ void ldm_x4t(uint32_t* r, uint32_t addr) {
    asm volatile("ldmatrix.sync.aligned.m8n8.x4.trans.shared.b16 {%0,%1,%2,%3}, [%4];"
                 : "=r"(r[0]), "=r"(r[1]), "=r"(r[2]), "=r"(r[3]) : "r"(addr));
}
__device__ __forceinline__ void mma16816(float* c, const uint32_t* a, const uint32_t* b) {
    asm volatile(
        "mma.sync.aligned.m16n8k16.row.col.f32.f16.f16.f32 "
        "{%0,%1,%2,%3}, {%4,%5,%6,%7}, {%8,%9}, {%0,%1,%2,%3};"
        : "+f"(c[0]), "+f"(c[1]), "+f"(c[2]), "+f"(c[3])
        : "r"(a[0]), "r"(a[1]), "r"(a[2]), "r"(a[3]), "r"(b[0]), "r"(b[1]));
}
__device__ __forceinline__ uint32_t pack_h2(float a, float b) {
    __half2 t = __floats2half2_rn(a, b);
    return *(uint32_t*)&t;
}

// ---------------------------------------------------------------------------
// fp16 GEMM (fp32 accum) with single-tile cp.async.bulk loads.
// CTA 128x128, BK=32, 128 threads (4 warps, warp tile 64x64), 4-stage
// mbarrier pipeline, occupancy 2.
// MODE 0: fp32 C.  MODE 1: fp16 C (row-major).  MODE 2: RMSNorm + fp16 C.
// ---------------------------------------------------------------------------
#define G_BM 128
#define G_BN 128
#define TILB 8192
#define STAGEB (2 * TILB)        // 16384
#define NSTAGE 4
#define GEMM_SMEM 68608          // >= max(4*16384+64, 128*132*4)

template<int MODE>
__global__ __launch_bounds__(128, 2)
void gemm_mma_kernel(const __half* __restrict__ A,   // single tiles
                     const __half* __restrict__ B,   // single tiles
                     float* __restrict__ C,
                     __half* __restrict__ Ch,
                     const float* __restrict__ gamma,
                     int M, int N, int K)
{
    extern __shared__ char smem[];
    const uint32_t sbase = smem_u32(smem);
    const uint32_t mbar0 = sbase + NSTAGE * STAGEB;
    const int tid  = threadIdx.x;
    const int warp = tid >> 5;
    const int lane = tid & 31;
    const int wm = warp >> 1;
    const int wn = warp & 1;

    const int rowblk = blockIdx.y;
    const int colblk = blockIdx.x;
    const int row0 = rowblk * G_BM;
    const int col0 = colblk * G_BN;
    const int KC = K >> 5;

    if (tid == 0) {
#pragma unroll
        for (int s = 0; s < NSTAGE; s++) mbar_init(mbar0 + s * 8, 1);
        fence_async();
    }
    __syncthreads();

    float acc[4][8][4];
#pragma unroll
    for (int mt = 0; mt < 4; mt++)
#pragma unroll
        for (int nt = 0; nt < 8; nt++)
#pragma unroll
            for (int r = 0; r < 4; r++) acc[mt][nt][r] = 0.0f;

    auto issue = [&](int c, int s) {
        uint32_t stb = sbase + s * STAGEB;
        uint32_t mb = mbar0 + s * 8;
        const char* ap = (const char*)A + (((size_t)(rowblk * KC + c)) << 13);
        const char* bp = (const char*)B + (((size_t)(colblk * KC + c)) << 13);
        mbar_expect(mb, STAGEB);
        bulkcp(stb,        ap, TILB, mb);
        bulkcp(stb + TILB, bp, TILB, mb);
    };

    if (tid == 0) { issue(0, 0); issue(1, 1); issue(2, 2); }

    const int arow_l = (lane & 15);
    const int brow_l = (lane & 7) + 8 * (lane >> 4);
    const int a_chl  = lane >> 4;
    const int b_chl  = (lane >> 3) & 1;

    for (int c = 0; c < KC; ++c) {
        const int s = c % NSTAGE;
        if (tid == 0 && c + 3 < KC) issue(c + 3, (c + 3) % NSTAGE);
        mbar_wait(mbar0 + s * 8, (c / NSTAGE) & 1);

        const uint32_t sA = sbase + s * STAGEB;
        const uint32_t sB = sA + TILB;
#pragma unroll
        for (int ks = 0; ks < 2; ks++) {
            uint32_t a[4][4];
#pragma unroll
            for (int mt = 0; mt < 4; mt++) {
                int arow = wm * 64 + mt * 16 + arow_l;
                int ch = (2 * ks + a_chl) ^ ((arow >> 1) & 3);
                ldm_x4(a[mt], sA + arow * 64 + ch * 16);
            }
            uint32_t b[8][2];
#pragma unroll
            for (int p = 0; p < 4; p++) {
                int brow = wn * 64 + p * 16 + brow_l;
                int ch = (2 * ks + b_chl) ^ ((brow >> 1) & 3);
                uint32_t t0[4];
                ldm_x4(t0, sB + brow * 64 + ch * 16);
                b[2*p][0]   = t0[0]; b[2*p][1]   = t0[1];
                b[2*p+1][0] = t0[2]; b[2*p+1][1] = t0[3];
            }
#pragma unroll
            for (int mt = 0; mt < 4; mt++)
#pragma unroll
                for (int nt = 0; nt < 8; nt++)
                    mma16816(acc[mt][nt], a[mt], b[nt]);
        }
        __syncthreads();
    }

    if (MODE == 0) {
#pragma unroll
        for (int mt = 0; mt < 4; mt++) {
            int r0 = row0 + wm * 64 + mt * 16 + (lane >> 2);
#pragma unroll
            for (int nt = 0; nt < 8; nt++) {
                int cc = col0 + wn * 64 + nt * 8 + (lane & 3) * 2;
                *(float2*)(C + (size_t)r0 * N + cc) =
                    make_float2(acc[mt][nt][0], acc[mt][nt][1]);
                *(float2*)(C + (size_t)(r0 + 8) * N + cc) =
                    make_float2(acc[mt][nt][2], acc[mt][nt][3]);
            }
        }
    } else if (MODE == 1) {
#pragma unroll
        for (int mt = 0; mt < 4; mt++) {
            int r0 = row0 + wm * 64 + mt * 16 + (lane >> 2);
#pragma unroll
            for (int nt = 0; nt < 8; nt++) {
                int cc = col0 + wn * 64 + nt * 8 + (lane & 3) * 2;
                *(uint32_t*)(Ch + (size_t)r0 * N + cc) =
                    pack_h2(acc[mt][nt][0], acc[mt][nt][1]);
                *(uint32_t*)(Ch + (size_t)(r0 + 8) * N + cc) =
                    pack_h2(acc[mt][nt][2], acc[mt][nt][3]);
            }
        }
    } else {
        // MODE 2: per-row (=head) RMSNorm + fp16 out, row-major
        float* CS = (float*)smem;      // 128 x 132 fp32 (mbar bytes reusable now)
        float4 g4 = *(const float4*)(gamma + lane * 4);
#pragma unroll
        for (int mt = 0; mt < 4; mt++) {
            int r = wm * 64 + mt * 16 + (lane >> 2);
#pragma unroll
            for (int nt = 0; nt < 8; nt++) {
                int cc = wn * 64 + nt * 8 + (lane & 3) * 2;
                CS[r * 132 + cc]         = acc[mt][nt][0];
                CS[r * 132 + cc + 1]     = acc[mt][nt][1];
                CS[(r+8) * 132 + cc]     = acc[mt][nt][2];
                CS[(r+8) * 132 + cc + 1] = acc[mt][nt][3];
            }
        }
        __syncthreads();
#pragma unroll
        for (int rr = 0; rr < 32; rr++) {
            int row = warp * 32 + rr;
            float4 v = *(float4*)&CS[row * 132 + lane * 4];
            float ss = v.x*v.x + v.y*v.y + v.z*v.z + v.w*v.w;
#pragma unroll
            for (int o = 16; o > 0; o >>= 1)
                ss += __shfl_xor_sync(0xffffffffu, ss, o);
            float rn = rsqrtf(ss * (1.0f / 128.0f) + 1e-6f);
            size_t o = (size_t)(row0 + row) * N + col0 + lane * 4;
            uint2 hp;
            hp.x = pack_h2(v.x * rn * g4.x, v.y * rn * g4.y);
            hp.y = pack_h2(v.z * rn * g4.z, v.w * rn * g4.w);
            *(uint2*)(Ch + o) = hp;
        }
    }
}

// ---------------------------------------------------------------------------
// Flash attention, plain fp16 (fp32 accum): S = q@k^T 1-term, O += p@v 1-term.
// 64x64 tile, 128 thr, occ 2. smem: Q, K, V single tiles.
// Epilogue writes ao into single-tile fp16 layout.
// ---------------------------------------------------------------------------
#define F_ROWB 272
#define FT_BYTES (64 * F_ROWB)
#define FLASH_SMEM (3 * FT_BYTES)   // 52224

__global__ __launch_bounds__(128, 2)
void flash_mma_kernel(const __half* __restrict__ Q,
                      const __half* __restrict__ K,
                      const __half* __restrict__ V,
                      __half* __restrict__ Ot)
{
    extern __shared__ char sm_raw[];
    const uint32_t sb = smem_u32(sm_raw);
    const uint32_t sQ = sb;
    const uint32_t sK = sb + FT_BYTES;
    const uint32_t sV = sb + 2 * FT_BYTES;

    const int tid  = threadIdx.x;
    const int warp = tid >> 5;
    const int lane = tid & 31;
    const int lr   = lane >> 2;
    const int lc   = lane & 3;
    const int m0   = warp * 16;

    const int mblk = blockIdx.x, h = blockIdx.y, b = blockIdx.z;
    const size_t qoff = ((size_t)(b * S_LEN + mblk * 64)) * INNER + h * HDIM;
    const size_t koff = ((size_t)(b * S_LEN)) * INNER + h * HDIM;

#pragma unroll
    for (int i = 0; i < 8; i++) {
        int idx = i * 128 + tid;
        int r = idx >> 4, s = idx & 15;
        cp16(sQ + r * F_ROWB + s * 16, Q + qoff + (size_t)r * INNER + s * 8);
    }
    cp_commit();

    float o[16][4];
#pragma unroll
    for (int nt = 0; nt < 16; nt++)
#pragma unroll
        for (int r = 0; r < 4; r++) o[nt][r] = 0.0f;
    float s_m[2] = { -1e30f, -1e30f };
    float s_l[2] = { 0.0f, 0.0f };
    const float scale = 0.08838834764831845f;

    const uint32_t a_row = m0 + (lane & 15);
    const uint32_t lhalf = 8 * (lane >> 4);

    for (int n0 = 0; n0 < S_LEN; n0 += 64) {
#pragma unroll
        for (int i = 0; i < 8; i++) {
            int idx = i * 128 + tid;
            int r = idx >> 4, s = idx & 15;
            uint32_t so = r * F_ROWB + s * 16;
            const size_t go = koff + (size_t)(n0 + r) * INNER + s * 8;
            cp16(sK + so, K + go);
            cp16(sV + so, V + go);
        }
        cp_commit();
        cp_wait<0>();
        __syncthreads();

        // ---- S = Q @ K^T ----
        float s[8][4];
#pragma unroll
        for (int j = 0; j < 8; j++)
#pragma unroll
            for (int r = 0; r < 4; r++) s[j][r] = 0.0f;

#pragma unroll
        for (int t = 0; t < 8; t++) {
            const int d0 = t * 16;
            uint32_t ah[4];
            ldm_x4(ah, sQ + a_row * F_ROWB + (d0 + lhalf) * 2);
#pragma unroll
            for (int p = 0; p < 4; p++) {
                uint32_t bh[4];
                ldm_x4(bh, sK + (p * 16 + (lane & 15)) * F_ROWB + (d0 + lhalf) * 2);
                uint32_t b0h[2] = { bh[0], bh[2] }, b1h[2] = { bh[1], bh[3] };
                mma16816(s[2*p],   ah, b0h);
                mma16816(s[2*p+1], ah, b1h);
            }
        }

        // ---- online softmax ----
#pragma unroll
        for (int j = 0; j < 8; j++)
#pragma unroll
            for (int r = 0; r < 4; r++) s[j][r] *= scale;

        float mx0 = -1e30f, mx1 = -1e30f;
#pragma unroll
        for (int j = 0; j < 8; j++) {
            mx0 = fmaxf(mx0, fmaxf(s[j][0], s[j][1]));
            mx1 = fmaxf(mx1, fmaxf(s[j][2], s[j][3]));
        }
        mx0 = fmaxf(mx0, __shfl_xor_sync(0xffffffffu, mx0, 1));
        mx0 = fmaxf(mx0, __shfl_xor_sync(0xffffffffu, mx0, 2));
        mx1 = fmaxf(mx1, __shfl_xor_sync(0xffffffffu, mx1, 1));
        mx1 = fmaxf(mx1, __shfl_xor_sync(0xffffffffu, mx1, 2));

        float mn0 = fmaxf(s_m[0], mx0), mn1 = fmaxf(s_m[1], mx1);
        float al0 = __expf(s_m[0] - mn0), al1 = __expf(s_m[1] - mn1);
        s_m[0] = mn0; s_m[1] = mn1;

        float rs0 = 0.0f, rs1 = 0.0f;
#pragma unroll
        for (int j = 0; j < 8; j++) {
            s[j][0] = __expf(s[j][0] - mn0);
            s[j][1] = __expf(s[j][1] - mn0);
            s[j][2] = __expf(s[j][2] - mn1);
            s[j][3] = __expf(s[j][3] - mn1);
            rs0 += s[j][0] + s[j][1];
            rs1 += s[j][2] + s[j][3];
        }
        rs0 += __shfl_xor_sync(0xffffffffu, rs0, 1);
        rs0 += __shfl_xor_sync(0xffffffffu, rs0, 2);
        rs1 += __shfl_xor_sync(0xffffffffu, rs1, 1);
        rs1 += __shfl_xor_sync(0xffffffffu, rs1, 2);
        s_l[0] = s_l[0] * al0 + rs0;
        s_l[1] = s_l[1] * al1 + rs1;

#pragma unroll
        for (int nt = 0; nt < 16; nt++) {
            o[nt][0] *= al0; o[nt][1] *= al0;
            o[nt][2] *= al1; o[nt][3] *= al1;
        }

        // ---- pack P into fp16 A-frags ----
        uint32_t ph[4][4];
#pragma unroll
        for (int t = 0; t < 4; t++) {
#pragma unroll
            for (int q = 0; q < 4; q++) {
                int j = 2 * t + (q >> 1);
                int cc = (q & 1) * 2;
                ph[t][q] = pack_h2(s[j][cc], s[j][cc + 1]);
            }
        }

        // ---- O += P @ V ----
#pragma unroll
        for (int t = 0; t < 4; t++) {
#pragma unroll
            for (int np = 0; np < 8; np++) {
                uint32_t vh[4];
                ldm_x4t(vh, sV + (t * 16 + (lane & 15)) * F_ROWB + (np * 16 + lhalf) * 2);
                uint32_t b0h[2] = { vh[0], vh[1] }, b1h[2] = { vh[2], vh[3] };
                mma16816(o[2*np],   ph[t], b0h);
                mma16816(o[2*np+1], ph[t], b1h);
            }
        }
        __syncthreads();
    }

    // epilogue: normalize, round to fp16, store into single-tile layout
    float inv0 = 1.0f / s_l[0];
    float inv1 = 1.0f / s_l[1];
    int row0g = b * S_LEN + mblk * 64 + m0 + lr;
    int row1g = row0g + 8;
#pragma unroll
    for (int nt = 0; nt < 16; nt++) {
        int col = h * HDIM + nt * 8 + lc * 2;
        size_t o0 = single_off(row0g, col, INNER);
        size_t o1 = single_off(row1g, col, INNER);
        *(uint32_t*)(Ot + o0) = pack_h2(o[nt][0] * inv0, o[nt][1] * inv0);
        *(uint32_t*)(Ot + o1) = pack_h2(o[nt][2] * inv1, o[nt][3] * inv1);
    }
}

// ---------------------------------------------------------------------------
// fp32 -> fp16 convert, writing single-tile layout (x)
// ---------------------------------------------------------------------------
__global__ void convert_kernel(const float4* __restrict__ in,
                               __half* __restrict__ T, int n4, int K) {
    int i = blockIdx.x * blockDim.x + threadIdx.x;
    if (i >= n4) return;
    float4 v = in[i];
    int rg = (i * 4) / K;
    int k0 = (i * 4) % K;
    size_t o = single_off(rg, k0, K);
    uint2 hp;
    hp.x = pack_h2(v.x, v.y);
    hp.y = pack_h2(v.z, v.w);
    *(uint2*)(T + o) = hp;
}

// ---------------------------------------------------------------------------
// Transpose: W[K,N] fp32 -> single-tile fp16 T[N,K]
// ---------------------------------------------------------------------------
__global__ void transpose_single_kernel(const float* __restrict__ W,
                                        __half* __restrict__ T) {
    __shared__ float t[32][33];
    int n0 = blockIdx.x * 32, k0 = blockIdx.y * 32;
#pragma unroll
    for (int i = 0; i < 32; i += 8)
        t[threadIdx.y + i][threadIdx.x] =
            W[(size_t)(k0 + threadIdx.y + i) * 2048 + n0 + threadIdx.x];
    __syncthreads();
#pragma unroll
    for (int i = 0; i < 32; i += 8) {
        float v = t[threadIdx.x][threadIdx.y + i];
        size_t o = single_off(n0 + threadIdx.y + i, k0 + threadIdx.x, 2048);
        T[o] = __float2half_rn(v);
    }
}

// ---------------------------------------------------------------------------
// Launcher (ncu capture slot = launch index 5 -> V GEMM)
// ---------------------------------------------------------------------------
extern "C" void kernel_launch(void* const* d_in, const int* in_sizes, int n_in,
                              void* d_out, int out_size) {
    const float* x  = (const float*)d_in[0];
    const float* Wq = (const float*)d_in[1];
    const float* Wk = (const float*)d_in[2];
    const float* Wv = (const float*)d_in[3];
    const float* Wo = (const float*)d_in[4];
    const float* qg = (const float*)d_in[5];
    const float* kg = (const float*)d_in[6];
    float* out = (float*)d_out;

    __half *xt, *w, *aot, *q, *k, *v;
    cudaGetSymbolAddress((void**)&xt,  g_xt);
    cudaGetSymbolAddress((void**)&w,   g_w);
    cudaGetSymbolAddress((void**)&aot, g_aot);
    cudaGetSymbolAddress((void**)&q,   g_q);
    cudaGetSymbolAddress((void**)&k,   g_k);
    cudaGetSymbolAddress((void**)&v,   g_v);
    const size_t WSZ = (size_t)DMODEL * INNER;

    cudaFuncSetAttribute(gemm_mma_kernel<0>, cudaFuncAttributeMaxDynamicSharedMemorySize, GEMM_SMEM);
    cudaFuncSetAttribute(gemm_mma_kernel<1>, cudaFuncAttributeMaxDynamicSharedMemorySize, GEMM_SMEM);
    cudaFuncSetAttribute(gemm_mma_kernel<2>, cudaFuncAttributeMaxDynamicSharedMemorySize, GEMM_SMEM);
    cudaFuncSetAttribute(flash_mma_kernel, cudaFuncAttributeMaxDynamicSharedMemorySize, FLASH_SMEM);

    dim3 tb(32, 8), tg(64, 64);
    dim3 gg(INNER / G_BN, ROWS / G_BM);   // (16, 32)
    dim3 gridF(S_LEN / 64, NHEAD, BATCH);

    // launch 0: convert x -> fp16 single tiles
    int n4x = ROWS * DMODEL / 4;
    convert_kernel<<<n4x / 256, 256>>>((const float4*)x, xt, n4x, DMODEL);
    // launches 1-4: transpose Wq, Wk, Wv, Wo
    transpose_single_kernel<<<tg, tb>>>(Wq, w + 0*WSZ);
    transpose_single_kernel<<<tg, tb>>>(Wk, w + 1*WSZ);
    transpose_single_kernel<<<tg, tb>>>(Wv, w + 2*WSZ);
    transpose_single_kernel<<<tg, tb>>>(Wo, w + 3*WSZ);
    // launch 5 (ncu capture slot): V projection
    gemm_mma_kernel<1><<<gg, 128, GEMM_SMEM>>>(xt, w + 2*WSZ, nullptr, v, nullptr,
                                               ROWS, INNER, DMODEL);
    // launches 6-7: Q, K projections with fused RMSNorm
    gemm_mma_kernel<2><<<gg, 128, GEMM_SMEM>>>(xt, w + 0*WSZ, nullptr, q, qg,
                                               ROWS, INNER, DMODEL);
    gemm_mma_kernel<2><<<gg, 128, GEMM_SMEM>>>(xt, w + 1*WSZ, nullptr, k, kg,
                                               ROWS, INNER, DMODEL);
    // launch 8: flash attention (epilogue writes single-tile ao)
    flash_mma_kernel<<<gridF, 128, FLASH_SMEM>>>(q, k, v, aot);
    // launch 9: output projection -> d_out (fp32)
    gemm_mma_kernel<0><<<gg, 128, GEMM_SMEM>>>(aot, w + 3*WSZ, out, nullptr, nullptr,
                                               ROWS, DMODEL, INNER);
}

// round 17
// speedup vs baseline: 3.5503x; 1.1119x over previous
#include <cuda_runtime.h>
#include <cuda_fp16.h>
#include <stdint.h>
#include <math.h>

// Problem constants
#define S_LEN   2048
#define BATCH   2
#define NHEAD   16
#define HDIM    128
#define DMODEL  2048
#define INNER   2048          // NHEAD*HDIM
#define ROWS    (BATCH*S_LEN) // 4096

// Scratch (allocation forbidden -> __device__ globals)
// x / W / ao: single-tile fp16 swizzled layouts (below), 1024B-aligned for
// cp.async.bulk.  q/k/v: row-major [ROWS, INNER] fp16 for the flash kernel.
__device__ __align__(1024) __half g_xt[(size_t)ROWS * DMODEL];
__device__ __align__(1024) __half g_w[4][(size_t)DMODEL * INNER];
__device__ __align__(1024) __half g_aot[(size_t)ROWS * INNER];
__device__ __align__(1024) __half g_q[(size_t)ROWS * INNER];
__device__ __align__(1024) __half g_k[(size_t)ROWS * INNER];
__device__ __align__(1024) __half g_v[(size_t)ROWS * INNER];

// ---------------------------------------------------------------------------
// Single-tile layout (element offsets in fp16 units).
// Tile = 128 rows x 32 cols = 4096 elems (8KB); tile idx = rowblk*(K/32)+chunk.
// In-tile: elem (rl,kl) at rl*32 + ((ch ^ ((rl>>1)&3))<<3) + w,
//   ch = kl>>3, w = kl&7  (XOR swizzle -> conflict-free ldmatrix, 64B rows).
// Two consecutive chunks form a contiguous 16KB span (used by BK=64 stages).
// ---------------------------------------------------------------------------
__device__ __forceinline__ size_t single_off(int rg, int k, int K) {
    int rb = rg >> 7, rl = rg & 127, c = k >> 5, kl = k & 31;
    int ch = kl >> 3, w = kl & 7;
    return ((size_t)(rb * (K >> 5) + c) << 12) + rl * 32 +
           (((ch ^ ((rl >> 1) & 3)) << 3) + w);
}

// ---------------------------------------------------------------------------
// PTX helpers
// ---------------------------------------------------------------------------
__device__ __forceinline__ uint32_t smem_u32(const void* p) {
    uint32_t a;
    asm("{ .reg .u64 t; cvta.to.shared.u64 t, %1; cvt.u32.u64 %0, t; }"
        : "=r"(a) : "l"(p));
    return a;
}
__device__ __forceinline__ void cp16(uint32_t dst, const void* src) {
    asm volatile("cp.async.cg.shared.global [%0], [%1], 16;" :: "r"(dst), "l"(src));
}
__device__ __forceinline__ void cp_commit() { asm volatile("cp.async.commit_group;"); }
template<int N> __device__ __forceinline__ void cp_wait() {
    asm volatile("cp.async.wait_group %0;" :: "n"(N));
}
__device__ __forceinline__ void bulkcp(uint32_t dst, const void* src,
                                       uint32_t bytes, uint32_t mbar) {
    asm volatile(
        "cp.async.bulk.shared::cluster.global.mbarrier::complete_tx::bytes "
        "[%0], [%1], %2, [%3];"
        :: "r"(dst), "l"(src), "r"(bytes), "r"(mbar) : "memory");
}
__device__ __forceinline__ void mbar_init(uint32_t a, uint32_t c) {
    asm volatile("mbarrier.init.shared.b64 [%0], %1;" :: "r"(a), "r"(c) : "memory");
}
__device__ __forceinline__ void mbar_expect(uint32_t mbar, uint32_t bytes) {
    asm volatile("mbarrier.arrive.expect_tx.shared.b64 _, [%0], %1;"
                 :: "r"(mbar), "r"(bytes) : "memory");
}
__device__ __forceinline__ void mbar_wait(uint32_t mbar, uint32_t parity) {
    asm volatile(
        "{\n\t.reg .pred P;\n\t"
        "WL_%=:\n\t"
        "mbarrier.try_wait.parity.shared.b64 P, [%0], %1;\n\t"
        "@P bra.uni WD_%=;\n\t"
        "bra.uni WL_%=;\n\t"
        "WD_%=:\n\t}"
        :: "r"(mbar), "r"(parity) : "memory");
}
__device__ __forceinline__ void fence_async() {
    asm volatile("fence.proxy.async.shared::cta;" ::: "memory");
}
__device__ __forceinline__ void ldm_x4(uint32_t* r, uint32_t addr) {
    asm volatile("ldmatrix.sync.aligned.m8n8.x4.shared.b16 {%0,%1,%2,%3}, [%4];"
                 : "=r"(r[0]), "=r"(r[1]), "=r"(r[2]), "=r"(r[3]) : "r"(addr));
}
__device__ __forceinline__ void ldm_x4t(uint32_t* r, uint32_t addr) {
    asm volatile("ldmatrix.sync.aligned.m8n8.x4.trans.shared.b16 {%0,%1,%2,%3}, [%4];"
                 : "=r"(r[0]), "=r"(r[1]), "=r"(r[2]), "=r"(r[3]) : "r"(addr));
}
__device__ __forceinline__ void mma16816(float* c, const uint32_t* a, const uint32_t* b) {
    asm volatile(
        "mma.sync.aligned.m16n8k16.row.col.f32.f16.f16.f32 "
        "{%0,%1,%2,%3}, {%4,%5,%6,%7}, {%8,%9}, {%0,%1,%2,%3};"
        : "+f"(c[0]), "+f"(c[1]), "+f"(c[2]), "+f"(c[3])
        : "r"(a[0]), "r"(a[1]), "r"(a[2]), "r"(a[3]), "r"(b[0]), "r"(b[1]));
}
__device__ __forceinline__ uint32_t pack_h2(float a, float b) {
    __half2 t = __floats2half2_rn(a, b);
    return *(uint32_t*)&t;
}

// ---------------------------------------------------------------------------
// fp16 GEMM (fp32 accum), BK=64 stages fed by cp.async.bulk (2x16KB per stage).
// CTA 128x128, 128 threads (4 warps, warp tile 64x64), 3-stage mbarrier
// pipeline, occupancy 2.
// MODE 0: fp32 C.  MODE 1: fp16 C (row-major).  MODE 2: RMSNorm + fp16 C.
// ---------------------------------------------------------------------------
#define G_BM 128
#define G_BN 128
#define TILB 8192                 // one 128x32 tile
#define SUPB 16384                // two consecutive chunks (BK=64) per operand
#define STAGEB (2 * SUPB)         // 32768
#define NSTAGE 3
#define GEMM_SMEM (NSTAGE * STAGEB + 64)   // 98368

template<int MODE>
__global__ __launch_bounds__(128, 2)
void gemm_mma_kernel(const __half* __restrict__ A,   // single tiles
                     const __half* __restrict__ B,   // single tiles
                     float* __restrict__ C,
                     __half* __restrict__ Ch,
                     const float* __restrict__ gamma,
                     int M, int N, int K)
{
    extern __shared__ char smem[];
    const uint32_t sbase = smem_u32(smem);
    const uint32_t mbar0 = sbase + NSTAGE * STAGEB;
    const int tid  = threadIdx.x;
    const int warp = tid >> 5;
    const int lane = tid & 31;
    const int wm = warp >> 1;
    const int wn = warp & 1;

    const int rowblk = blockIdx.y;
    const int colblk = blockIdx.x;
    const int row0 = rowblk * G_BM;
    const int col0 = colblk * G_BN;
    const int KC  = K >> 5;         // 32-wide chunks
    const int KC2 = K >> 6;         // 64-wide super-chunks

    if (tid == 0) {
#pragma unroll
        for (int s = 0; s < NSTAGE; s++) mbar_init(mbar0 + s * 8, 1);
        fence_async();
    }
    __syncthreads();

    float acc[4][8][4];
#pragma unroll
    for (int mt = 0; mt < 4; mt++)
#pragma unroll
        for (int nt = 0; nt < 8; nt++)
#pragma unroll
            for (int r = 0; r < 4; r++) acc[mt][nt][r] = 0.0f;

    auto issue = [&](int c2, int s) {
        uint32_t stb = sbase + s * STAGEB;
        uint32_t mb = mbar0 + s * 8;
        const char* ap = (const char*)A + (((size_t)(rowblk * KC + 2 * c2)) << 13);
        const char* bp = (const char*)B + (((size_t)(colblk * KC + 2 * c2)) << 13);
        mbar_expect(mb, STAGEB);
        bulkcp(stb,        ap, SUPB, mb);
        bulkcp(stb + SUPB, bp, SUPB, mb);
    };

    if (tid == 0) { issue(0, 0); issue(1, 1); }

    const int arow_l = (lane & 15);
    const int brow_l = (lane & 7) + 8 * (lane >> 4);
    const int a_chl  = lane >> 4;
    const int b_chl  = (lane >> 3) & 1;

    for (int c2 = 0; c2 < KC2; ++c2) {
        const int s = c2 % NSTAGE;
        if (tid == 0 && c2 + 2 < KC2) issue(c2 + 2, (c2 + 2) % NSTAGE);
        mbar_wait(mbar0 + s * 8, (c2 / NSTAGE) & 1);

        const uint32_t stg = sbase + s * STAGEB;
#pragma unroll
        for (int half = 0; half < 2; half++) {
            const uint32_t sA = stg + half * TILB;
            const uint32_t sB = stg + SUPB + half * TILB;
#pragma unroll
            for (int ks = 0; ks < 2; ks++) {
                uint32_t a[4][4];
#pragma unroll
                for (int mt = 0; mt < 4; mt++) {
                    int arow = wm * 64 + mt * 16 + arow_l;
                    int ch = (2 * ks + a_chl) ^ ((arow >> 1) & 3);
                    ldm_x4(a[mt], sA + arow * 64 + ch * 16);
                }
                uint32_t b[8][2];
#pragma unroll
                for (int p = 0; p < 4; p++) {
                    int brow = wn * 64 + p * 16 + brow_l;
                    int ch = (2 * ks + b_chl) ^ ((brow >> 1) & 3);
                    uint32_t t0[4];
                    ldm_x4(t0, sB + brow * 64 + ch * 16);
                    b[2*p][0]   = t0[0]; b[2*p][1]   = t0[1];
                    b[2*p+1][0] = t0[2]; b[2*p+1][1] = t0[3];
                }
#pragma unroll
                for (int mt = 0; mt < 4; mt++)
#pragma unroll
                    for (int nt = 0; nt < 8; nt++)
                        mma16816(acc[mt][nt], a[mt], b[nt]);
            }
        }
        __syncthreads();
    }

    if (MODE == 0) {
#pragma unroll
        for (int mt = 0; mt < 4; mt++) {
            int r0 = row0 + wm * 64 + mt * 16 + (lane >> 2);
#pragma unroll
            for (int nt = 0; nt < 8; nt++) {
                int cc = col0 + wn * 64 + nt * 8 + (lane & 3) * 2;
                *(float2*)(C + (size_t)r0 * N + cc) =
                    make_float2(acc[mt][nt][0], acc[mt][nt][1]);
                *(float2*)(C + (size_t)(r0 + 8) * N + cc) =
                    make_float2(acc[mt][nt][2], acc[mt][nt][3]);
            }
        }
    } else if (MODE == 1) {
#pragma unroll
        for (int mt = 0; mt < 4; mt++) {
            int r0 = row0 + wm * 64 + mt * 16 + (lane >> 2);
#pragma unroll
            for (int nt = 0; nt < 8; nt++) {
                int cc = col0 + wn * 64 + nt * 8 + (lane & 3) * 2;
                *(uint32_t*)(Ch + (size_t)r0 * N + cc) =
                    pack_h2(acc[mt][nt][0], acc[mt][nt][1]);
                *(uint32_t*)(Ch + (size_t)(r0 + 8) * N + cc) =
                    pack_h2(acc[mt][nt][2], acc[mt][nt][3]);
            }
        }
    } else {
        // MODE 2: per-row (=head) RMSNorm + fp16 out, row-major
        float* CS = (float*)smem;      // 128 x 132 fp32
        float4 g4 = *(const float4*)(gamma + lane * 4);
#pragma unroll
        for (int mt = 0; mt < 4; mt++) {
            int r = wm * 64 + mt * 16 + (lane >> 2);
#pragma unroll
            for (int nt = 0; nt < 8; nt++) {
                int cc = wn * 64 + nt * 8 + (lane & 3) * 2;
                CS[r * 132 + cc]         = acc[mt][nt][0];
                CS[r * 132 + cc + 1]     = acc[mt][nt][1];
                CS[(r+8) * 132 + cc]     = acc[mt][nt][2];
                CS[(r+8) * 132 + cc + 1] = acc[mt][nt][3];
            }
        }
        __syncthreads();
#pragma unroll
        for (int rr = 0; rr < 32; rr++) {
            int row = warp * 32 + rr;
            float4 v = *(float4*)&CS[row * 132 + lane * 4];
            float ss = v.x*v.x + v.y*v.y + v.z*v.z + v.w*v.w;
#pragma unroll
            for (int o = 16; o > 0; o >>= 1)
                ss += __shfl_xor_sync(0xffffffffu, ss, o);
            float rn = rsqrtf(ss * (1.0f / 128.0f) + 1e-6f);
            size_t o = (size_t)(row0 + row) * N + col0 + lane * 4;
            uint2 hp;
            hp.x = pack_h2(v.x * rn * g4.x, v.y * rn * g4.y);
            hp.y = pack_h2(v.z * rn * g4.z, v.w * rn * g4.w);
            *(uint2*)(Ch + o) = hp;
        }
    }
}

// ---------------------------------------------------------------------------
// Flash attention, plain fp16 (fp32 accum), double-buffered K/V tiles.
// 64x64 tile, 128 thr, occ 2. smem: Q + 2x(K,V) tiles = 87040 B.
// Epilogue writes ao into single-tile fp16 layout.
// ---------------------------------------------------------------------------
#define F_ROWB 272
#define FT_BYTES (64 * F_ROWB)
#define FLASH_SMEM (5 * FT_BYTES)   // 87040

__global__ __launch_bounds__(128, 2)
void flash_mma_kernel(const __half* __restrict__ Q,
                      const __half* __restrict__ K,
                      const __half* __restrict__ V,
                      __half* __restrict__ Ot)
{
    extern __shared__ char sm_raw[];
    const uint32_t sb = smem_u32(sm_raw);
    const uint32_t sQ  = sb;
    const uint32_t sKV = sb + FT_BYTES;   // stage s: K at +s*2*FT, V at +FT

    const int tid  = threadIdx.x;
    const int warp = tid >> 5;
    const int lane = tid & 31;
    const int lr   = lane >> 2;
    const int lc   = lane & 3;
    const int m0   = warp * 16;

    const int mblk = blockIdx.x, h = blockIdx.y, b = blockIdx.z;
    const size_t qoff = ((size_t)(b * S_LEN + mblk * 64)) * INNER + h * HDIM;
    const size_t koff = ((size_t)(b * S_LEN)) * INNER + h * HDIM;

    auto load_kv = [&](int it, int stage) {
        uint32_t stb = sKV + stage * (2 * FT_BYTES);
        int n0 = it * 64;
#pragma unroll
        for (int i = 0; i < 8; i++) {
            int idx = i * 128 + tid;
            int r = idx >> 4, s = idx & 15;
            uint32_t so = r * F_ROWB + s * 16;
            const size_t go = koff + (size_t)(n0 + r) * INNER + s * 8;
            cp16(stb + so,            K + go);
            cp16(stb + FT_BYTES + so, V + go);
        }
    };

    // group 0: Q + KV(0)
#pragma unroll
    for (int i = 0; i < 8; i++) {
        int idx = i * 128 + tid;
        int r = idx >> 4, s = idx & 15;
        cp16(sQ + r * F_ROWB + s * 16, Q + qoff + (size_t)r * INNER + s * 8);
    }
    load_kv(0, 0);
    cp_commit();

    float o[16][4];
#pragma unroll
    for (int nt = 0; nt < 16; nt++)
#pragma unroll
        for (int r = 0; r < 4; r++) o[nt][r] = 0.0f;
    float s_m[2] = { -1e30f, -1e30f };
    float s_l[2] = { 0.0f, 0.0f };
    const float scale = 0.08838834764831845f;

    const uint32_t a_row = m0 + (lane & 15);
    const uint32_t lhalf = 8 * (lane >> 4);
    const int NIT = S_LEN / 64;

    for (int it = 0; it < NIT; it++) {
        if (it + 1 < NIT) {
            load_kv(it + 1, (it + 1) & 1);
            cp_commit();
            cp_wait<1>();
        } else {
            cp_wait<0>();
        }
        __syncthreads();

        const uint32_t cK = sKV + (it & 1) * (2 * FT_BYTES);
        const uint32_t cV = cK + FT_BYTES;

        // ---- S = Q @ K^T ----
        float s[8][4];
#pragma unroll
        for (int j = 0; j < 8; j++)
#pragma unroll
            for (int r = 0; r < 4; r++) s[j][r] = 0.0f;

#pragma unroll
        for (int t = 0; t < 8; t++) {
            const int d0 = t * 16;
            uint32_t ah[4];
            ldm_x4(ah, sQ + a_row * F_ROWB + (d0 + lhalf) * 2);
#pragma unroll
            for (int p = 0; p < 4; p++) {
                uint32_t bh[4];
                ldm_x4(bh, cK + (p * 16 + (lane & 15)) * F_ROWB + (d0 + lhalf) * 2);
                uint32_t b0h[2] = { bh[0], bh[2] }, b1h[2] = { bh[1], bh[3] };
                mma16816(s[2*p],   ah, b0h);
                mma16816(s[2*p+1], ah, b1h);
            }
        }

        // ---- online softmax ----
#pragma unroll
        for (int j = 0; j < 8; j++)
#pragma unroll
            for (int r = 0; r < 4; r++) s[j][r] *= scale;

        float mx0 = -1e30f, mx1 = -1e30f;
#pragma unroll
        for (int j = 0; j < 8; j++) {
            mx0 = fmaxf(mx0, fmaxf(s[j][0], s[j][1]));
            mx1 = fmaxf(mx1, fmaxf(s[j][2], s[j][3]));
        }
        mx0 = fmaxf(mx0, __shfl_xor_sync(0xffffffffu, mx0, 1));
        mx0 = fmaxf(mx0, __shfl_xor_sync(0xffffffffu, mx0, 2));
        mx1 = fmaxf(mx1, __shfl_xor_sync(0xffffffffu, mx1, 1));
        mx1 = fmaxf(mx1, __shfl_xor_sync(0xffffffffu, mx1, 2));

        float mn0 = fmaxf(s_m[0], mx0), mn1 = fmaxf(s_m[1], mx1);
        float al0 = __expf(s_m[0] - mn0), al1 = __expf(s_m[1] - mn1);
        s_m[0] = mn0; s_m[1] = mn1;

        float rs0 = 0.0f, rs1 = 0.0f;
#pragma unroll
        for (int j = 0; j < 8; j++) {
            s[j][0] = __expf(s[j][0] - mn0);
            s[j][1] = __expf(s[j][1] - mn0);
            s[j][2] = __expf(s[j][2] - mn1);
            s[j][3] = __expf(s[j][3] - mn1);
            rs0 += s[j][0] + s[j][1];
            rs1 += s[j][2] + s[j][3];
        }
        rs0 += __shfl_xor_sync(0xffffffffu, rs0, 1);
        rs0 += __shfl_xor_sync(0xffffffffu, rs0, 2);
        rs1 += __shfl_xor_sync(0xffffffffu, rs1, 1);
        rs1 += __shfl_xor_sync(0xffffffffu, rs1, 2);
        s_l[0] = s_l[0] * al0 + rs0;
        s_l[1] = s_l[1] * al1 + rs1;

#pragma unroll
        for (int nt = 0; nt < 16; nt++) {
            o[nt][0] *= al0; o[nt][1] *= al0;
            o[nt][2] *= al1; o[nt][3] *= al1;
        }

        // ---- pack P into fp16 A-frags ----
        uint32_t ph[4][4];
#pragma unroll
        for (int t = 0; t < 4; t++) {
#pragma unroll
            for (int q = 0; q < 4; q++) {
                int j = 2 * t + (q >> 1);
                int cc = (q & 1) * 2;
                ph[t][q] = pack_h2(s[j][cc], s[j][cc + 1]);
            }
        }

        // ---- O += P @ V ----
#pragma unroll
        for (int t = 0; t < 4; t++) {
#pragma unroll
            for (int np = 0; np < 8; np++) {
                uint32_t vh[4];
                ldm_x4t(vh, cV + (t * 16 + (lane & 15)) * F_ROWB + (np * 16 + lhalf) * 2);
                uint32_t b0h[2] = { vh[0], vh[1] }, b1h[2] = { vh[2], vh[3] };
                mma16816(o[2*np],   ph[t], b0h);
                mma16816(o[2*np+1], ph[t], b1h);
            }
        }
        __syncthreads();
    }

    // epilogue: normalize, round to fp16, store into single-tile layout
    float inv0 = 1.0f / s_l[0];
    float inv1 = 1.0f / s_l[1];
    int row0g = b * S_LEN + mblk * 64 + m0 + lr;
    int row1g = row0g + 8;
#pragma unroll
    for (int nt = 0; nt < 16; nt++) {
        int col = h * HDIM + nt * 8 + lc * 2;
        size_t o0 = single_off(row0g, col, INNER);
        size_t o1 = single_off(row1g, col, INNER);
        *(uint32_t*)(Ot + o0) = pack_h2(o[nt][0] * inv0, o[nt][1] * inv0);
        *(uint32_t*)(Ot + o1) = pack_h2(o[nt][2] * inv1, o[nt][3] * inv1);
    }
}

// ---------------------------------------------------------------------------
// fp32 -> fp16 convert, writing single-tile layout (x)
// ---------------------------------------------------------------------------
__global__ void convert_kernel(const float4* __restrict__ in,
                               __half* __restrict__ T, int n4, int K) {
    int i = blockIdx.x * blockDim.x + threadIdx.x;
    if (i >= n4) return;
    float4 v = in[i];
    int rg = (i * 4) / K;
    int k0 = (i * 4) % K;
    size_t o = single_off(rg, k0, K);
    uint2 hp;
    hp.x = pack_h2(v.x, v.y);
    hp.y = pack_h2(v.z, v.w);
    *(uint2*)(T + o) = hp;
}

// ---------------------------------------------------------------------------
// Transpose: W[K,N] fp32 -> single-tile fp16 T[N,K]
// ---------------------------------------------------------------------------
__global__ void transpose_single_kernel(const float* __restrict__ W,
                                        __half* __restrict__ T) {
    __shared__ float t[32][33];
    int n0 = blockIdx.x * 32, k0 = blockIdx.y * 32;
#pragma unroll
    for (int i = 0; i < 32; i += 8)
        t[threadIdx.y + i][threadIdx.x] =
            W[(size_t)(k0 + threadIdx.y + i) * 2048 + n0 + threadIdx.x];
    __syncthreads();
#pragma unroll
    for (int i = 0; i < 32; i += 8) {
        float v = t[threadIdx.x][threadIdx.y + i];
        size_t o = single_off(n0 + threadIdx.y + i, k0 + threadIdx.x, 2048);
        T[o] = __float2half_rn(v);
    }
}

// ---------------------------------------------------------------------------
// Launcher
// ---------------------------------------------------------------------------
extern "C" void kernel_launch(void* const* d_in, const int* in_sizes, int n_in,
                              void* d_out, int out_size) {
    const float* x  = (const float*)d_in[0];
    const float* Wq = (const float*)d_in[1];
    const float* Wk = (const float*)d_in[2];
    const float* Wv = (const float*)d_in[3];
    const float* Wo = (const float*)d_in[4];
    const float* qg = (const float*)d_in[5];
    const float* kg = (const float*)d_in[6];
    float* out = (float*)d_out;

    __half *xt, *w, *aot, *q, *k, *v;
    cudaGetSymbolAddress((void**)&xt,  g_xt);
    cudaGetSymbolAddress((void**)&w,   g_w);
    cudaGetSymbolAddress((void**)&aot, g_aot);
    cudaGetSymbolAddress((void**)&q,   g_q);
    cudaGetSymbolAddress((void**)&k,   g_k);
    cudaGetSymbolAddress((void**)&v,   g_v);
    const size_t WSZ = (size_t)DMODEL * INNER;

    cudaFuncSetAttribute(gemm_mma_kernel<0>, cudaFuncAttributeMaxDynamicSharedMemorySize, GEMM_SMEM);
    cudaFuncSetAttribute(gemm_mma_kernel<1>, cudaFuncAttributeMaxDynamicSharedMemorySize, GEMM_SMEM);
    cudaFuncSetAttribute(gemm_mma_kernel<2>, cudaFuncAttributeMaxDynamicSharedMemorySize, GEMM_SMEM);
    cudaFuncSetAttribute(flash_mma_kernel, cudaFuncAttributeMaxDynamicSharedMemorySize, FLASH_SMEM);

    dim3 tb(32, 8), tg(64, 64);
    dim3 gg(INNER / G_BN, ROWS / G_BM);   // (16, 32)
    dim3 gridF(S_LEN / 64, NHEAD, BATCH);

    // launch 0: convert x -> fp16 single tiles
    int n4x = ROWS * DMODEL / 4;
    convert_kernel<<<n4x / 256, 256>>>((const float4*)x, xt, n4x, DMODEL);
    // launches 1-4: transpose Wq, Wk, Wv, Wo
    transpose_single_kernel<<<tg, tb>>>(Wq, w + 0*WSZ);
    transpose_single_kernel<<<tg, tb>>>(Wk, w + 1*WSZ);
    transpose_single_kernel<<<tg, tb>>>(Wv, w + 2*WSZ);
    transpose_single_kernel<<<tg, tb>>>(Wo, w + 3*WSZ);
    // launch 5: V projection
    gemm_mma_kernel<1><<<gg, 128, GEMM_SMEM>>>(xt, w + 2*WSZ, nullptr, v, nullptr,
                                               ROWS, INNER, DMODEL);
    // launches 6-7: Q, K projections with fused RMSNorm
    gemm_mma_kernel<2><<<gg, 128, GEMM_SMEM>>>(xt, w + 0*WSZ, nullptr, q, qg,
                                               ROWS, INNER, DMODEL);
    gemm_mma_kernel<2><<<gg, 128, GEMM_SMEM>>>(xt, w + 1*WSZ, nullptr, k, kg,
                                               ROWS, INNER, DMODEL);
    // launch 8: flash attention (epilogue writes single-tile ao)
    flash_mma_kernel<<<gridF, 128, FLASH_SMEM>>>(q, k, v, aot);
    // launch 9: output projection -> d_out (fp32)
    gemm_mma_kernel<0><<<gg, 128, GEMM_SMEM>>>(aot, w + 3*WSZ, out, nullptr, nullptr,
                                               ROWS, DMODEL, INNER);
}